// round 10
// baseline (speedup 1.0000x reference)
#include <cuda_runtime.h>
#include <cuda_bf16.h>
#include <cstdint>

#define NN 100000
#define NE 1200000
#define HH 64
#define H2 128
#define NB_SCAN 98

// ---------------- device scratch (no allocations allowed) ----------------
__device__ float g_z[NN * HH];      // layer input features (fp32)
__device__ float g_h[NN * HH];      // residual stream (fp32)
__device__ unsigned g_uh[NN * 32];  // MLP input, bf16x2 hi words (k-pairs)
__device__ unsigned g_ul[NN * 32];  // MLP input, bf16x2 lo words
__device__ int   g_rowptr[NN + 1];
__device__ int   g_wp[NN];          // zeroed by previous replay's k_final
__device__ int   g_srcs[NE];        // src ids PRE-SCALED by 64
__device__ int   g_sval[128];
__device__ int   g_sincl[128];
__device__ int   g_sflag[128];      // tail-zeroed by k_final
// pre-split weights, [n][kp] rows (k contiguous as bf16):
__device__ unsigned g_w1h[3 * 4096], g_w1l[3 * 4096];
__device__ unsigned g_w2h[3 * 4096], g_w2l[3 * 4096];

// ---------------- helpers ----------------
__device__ __forceinline__ unsigned pk_bf2(float xe, float xo) {
    unsigned d;
    asm("cvt.rn.bf16x2.f32 %0, %1, %2;" : "=r"(d) : "f"(xo), "f"(xe));
    return d;
}
__device__ __forceinline__ float lo16f(unsigned w) { return __uint_as_float(w << 16); }
__device__ __forceinline__ float hi16f(unsigned w) { return __uint_as_float(w & 0xffff0000u); }
__device__ __forceinline__ void split_pair(float xe, float xo, unsigned& hw, unsigned& lw) {
    hw = pk_bf2(xe, xo);
    lw = pk_bf2(xe - lo16f(hw), xo - hi16f(hw));
}
__device__ __forceinline__ uint32_t smem_u32(const void* p) {
    uint32_t a;
    asm("{ .reg .u64 t; cvta.to.shared.u64 t, %1; cvt.u32.u64 %0, t; }" : "=r"(a) : "l"(p));
    return a;
}
__device__ __forceinline__ void mma16(float* c, unsigned a0, unsigned a1,
                                      unsigned a2, unsigned a3,
                                      unsigned b0, unsigned b1) {
    asm("mma.sync.aligned.m16n8k16.row.col.f32.bf16.bf16.f32 "
        "{%0,%1,%2,%3}, {%4,%5,%6,%7}, {%8,%9}, {%0,%1,%2,%3};"
        : "+f"(c[0]), "+f"(c[1]), "+f"(c[2]), "+f"(c[3])
        : "r"(a0), "r"(a1), "r"(a2), "r"(a3), "r"(b0), "r"(b1));
}
__device__ __forceinline__ void ldsm4(unsigned& r0, unsigned& r1, unsigned& r2,
                                      unsigned& r3, uint32_t addr) {
    asm volatile("ldmatrix.sync.aligned.m8n8.x4.shared.b16 {%0,%1,%2,%3}, [%4];"
                 : "=r"(r0), "=r"(r1), "=r"(r2), "=r"(r3) : "r"(addr));
}
// per-edge softmax accumulate, packed f32x2 (scaled-domain message sum)
__device__ __forceinline__ void edge_acc(float2 v, unsigned long long tl2d,
                                         unsigned long long& z, unsigned long long& s) {
    asm("{\n\t"
        ".reg .f32 m0, m1, w0, w1;\n\t"
        ".reg .b64 mv, wp, mp;\n\t"
        "mov.b64 mv, {%2, %3};\n\t"
        "mul.rn.f32x2 mv, mv, %4;\n\t"
        "mov.b64 {m0, m1}, mv;\n\t"
        "max.f32 m0, m0, 0f00000000;\n\t"
        "max.f32 m1, m1, 0f00000000;\n\t"
        "ex2.approx.f32 w0, m0;\n\t"
        "ex2.approx.f32 w1, m1;\n\t"
        "mov.b64 wp, {w0, w1};\n\t"
        "mov.b64 mp, {m0, m1};\n\t"
        "add.rn.f32x2 %0, %0, wp;\n\t"
        "fma.rn.f32x2 %1, mp, wp, %1;\n\t"
        "}"
        : "+l"(z), "+l"(s)
        : "f"(v.x), "f"(v.y), "l"(tl2d));
}

// ------ launch 0: encoder (x4 vectorized) + histogram + weight pre-split ---
__global__ void k_enc_hist(const float* __restrict__ x, const float* __restrict__ W,
                           const float* __restrict__ b, const int* __restrict__ ei,
                           const float* __restrict__ W1g, const float* __restrict__ W2g) {
    int idx = blockIdx.x * blockDim.x + threadIdx.x;
    if (idx == 0) g_rowptr[NN] = NE;
    if (idx < NE) atomicAdd(&g_wp[ei[NE + idx]], 1);
    if (idx < NN * 16) {
        int n = idx >> 4, c = (idx & 15) * 4;
        float x0 = x[n * 3], x1 = x[n * 3 + 1], x2 = x[n * 3 + 2];
        float4 w0 = *(const float4*)&W[c];
        float4 w1 = *(const float4*)&W[HH + c];
        float4 w2 = *(const float4*)&W[2 * HH + c];
        float4 bb = *(const float4*)&b[c];
        float4 o;
        o.x = x0 * w0.x + x1 * w1.x + x2 * w2.x + bb.x;
        o.y = x0 * w0.y + x1 * w1.y + x2 * w2.y + bb.y;
        o.z = x0 * w0.z + x1 * w1.z + x2 * w2.z + bb.z;
        o.w = x0 * w0.w + x1 * w1.w + x2 * w2.w + bb.w;
        *(float4*)&g_z[n * HH + c] = o;
    }
    if (idx < 3 * 4096) {   // W1^T: idx = l*4096 + n*32 + kp
        int l = idx >> 12, r = idx & 4095, n = r >> 5, kp = r & 31;
        const float* Wl = W1g + l * (HH * H2);
        unsigned hw, lw;
        split_pair(Wl[(2 * kp) * H2 + n], Wl[(2 * kp + 1) * H2 + n], hw, lw);
        g_w1h[idx] = hw; g_w1l[idx] = lw;
    }
    if (idx < 3 * 4096) {   // W2^T: idx = l*4096 + n*64 + kp
        int l = idx >> 12, r = idx & 4095, n = r >> 6, kp = r & 63;
        const float* Wl = W2g + l * (H2 * HH);
        unsigned hw, lw;
        split_pair(Wl[(2 * kp) * HH + n], Wl[(2 * kp + 1) * HH + n], hw, lw);
        g_w2h[idx] = hw; g_w2l[idx] = lw;
    }
}

// ------------- launch 1: single-pass scan (decoupled lookback) -------------
__global__ void k_scan() {
    __shared__ int wsum[32];
    __shared__ int s_excl;
    int t = threadIdx.x, b = blockIdx.x;
    int lane = t & 31, wid = t >> 5;
    int i = b * 1024 + t;
    int x = (i < NN) ? g_wp[i] : 0;

    int v = x;
#pragma unroll
    for (int d = 1; d < 32; d <<= 1) {
        int u = __shfl_up_sync(0xffffffffu, v, d);
        if (lane >= d) v += u;
    }
    if (lane == 31) wsum[wid] = v;
    __syncthreads();
    if (wid == 0) {
        int w = wsum[lane];
#pragma unroll
        for (int d = 1; d < 32; d <<= 1) {
            int u = __shfl_up_sync(0xffffffffu, w, d);
            if (lane >= d) w += u;
        }
        wsum[lane] = w;
    }
    __syncthreads();
    int incl = v + (wid ? wsum[wid - 1] : 0);
    int bsum = wsum[31];

    if (t == 0) {
        if (b == 0) {
            g_sincl[0] = bsum; __threadfence(); g_sflag[0] = 2;
            s_excl = 0;
        } else {
            g_sval[b] = bsum; __threadfence(); g_sflag[b] = 1;
            int excl = 0, j = b - 1;
            while (true) {
                int f;
                do { f = ((volatile int*)g_sflag)[j]; } while (f == 0);
                __threadfence();
                if (f == 2) { excl += ((volatile int*)g_sincl)[j]; break; }
                excl += ((volatile int*)g_sval)[j]; j--;
            }
            g_sincl[b] = excl + bsum; __threadfence(); g_sflag[b] = 2;
            s_excl = excl;
        }
    }
    __syncthreads();
    if (i < NN) {
        int e = s_excl + incl - x;
        g_rowptr[i] = e;
        g_wp[i] = e;
    }
}

// ------------- launch 2: scatter src ids (pre-scaled) into CSR -------------
__global__ void k_scatter(const int* __restrict__ ei) {
    int e = blockIdx.x * blockDim.x + threadIdx.x;
    if (e < NE) {
        int d = ei[NE + e];
        int p = atomicAdd(&g_wp[d], 1);
        g_srcs[p] = ei[e] << 6;   // src * HH
    }
}

// ------- single-pass softmax aggregation (32 regs, 80% occ, packed f32x2) --
__global__ __launch_bounds__(256, 8) void k_agg(const float* __restrict__ tptr) {
    int gw = (blockIdx.x * blockDim.x + threadIdx.x) >> 5;
    if (gw >= NN) return;
    int lane = threadIdx.x & 31;
    int beg = g_rowptr[gw], end = g_rowptr[gw + 1];
    float tl2 = __ldg(tptr) * 1.44269504f;
    unsigned long long tl2d;
    asm("mov.b64 %0, {%1, %1};" : "=l"(tl2d) : "f"(tl2));
    const float* zp = g_z + 2 * lane;

    unsigned long long zzp = 0ull, ssp = 0ull;
    for (int base = beg; base < end; base += 32) {
        int nn = end - base; if (nn > 32) nn = 32;
        int sid = (base + lane < end) ? __ldg(&g_srcs[base + lane]) : 0;
#pragma unroll 4
        for (int j = 0; j < nn; j++) {
            int s = __shfl_sync(0xffffffffu, sid, j);
            float2 v = *(const float2*)(zp + s);
            edge_acc(v, tl2d, zzp, ssp);
        }
    }
    float z0, z1, s0, s1;
    asm("mov.b64 {%0, %1}, %2;" : "=f"(z0), "=f"(z1) : "l"(zzp));
    asm("mov.b64 {%0, %1}, %2;" : "=f"(s0), "=f"(s1) : "l"(ssp));

    float2 zz = *(const float2*)(g_z + gw * HH + 2 * lane);
    float ox = zz.x, oy = zz.y;
    if (end > beg) {
        // s accumulated in scaled domain (m = r*tl2): msg = s/(z*tl2)
        ox += __fdividef(s0, z0 * tl2) + 1e-7f;
        oy += __fdividef(s1, z1 * tl2) + 1e-7f;
    }
    unsigned hw, lw;
    split_pair(ox, oy, hw, lw);
    g_uh[gw * 32 + lane] = hw;
    g_ul[gw * 32 + lane] = lw;
}

// -------- fused MLP: bf16 mma.sync + ldmatrix, 3-term emulated fp32 -------
// also (wz=1) fuses the NEXT layer's z = relu(LN(h)) epilogue.
#define W_PSUM 0
#define W_PSQ  128
#define W_B1   256
#define W_GAM  384
#define W_BET  512
#define W_B2   640
#define W_A    704
#define W_UH   (W_A)
#define W_UL   (W_A + 2304)
#define W_HH   (W_A)
#define W_HL   (W_A + 4352)
#define W_W1H  9408
#define W_W1L  14016
#define W_W2H  18624
#define W_W2L  22976
#define SMEM_MLP_BYTES (27328 * 4)

extern __shared__ unsigned smw[];
__global__ __launch_bounds__(256, 2) void k_mlp(
    const float* __restrict__ b1g, const float* __restrict__ gamg,
    const float* __restrict__ betg, const float* __restrict__ b2g,
    const float* __restrict__ lngN, const float* __restrict__ lnbN,
    int layer, int addm, int wz)
{
    float* smf = (float*)smw;
    int tid = threadIdx.x, w = tid >> 5, lane = tid & 31;
    int g = lane >> 2, t4 = lane & 3;
    int wm = w & 3, wn = w >> 2;
    int n0 = blockIdx.x * 64;
    int lofs = layer * 4096;

    if (tid < 128) {
        smf[W_B1 + tid]  = b1g[tid];
        smf[W_GAM + tid] = gamg[tid];
        smf[W_BET + tid] = betg[tid];
        if (tid < 64) smf[W_B2 + tid] = b2g[tid];
    }
    for (int i = tid * 4; i < 2048; i += 1024) {
        int r = i >> 5, c = i & 31;
        int node = n0 + r;
        uint4 hv = make_uint4(0, 0, 0, 0), lv = hv;
        if (node < NN) {
            hv = *(const uint4*)&g_uh[node * 32 + c];
            lv = *(const uint4*)&g_ul[node * 32 + c];
        }
        *(uint4*)&smw[W_UH + r * 36 + c] = hv;
        *(uint4*)&smw[W_UL + r * 36 + c] = lv;
    }
    for (int i = tid * 4; i < 4096; i += 1024) {
        int r = i >> 5, c = i & 31;
        *(uint4*)&smw[W_W1H + r * 36 + c] = *(const uint4*)&g_w1h[lofs + i];
        *(uint4*)&smw[W_W1L + r * 36 + c] = *(const uint4*)&g_w1l[lofs + i];
    }
    for (int i = tid * 4; i < 4096; i += 1024) {
        int r = i >> 6, c = i & 63;
        *(uint4*)&smw[W_W2H + r * 68 + c] = *(const uint4*)&g_w2h[lofs + i];
        *(uint4*)&smw[W_W2L + r * 68 + c] = *(const uint4*)&g_w2l[lofs + i];
    }
    __syncthreads();

    uint32_t sb = smem_u32(smw);
    int lr = (lane & 7) + ((lane >> 3) & 1) * 8;
    int lhalf = lane >> 4;
    int l8 = lane & 7, lg = lane >> 3;

    // ---- GEMM1 ----
    uint32_t a1H = sb + W_UH * 4 + (16 * wm + lr) * 144 + lhalf * 16;
    uint32_t a1L = a1H + (W_UL - W_UH) * 4;
    uint32_t b1H = sb + W_W1H * 4 + (64 * wn + l8) * 144 + lg * 16;
    uint32_t b1L = b1H + (W_W1L - W_W1H) * 4;

    unsigned aH[4][4], aL[4][4];
#pragma unroll
    for (int ks = 0; ks < 4; ks++) {
        ldsm4(aH[ks][0], aH[ks][1], aH[ks][2], aH[ks][3], a1H + ks * 32);
        ldsm4(aL[ks][0], aL[ks][1], aL[ks][2], aL[ks][3], a1L + ks * 32);
    }
    float c1[8][4];
#pragma unroll
    for (int j = 0; j < 8; j++)
#pragma unroll
        for (int q = 0; q < 4; q++) c1[j][q] = 0.f;

#pragma unroll
    for (int j = 0; j < 8; j++) {
        uint32_t bj = b1H + j * 1152, bjL = b1L + j * 1152;
#pragma unroll
        for (int p = 0; p < 2; p++) {
            unsigned h0, h1, h2, h3, l0, l1, l2, l3;
            ldsm4(h0, h1, h2, h3, bj + p * 64);
            ldsm4(l0, l1, l2, l3, bjL + p * 64);
            int ka = 2 * p, kb = 2 * p + 1;
            mma16(c1[j], aH[ka][0], aH[ka][1], aH[ka][2], aH[ka][3], h0, h1);
            mma16(c1[j], aH[ka][0], aH[ka][1], aH[ka][2], aH[ka][3], l0, l1);
            mma16(c1[j], aL[ka][0], aL[ka][1], aL[ka][2], aL[ka][3], h0, h1);
            mma16(c1[j], aH[kb][0], aH[kb][1], aH[kb][2], aH[kb][3], h2, h3);
            mma16(c1[j], aH[kb][0], aH[kb][1], aH[kb][2], aH[kb][3], l2, l3);
            mma16(c1[j], aL[kb][0], aL[kb][1], aL[kb][2], aL[kb][3], h2, h3);
        }
    }

    // ---- epilogue 1: bias + LN(128) partial sums ----
    int r0 = 16 * wm + g, r1 = r0 + 8;
    float sA = 0.f, sqA = 0.f, sB = 0.f, sqB = 0.f;
#pragma unroll
    for (int j = 0; j < 8; j++) {
        int cb = 64 * wn + 8 * j + 2 * t4;
        float bx = smf[W_B1 + cb], by = smf[W_B1 + cb + 1];
        c1[j][0] += bx; c1[j][1] += by; c1[j][2] += bx; c1[j][3] += by;
        sA += c1[j][0] + c1[j][1];
        sqA = fmaf(c1[j][0], c1[j][0], fmaf(c1[j][1], c1[j][1], sqA));
        sB += c1[j][2] + c1[j][3];
        sqB = fmaf(c1[j][2], c1[j][2], fmaf(c1[j][3], c1[j][3], sqB));
    }
    sA += __shfl_xor_sync(0xffffffffu, sA, 1);  sA += __shfl_xor_sync(0xffffffffu, sA, 2);
    sqA += __shfl_xor_sync(0xffffffffu, sqA, 1); sqA += __shfl_xor_sync(0xffffffffu, sqA, 2);
    sB += __shfl_xor_sync(0xffffffffu, sB, 1);  sB += __shfl_xor_sync(0xffffffffu, sB, 2);
    sqB += __shfl_xor_sync(0xffffffffu, sqB, 1); sqB += __shfl_xor_sync(0xffffffffu, sqB, 2);
    if (t4 == 0) {
        smf[W_PSUM + wn * 64 + r0] = sA;  smf[W_PSQ + wn * 64 + r0] = sqA;
        smf[W_PSUM + wn * 64 + r1] = sB;  smf[W_PSQ + wn * 64 + r1] = sqB;
    }
    __syncthreads();

    float s0 = smf[W_PSUM + r0] + smf[W_PSUM + 64 + r0];
    float q0 = smf[W_PSQ + r0]  + smf[W_PSQ + 64 + r0];
    float s1 = smf[W_PSUM + r1] + smf[W_PSUM + 64 + r1];
    float q1 = smf[W_PSQ + r1]  + smf[W_PSQ + 64 + r1];
    float mu0 = s0 * (1.f / 128.f), mu1 = s1 * (1.f / 128.f);
    float rs0 = rsqrtf(q0 * (1.f / 128.f) - mu0 * mu0 + 1e-5f);
    float rs1 = rsqrtf(q1 * (1.f / 128.f) - mu1 * mu1 + 1e-5f);

#pragma unroll
    for (int j = 0; j < 8; j++) {
        int cb = 64 * wn + 8 * j + 2 * t4;
        float gx = smf[W_GAM + cb], gy = smf[W_GAM + cb + 1];
        float ex = smf[W_BET + cb], ey = smf[W_BET + cb + 1];
        float h0 = fmaxf((c1[j][0] - mu0) * rs0 * gx + ex, 0.f);
        float h1 = fmaxf((c1[j][1] - mu0) * rs0 * gy + ey, 0.f);
        float h2 = fmaxf((c1[j][2] - mu1) * rs1 * gx + ex, 0.f);
        float h3 = fmaxf((c1[j][3] - mu1) * rs1 * gy + ey, 0.f);
        int kp = cb >> 1;
        unsigned hw, lw;
        split_pair(h0, h1, hw, lw);
        smw[W_HH + r0 * 68 + kp] = hw; smw[W_HL + r0 * 68 + kp] = lw;
        split_pair(h2, h3, hw, lw);
        smw[W_HH + r1 * 68 + kp] = hw; smw[W_HL + r1 * 68 + kp] = lw;
    }
    __syncthreads();

    // ---- GEMM2 ----
    uint32_t a2H = sb + W_HH * 4 + (16 * wm + lr) * 272 + lhalf * 16;
    uint32_t a2L = a2H + (W_HL - W_HH) * 4;
    uint32_t b2H = sb + W_W2H * 4 + (32 * wn + l8) * 272 + lg * 16;
    uint32_t b2L = b2H + (W_W2L - W_W2H) * 4;

    float c2[4][4];
#pragma unroll
    for (int j = 0; j < 4; j++)
#pragma unroll
        for (int q = 0; q < 4; q++) c2[j][q] = 0.f;

#pragma unroll
    for (int p = 0; p < 4; p++) {
        unsigned xh[8], xl[8];
        ldsm4(xh[0], xh[1], xh[2], xh[3], a2H + p * 64);
        ldsm4(xh[4], xh[5], xh[6], xh[7], a2H + p * 64 + 32);
        ldsm4(xl[0], xl[1], xl[2], xl[3], a2L + p * 64);
        ldsm4(xl[4], xl[5], xl[6], xl[7], a2L + p * 64 + 32);
#pragma unroll
        for (int j = 0; j < 4; j++) {
            unsigned h0, h1, h2, h3, l0, l1, l2, l3;
            ldsm4(h0, h1, h2, h3, b2H + j * 2176 + p * 64);
            ldsm4(l0, l1, l2, l3, b2L + j * 2176 + p * 64);
            mma16(c2[j], xh[0], xh[1], xh[2], xh[3], h0, h1);
            mma16(c2[j], xh[0], xh[1], xh[2], xh[3], l0, l1);
            mma16(c2[j], xl[0], xl[1], xl[2], xl[3], h0, h1);
            mma16(c2[j], xh[4], xh[5], xh[6], xh[7], h2, h3);
            mma16(c2[j], xh[4], xh[5], xh[6], xh[7], l2, l3);
            mma16(c2[j], xl[4], xl[5], xl[6], xl[7], h2, h3);
        }
    }

    // ---- epilogue 2: bias (+residual) -> g_h ; keep final h in c2 ----
    int node0 = n0 + r0, node1 = n0 + r1;
    float ps0 = 0.f, pq0 = 0.f, ps1 = 0.f, pq1 = 0.f;
#pragma unroll
    for (int j = 0; j < 4; j++) {
        int cb = 32 * wn + 8 * j + 2 * t4;
        float bx = smf[W_B2 + cb], by = smf[W_B2 + cb + 1];
        float h00 = c2[j][0] + bx, h01 = c2[j][1] + by;
        float h10 = c2[j][2] + bx, h11 = c2[j][3] + by;
        if (node0 < NN) {
            float* dst = g_h + node0 * HH + cb;
            if (addm) { float2 pv = *(const float2*)dst; h00 += pv.x; h01 += pv.y; }
            *(float2*)dst = make_float2(h00, h01);
        }
        if (node1 < NN) {
            float* dst = g_h + node1 * HH + cb;
            if (addm) { float2 pv = *(const float2*)dst; h10 += pv.x; h11 += pv.y; }
            *(float2*)dst = make_float2(h10, h11);
        }
        c2[j][0] = h00; c2[j][1] = h01; c2[j][2] = h10; c2[j][3] = h11;
        ps0 += h00 + h01; pq0 = fmaf(h00, h00, fmaf(h01, h01, pq0));
        ps1 += h10 + h11; pq1 = fmaf(h10, h10, fmaf(h11, h11, pq1));
    }

    // ---- fused z = relu(LN_{next}(h)) (wz layers only) ----
    if (wz) {
        ps0 += __shfl_xor_sync(0xffffffffu, ps0, 1); ps0 += __shfl_xor_sync(0xffffffffu, ps0, 2);
        pq0 += __shfl_xor_sync(0xffffffffu, pq0, 1); pq0 += __shfl_xor_sync(0xffffffffu, pq0, 2);
        ps1 += __shfl_xor_sync(0xffffffffu, ps1, 1); ps1 += __shfl_xor_sync(0xffffffffu, ps1, 2);
        pq1 += __shfl_xor_sync(0xffffffffu, pq1, 1); pq1 += __shfl_xor_sync(0xffffffffu, pq1, 2);
        if (t4 == 0) {
            smf[W_PSUM + wn * 64 + r0] = ps0;  smf[W_PSQ + wn * 64 + r0] = pq0;
            smf[W_PSUM + wn * 64 + r1] = ps1;  smf[W_PSQ + wn * 64 + r1] = pq1;
        }
        __syncthreads();
        float S0 = smf[W_PSUM + r0] + smf[W_PSUM + 64 + r0];
        float Q0 = smf[W_PSQ + r0]  + smf[W_PSQ + 64 + r0];
        float S1 = smf[W_PSUM + r1] + smf[W_PSUM + 64 + r1];
        float Q1 = smf[W_PSQ + r1]  + smf[W_PSQ + 64 + r1];
        float m0 = S0 * (1.f / 64.f), m1 = S1 * (1.f / 64.f);
        float v0 = rsqrtf(Q0 * (1.f / 64.f) - m0 * m0 + 1e-5f);
        float v1 = rsqrtf(Q1 * (1.f / 64.f) - m1 * m1 + 1e-5f);
#pragma unroll
        for (int j = 0; j < 4; j++) {
            int cb = 32 * wn + 8 * j + 2 * t4;
            float gx = __ldg(&lngN[cb]), gy = __ldg(&lngN[cb + 1]);
            float ex = __ldg(&lnbN[cb]), ey = __ldg(&lnbN[cb + 1]);
            if (node0 < NN) {
                float z0 = fmaxf((c2[j][0] - m0) * v0 * gx + ex, 0.f);
                float z1 = fmaxf((c2[j][1] - m0) * v0 * gy + ey, 0.f);
                *(float2*)(g_z + node0 * HH + cb) = make_float2(z0, z1);
            }
            if (node1 < NN) {
                float z0 = fmaxf((c2[j][2] - m1) * v1 * gx + ex, 0.f);
                float z1 = fmaxf((c2[j][3] - m1) * v1 * gy + ey, 0.f);
                *(float2*)(g_z + node1 * HH + cb) = make_float2(z0, z1);
            }
        }
    }
}

// -------- final: relu(LN(h)) @ lin_W + lin_b ; also re-zero scratch --------
__global__ void k_final(const float* __restrict__ g, const float* __restrict__ b,
                        const float* __restrict__ lw, const float* __restrict__ lb,
                        float* __restrict__ out) {
    int gw = (blockIdx.x * blockDim.x + threadIdx.x) >> 5;
    if (gw >= NN) return;
    int lane = threadIdx.x & 31;
    if (lane == 1) g_wp[gw] = 0;
    if (gw < 128 && lane == 2) g_sflag[gw] = 0;

    float2 v = *(const float2*)(g_h + gw * HH + 2 * lane);
    float s = v.x + v.y, sq = v.x * v.x + v.y * v.y;
    for (int o = 16; o; o >>= 1) {
        s  += __shfl_xor_sync(0xffffffffu, s, o);
        sq += __shfl_xor_sync(0xffffffffu, sq, o);
    }
    float mu = s * 0.015625f;
    float var = sq * 0.015625f - mu * mu;
    float rs = rsqrtf(var + 1e-5f);
    float a0 = fmaxf((v.x - mu) * rs * g[2 * lane]     + b[2 * lane],     0.f);
    float a1 = fmaxf((v.y - mu) * rs * g[2 * lane + 1] + b[2 * lane + 1], 0.f);
    float o0 = a0 * lw[(2 * lane) * 3 + 0] + a1 * lw[(2 * lane + 1) * 3 + 0];
    float o1 = a0 * lw[(2 * lane) * 3 + 1] + a1 * lw[(2 * lane + 1) * 3 + 1];
    float o2 = a0 * lw[(2 * lane) * 3 + 2] + a1 * lw[(2 * lane + 1) * 3 + 2];
    for (int ww = 16; ww; ww >>= 1) {
        o0 += __shfl_xor_sync(0xffffffffu, o0, ww);
        o1 += __shfl_xor_sync(0xffffffffu, o1, ww);
        o2 += __shfl_xor_sync(0xffffffffu, o2, ww);
    }
    if (lane == 0) {
        out[gw * 3 + 0] = o0 + lb[0];
        out[gw * 3 + 1] = o1 + lb[1];
        out[gw * 3 + 2] = o2 + lb[2];
    }
}

// ---------------- launch ----------------
extern "C" void kernel_launch(void* const* d_in, const int* in_sizes, int n_in,
                              void* d_out, int out_size) {
    const float* x    = (const float*)d_in[0];
    const int*   ei   = (const int*)  d_in[1];
    const float* encW = (const float*)d_in[2];
    const float* encb = (const float*)d_in[3];
    const float* t    = (const float*)d_in[4];
    const float* W1   = (const float*)d_in[5];
    const float* b1   = (const float*)d_in[6];
    const float* mg   = (const float*)d_in[7];
    const float* mb   = (const float*)d_in[8];
    const float* W2   = (const float*)d_in[9];
    const float* b2   = (const float*)d_in[10];
    const float* lng  = (const float*)d_in[11];
    const float* lnb  = (const float*)d_in[12];
    const float* lw   = (const float*)d_in[13];
    const float* lb   = (const float*)d_in[14];
    float* out = (float*)d_out;

    cudaFuncSetAttribute(k_mlp, cudaFuncAttributeMaxDynamicSharedMemorySize, SMEM_MLP_BYTES);

    const int WARP_BLOCKS = (NN * 32 + 255) / 256;
    const int MLP_BLOCKS  = (NN + 63) / 64;
    const int EH_BLOCKS   = (NN * 16 + 255) / 256;   // covers NE and 3*4096 too

    // CSR build + encoder + weight pre-split (launches 0..2)
    k_enc_hist<<<EH_BLOCKS, 256>>>(x, encW, encb, ei, W1, W2);
    k_scan<<<NB_SCAN, 1024>>>();
    k_scatter<<<(NE + 255) / 256, 256>>>(ei);

    // layer 0 (launch index 3 = k_agg -> profiled slot); mlp fuses z for layer 1
    k_agg<<<WARP_BLOCKS, 256>>>(t + 0);
    k_mlp<<<MLP_BLOCKS, 256, SMEM_MLP_BYTES>>>(b1, mg, mb, b2,
                                               lng + HH, lnb + HH, 0, 0, 1);

    // layer 1 (mlp fuses z for layer 2), layer 2 (no z)
    k_agg<<<WARP_BLOCKS, 256>>>(t + 1);
    k_mlp<<<MLP_BLOCKS, 256, SMEM_MLP_BYTES>>>(b1 + H2, mg + H2, mb + H2, b2 + HH,
                                               lng + 2 * HH, lnb + 2 * HH, 1, 1, 1);
    k_agg<<<WARP_BLOCKS, 256>>>(t + 2);
    k_mlp<<<MLP_BLOCKS, 256, SMEM_MLP_BYTES>>>(b1 + 2 * H2, mg + 2 * H2, mb + 2 * H2,
                                               b2 + 2 * HH, lng, lnb, 2, 1, 0);

    // final projection (+ scratch re-zero for next replay)
    k_final<<<WARP_BLOCKS, 256>>>(lng, lnb, lw, lb, out);
}

// round 11
// speedup vs baseline: 1.0485x; 1.0485x over previous
#include <cuda_runtime.h>
#include <cuda_bf16.h>
#include <cstdint>

#define NN 100000
#define NE 1200000
#define HH 64
#define H2 128
#define NB_SCAN 98

// ---------------- device scratch (no allocations allowed) ----------------
__device__ float g_z[NN * HH];      // layer input features (fp32)
__device__ float g_h[NN * HH];      // residual stream (fp32)
__device__ unsigned g_uh[NN * 32];  // MLP input, bf16x2 hi words (k-pairs)
__device__ unsigned g_ul[NN * 32];  // MLP input, bf16x2 lo words
__device__ int   g_rowptr[NN + 1];
__device__ int   g_wp[NN];          // zeroed by previous replay's k_final
__device__ int   g_srcs[NE];        // src ids PRE-SCALED by 64
__device__ int   g_sval[128];
__device__ int   g_sincl[128];
__device__ int   g_sflag[128];      // tail-zeroed by k_final
// pre-split weights, [n][kp] rows (k contiguous as bf16):
__device__ unsigned g_w1h[3 * 4096], g_w1l[3 * 4096];
__device__ unsigned g_w2h[3 * 4096], g_w2l[3 * 4096];

// ---------------- helpers ----------------
__device__ __forceinline__ float ex2(float x) {
    float r; asm("ex2.approx.f32 %0, %1;" : "=f"(r) : "f"(x)); return r;
}
__device__ __forceinline__ unsigned pk_bf2(float xe, float xo) {
    unsigned d;
    asm("cvt.rn.bf16x2.f32 %0, %1, %2;" : "=r"(d) : "f"(xo), "f"(xe));
    return d;
}
__device__ __forceinline__ float lo16f(unsigned w) { return __uint_as_float(w << 16); }
__device__ __forceinline__ float hi16f(unsigned w) { return __uint_as_float(w & 0xffff0000u); }
__device__ __forceinline__ void split_pair(float xe, float xo, unsigned& hw, unsigned& lw) {
    hw = pk_bf2(xe, xo);
    lw = pk_bf2(xe - lo16f(hw), xo - hi16f(hw));
}
__device__ __forceinline__ uint32_t smem_u32(const void* p) {
    uint32_t a;
    asm("{ .reg .u64 t; cvta.to.shared.u64 t, %1; cvt.u32.u64 %0, t; }" : "=r"(a) : "l"(p));
    return a;
}
__device__ __forceinline__ void mma16(float* c, unsigned a0, unsigned a1,
                                      unsigned a2, unsigned a3,
                                      unsigned b0, unsigned b1) {
    asm("mma.sync.aligned.m16n8k16.row.col.f32.bf16.bf16.f32 "
        "{%0,%1,%2,%3}, {%4,%5,%6,%7}, {%8,%9}, {%0,%1,%2,%3};"
        : "+f"(c[0]), "+f"(c[1]), "+f"(c[2]), "+f"(c[3])
        : "r"(a0), "r"(a1), "r"(a2), "r"(a3), "r"(b0), "r"(b1));
}
__device__ __forceinline__ void ldsm4(unsigned& r0, unsigned& r1, unsigned& r2,
                                      unsigned& r3, uint32_t addr) {
    asm volatile("ldmatrix.sync.aligned.m8n8.x4.shared.b16 {%0,%1,%2,%3}, [%4];"
                 : "=r"(r0), "=r"(r1), "=r"(r2), "=r"(r3) : "r"(addr));
}

// ------ launch 0: encoder (x4 vectorized) + histogram + weight pre-split ---
__global__ void k_enc_hist(const float* __restrict__ x, const float* __restrict__ W,
                           const float* __restrict__ b, const int* __restrict__ ei,
                           const float* __restrict__ W1g, const float* __restrict__ W2g) {
    int idx = blockIdx.x * blockDim.x + threadIdx.x;
    if (idx == 0) g_rowptr[NN] = NE;
    if (idx < NE) atomicAdd(&g_wp[ei[NE + idx]], 1);
    if (idx < NN * 16) {
        int n = idx >> 4, c = (idx & 15) * 4;
        float x0 = x[n * 3], x1 = x[n * 3 + 1], x2 = x[n * 3 + 2];
        float4 w0 = *(const float4*)&W[c];
        float4 w1 = *(const float4*)&W[HH + c];
        float4 w2 = *(const float4*)&W[2 * HH + c];
        float4 bb = *(const float4*)&b[c];
        float4 o;
        o.x = x0 * w0.x + x1 * w1.x + x2 * w2.x + bb.x;
        o.y = x0 * w0.y + x1 * w1.y + x2 * w2.y + bb.y;
        o.z = x0 * w0.z + x1 * w1.z + x2 * w2.z + bb.z;
        o.w = x0 * w0.w + x1 * w1.w + x2 * w2.w + bb.w;
        *(float4*)&g_z[n * HH + c] = o;
    }
    if (idx < 3 * 4096) {   // W1^T: idx = l*4096 + n*32 + kp
        int l = idx >> 12, r = idx & 4095, n = r >> 5, kp = r & 31;
        const float* Wl = W1g + l * (HH * H2);
        unsigned hw, lw;
        split_pair(Wl[(2 * kp) * H2 + n], Wl[(2 * kp + 1) * H2 + n], hw, lw);
        g_w1h[idx] = hw; g_w1l[idx] = lw;
    }
    if (idx < 3 * 4096) {   // W2^T: idx = l*4096 + n*64 + kp
        int l = idx >> 12, r = idx & 4095, n = r >> 6, kp = r & 63;
        const float* Wl = W2g + l * (H2 * HH);
        unsigned hw, lw;
        split_pair(Wl[(2 * kp) * HH + n], Wl[(2 * kp + 1) * HH + n], hw, lw);
        g_w2h[idx] = hw; g_w2l[idx] = lw;
    }
}

// ------------- launch 1: single-pass scan (decoupled lookback) -------------
__global__ void k_scan() {
    __shared__ int wsum[32];
    __shared__ int s_excl;
    int t = threadIdx.x, b = blockIdx.x;
    int lane = t & 31, wid = t >> 5;
    int i = b * 1024 + t;
    int x = (i < NN) ? g_wp[i] : 0;

    int v = x;
#pragma unroll
    for (int d = 1; d < 32; d <<= 1) {
        int u = __shfl_up_sync(0xffffffffu, v, d);
        if (lane >= d) v += u;
    }
    if (lane == 31) wsum[wid] = v;
    __syncthreads();
    if (wid == 0) {
        int w = wsum[lane];
#pragma unroll
        for (int d = 1; d < 32; d <<= 1) {
            int u = __shfl_up_sync(0xffffffffu, w, d);
            if (lane >= d) w += u;
        }
        wsum[lane] = w;
    }
    __syncthreads();
    int incl = v + (wid ? wsum[wid - 1] : 0);
    int bsum = wsum[31];

    if (t == 0) {
        if (b == 0) {
            g_sincl[0] = bsum; __threadfence(); g_sflag[0] = 2;
            s_excl = 0;
        } else {
            g_sval[b] = bsum; __threadfence(); g_sflag[b] = 1;
            int excl = 0, j = b - 1;
            while (true) {
                int f;
                do { f = ((volatile int*)g_sflag)[j]; } while (f == 0);
                __threadfence();
                if (f == 2) { excl += ((volatile int*)g_sincl)[j]; break; }
                excl += ((volatile int*)g_sval)[j]; j--;
            }
            g_sincl[b] = excl + bsum; __threadfence(); g_sflag[b] = 2;
            s_excl = excl;
        }
    }
    __syncthreads();
    if (i < NN) {
        int e = s_excl + incl - x;
        g_rowptr[i] = e;
        g_wp[i] = e;
    }
}

// ------------- launch 2: scatter src ids (pre-scaled) into CSR -------------
__global__ void k_scatter(const int* __restrict__ ei) {
    int e = blockIdx.x * blockDim.x + threadIdx.x;
    if (e < NE) {
        int d = ei[NE + e];
        int p = atomicAdd(&g_wp[d], 1);
        g_srcs[p] = ei[e] << 6;   // src * HH
    }
}

// ------- single-pass softmax aggregation (R9 scalar: 32 regs, 80% occ) -----
__global__ __launch_bounds__(256, 8) void k_agg(const float* __restrict__ tptr) {
    int gw = (blockIdx.x * blockDim.x + threadIdx.x) >> 5;
    if (gw >= NN) return;
    int lane = threadIdx.x & 31;
    int beg = g_rowptr[gw], end = g_rowptr[gw + 1];
    float tl2 = __ldg(tptr) * 1.44269504f;
    const float* zp = g_z + 2 * lane;

    float z0 = 0.f, z1 = 0.f, s0 = 0.f, s1 = 0.f;
    for (int base = beg; base < end; base += 32) {
        int nn = end - base; if (nn > 32) nn = 32;
        int sid = (base + lane < end) ? __ldg(&g_srcs[base + lane]) : 0;
#pragma unroll 4
        for (int j = 0; j < nn; j++) {
            int s = __shfl_sync(0xffffffffu, sid, j);
            float2 v = *(const float2*)(zp + s);
            float r0 = fmaxf(v.x, 0.f), r1 = fmaxf(v.y, 0.f);
            float w0 = ex2(r0 * tl2);
            float w1 = ex2(r1 * tl2);
            z0 += w0; z1 += w1;
            s0 = fmaf(r0, w0, s0);
            s1 = fmaf(r1, w1, s1);
        }
    }
    float2 zz = *(const float2*)(g_z + gw * HH + 2 * lane);
    float ox = zz.x, oy = zz.y;
    if (end > beg) {
        ox += __fdividef(s0, z0) + 1e-7f;
        oy += __fdividef(s1, z1) + 1e-7f;
    }
    unsigned hw, lw;
    split_pair(ox, oy, hw, lw);
    g_uh[gw * 32 + lane] = hw;
    g_ul[gw * 32 + lane] = lw;
}

// -------- fused MLP: bf16 mma.sync + ldmatrix, 3-term emulated fp32 -------
// also (wz=1) fuses the NEXT layer's z = relu(LN(h)) epilogue.
#define W_PSUM 0
#define W_PSQ  128
#define W_B1   256
#define W_GAM  384
#define W_BET  512
#define W_B2   640
#define W_A    704
#define W_UH   (W_A)
#define W_UL   (W_A + 2304)
#define W_HH   (W_A)
#define W_HL   (W_A + 4352)
#define W_W1H  9408
#define W_W1L  14016
#define W_W2H  18624
#define W_W2L  22976
#define SMEM_MLP_BYTES (27328 * 4)

extern __shared__ unsigned smw[];
__global__ __launch_bounds__(256, 2) void k_mlp(
    const float* __restrict__ b1g, const float* __restrict__ gamg,
    const float* __restrict__ betg, const float* __restrict__ b2g,
    const float* __restrict__ lngN, const float* __restrict__ lnbN,
    int layer, int addm, int wz)
{
    float* smf = (float*)smw;
    int tid = threadIdx.x, w = tid >> 5, lane = tid & 31;
    int g = lane >> 2, t4 = lane & 3;
    int wm = w & 3, wn = w >> 2;
    int n0 = blockIdx.x * 64;
    int lofs = layer * 4096;

    if (tid < 128) {
        smf[W_B1 + tid]  = b1g[tid];
        smf[W_GAM + tid] = gamg[tid];
        smf[W_BET + tid] = betg[tid];
        if (tid < 64) smf[W_B2 + tid] = b2g[tid];
    }
    for (int i = tid * 4; i < 2048; i += 1024) {
        int r = i >> 5, c = i & 31;
        int node = n0 + r;
        uint4 hv = make_uint4(0, 0, 0, 0), lv = hv;
        if (node < NN) {
            hv = *(const uint4*)&g_uh[node * 32 + c];
            lv = *(const uint4*)&g_ul[node * 32 + c];
        }
        *(uint4*)&smw[W_UH + r * 36 + c] = hv;
        *(uint4*)&smw[W_UL + r * 36 + c] = lv;
    }
    for (int i = tid * 4; i < 4096; i += 1024) {
        int r = i >> 5, c = i & 31;
        *(uint4*)&smw[W_W1H + r * 36 + c] = *(const uint4*)&g_w1h[lofs + i];
        *(uint4*)&smw[W_W1L + r * 36 + c] = *(const uint4*)&g_w1l[lofs + i];
    }
    for (int i = tid * 4; i < 4096; i += 1024) {
        int r = i >> 6, c = i & 63;
        *(uint4*)&smw[W_W2H + r * 68 + c] = *(const uint4*)&g_w2h[lofs + i];
        *(uint4*)&smw[W_W2L + r * 68 + c] = *(const uint4*)&g_w2l[lofs + i];
    }
    __syncthreads();

    uint32_t sb = smem_u32(smw);
    int lr = (lane & 7) + ((lane >> 3) & 1) * 8;
    int lhalf = lane >> 4;
    int l8 = lane & 7, lg = lane >> 3;

    // ---- GEMM1 ----
    uint32_t a1H = sb + W_UH * 4 + (16 * wm + lr) * 144 + lhalf * 16;
    uint32_t a1L = a1H + (W_UL - W_UH) * 4;
    uint32_t b1H = sb + W_W1H * 4 + (64 * wn + l8) * 144 + lg * 16;
    uint32_t b1L = b1H + (W_W1L - W_W1H) * 4;

    unsigned aH[4][4], aL[4][4];
#pragma unroll
    for (int ks = 0; ks < 4; ks++) {
        ldsm4(aH[ks][0], aH[ks][1], aH[ks][2], aH[ks][3], a1H + ks * 32);
        ldsm4(aL[ks][0], aL[ks][1], aL[ks][2], aL[ks][3], a1L + ks * 32);
    }
    float c1[8][4];
#pragma unroll
    for (int j = 0; j < 8; j++)
#pragma unroll
        for (int q = 0; q < 4; q++) c1[j][q] = 0.f;

#pragma unroll
    for (int j = 0; j < 8; j++) {
        uint32_t bj = b1H + j * 1152, bjL = b1L + j * 1152;
#pragma unroll
        for (int p = 0; p < 2; p++) {
            unsigned h0, h1, h2, h3, l0, l1, l2, l3;
            ldsm4(h0, h1, h2, h3, bj + p * 64);
            ldsm4(l0, l1, l2, l3, bjL + p * 64);
            int ka = 2 * p, kb = 2 * p + 1;
            mma16(c1[j], aH[ka][0], aH[ka][1], aH[ka][2], aH[ka][3], h0, h1);
            mma16(c1[j], aH[ka][0], aH[ka][1], aH[ka][2], aH[ka][3], l0, l1);
            mma16(c1[j], aL[ka][0], aL[ka][1], aL[ka][2], aL[ka][3], h0, h1);
            mma16(c1[j], aH[kb][0], aH[kb][1], aH[kb][2], aH[kb][3], h2, h3);
            mma16(c1[j], aH[kb][0], aH[kb][1], aH[kb][2], aH[kb][3], l2, l3);
            mma16(c1[j], aL[kb][0], aL[kb][1], aL[kb][2], aL[kb][3], h2, h3);
        }
    }

    // ---- epilogue 1: bias + LN(128) partial sums ----
    int r0 = 16 * wm + g, r1 = r0 + 8;
    float sA = 0.f, sqA = 0.f, sB = 0.f, sqB = 0.f;
#pragma unroll
    for (int j = 0; j < 8; j++) {
        int cb = 64 * wn + 8 * j + 2 * t4;
        float bx = smf[W_B1 + cb], by = smf[W_B1 + cb + 1];
        c1[j][0] += bx; c1[j][1] += by; c1[j][2] += bx; c1[j][3] += by;
        sA += c1[j][0] + c1[j][1];
        sqA = fmaf(c1[j][0], c1[j][0], fmaf(c1[j][1], c1[j][1], sqA));
        sB += c1[j][2] + c1[j][3];
        sqB = fmaf(c1[j][2], c1[j][2], fmaf(c1[j][3], c1[j][3], sqB));
    }
    sA += __shfl_xor_sync(0xffffffffu, sA, 1);  sA += __shfl_xor_sync(0xffffffffu, sA, 2);
    sqA += __shfl_xor_sync(0xffffffffu, sqA, 1); sqA += __shfl_xor_sync(0xffffffffu, sqA, 2);
    sB += __shfl_xor_sync(0xffffffffu, sB, 1);  sB += __shfl_xor_sync(0xffffffffu, sB, 2);
    sqB += __shfl_xor_sync(0xffffffffu, sqB, 1); sqB += __shfl_xor_sync(0xffffffffu, sqB, 2);
    if (t4 == 0) {
        smf[W_PSUM + wn * 64 + r0] = sA;  smf[W_PSQ + wn * 64 + r0] = sqA;
        smf[W_PSUM + wn * 64 + r1] = sB;  smf[W_PSQ + wn * 64 + r1] = sqB;
    }
    __syncthreads();

    float s0 = smf[W_PSUM + r0] + smf[W_PSUM + 64 + r0];
    float q0 = smf[W_PSQ + r0]  + smf[W_PSQ + 64 + r0];
    float s1 = smf[W_PSUM + r1] + smf[W_PSUM + 64 + r1];
    float q1 = smf[W_PSQ + r1]  + smf[W_PSQ + 64 + r1];
    float mu0 = s0 * (1.f / 128.f), mu1 = s1 * (1.f / 128.f);
    float rs0 = rsqrtf(q0 * (1.f / 128.f) - mu0 * mu0 + 1e-5f);
    float rs1 = rsqrtf(q1 * (1.f / 128.f) - mu1 * mu1 + 1e-5f);

#pragma unroll
    for (int j = 0; j < 8; j++) {
        int cb = 64 * wn + 8 * j + 2 * t4;
        float gx = smf[W_GAM + cb], gy = smf[W_GAM + cb + 1];
        float ex = smf[W_BET + cb], ey = smf[W_BET + cb + 1];
        float h0 = fmaxf((c1[j][0] - mu0) * rs0 * gx + ex, 0.f);
        float h1 = fmaxf((c1[j][1] - mu0) * rs0 * gy + ey, 0.f);
        float h2 = fmaxf((c1[j][2] - mu1) * rs1 * gx + ex, 0.f);
        float h3 = fmaxf((c1[j][3] - mu1) * rs1 * gy + ey, 0.f);
        int kp = cb >> 1;
        unsigned hw, lw;
        split_pair(h0, h1, hw, lw);
        smw[W_HH + r0 * 68 + kp] = hw; smw[W_HL + r0 * 68 + kp] = lw;
        split_pair(h2, h3, hw, lw);
        smw[W_HH + r1 * 68 + kp] = hw; smw[W_HL + r1 * 68 + kp] = lw;
    }
    __syncthreads();

    // ---- GEMM2 ----
    uint32_t a2H = sb + W_HH * 4 + (16 * wm + lr) * 272 + lhalf * 16;
    uint32_t a2L = a2H + (W_HL - W_HH) * 4;
    uint32_t b2H = sb + W_W2H * 4 + (32 * wn + l8) * 272 + lg * 16;
    uint32_t b2L = b2H + (W_W2L - W_W2H) * 4;

    float c2[4][4];
#pragma unroll
    for (int j = 0; j < 4; j++)
#pragma unroll
        for (int q = 0; q < 4; q++) c2[j][q] = 0.f;

#pragma unroll
    for (int p = 0; p < 4; p++) {
        unsigned xh[8], xl[8];
        ldsm4(xh[0], xh[1], xh[2], xh[3], a2H + p * 64);
        ldsm4(xh[4], xh[5], xh[6], xh[7], a2H + p * 64 + 32);
        ldsm4(xl[0], xl[1], xl[2], xl[3], a2L + p * 64);
        ldsm4(xl[4], xl[5], xl[6], xl[7], a2L + p * 64 + 32);
#pragma unroll
        for (int j = 0; j < 4; j++) {
            unsigned h0, h1, h2, h3, l0, l1, l2, l3;
            ldsm4(h0, h1, h2, h3, b2H + j * 2176 + p * 64);
            ldsm4(l0, l1, l2, l3, b2L + j * 2176 + p * 64);
            mma16(c2[j], xh[0], xh[1], xh[2], xh[3], h0, h1);
            mma16(c2[j], xh[0], xh[1], xh[2], xh[3], l0, l1);
            mma16(c2[j], xl[0], xl[1], xl[2], xl[3], h0, h1);
            mma16(c2[j], xh[4], xh[5], xh[6], xh[7], h2, h3);
            mma16(c2[j], xh[4], xh[5], xh[6], xh[7], l2, l3);
            mma16(c2[j], xl[4], xl[5], xl[6], xl[7], h2, h3);
        }
    }

    // ---- epilogue 2: bias (+residual) -> g_h ; keep final h in c2 ----
    int node0 = n0 + r0, node1 = n0 + r1;
    float ps0 = 0.f, pq0 = 0.f, ps1 = 0.f, pq1 = 0.f;
#pragma unroll
    for (int j = 0; j < 4; j++) {
        int cb = 32 * wn + 8 * j + 2 * t4;
        float bx = smf[W_B2 + cb], by = smf[W_B2 + cb + 1];
        float h00 = c2[j][0] + bx, h01 = c2[j][1] + by;
        float h10 = c2[j][2] + bx, h11 = c2[j][3] + by;
        if (node0 < NN) {
            float* dst = g_h + node0 * HH + cb;
            if (addm) { float2 pv = *(const float2*)dst; h00 += pv.x; h01 += pv.y; }
            *(float2*)dst = make_float2(h00, h01);
        }
        if (node1 < NN) {
            float* dst = g_h + node1 * HH + cb;
            if (addm) { float2 pv = *(const float2*)dst; h10 += pv.x; h11 += pv.y; }
            *(float2*)dst = make_float2(h10, h11);
        }
        c2[j][0] = h00; c2[j][1] = h01; c2[j][2] = h10; c2[j][3] = h11;
        ps0 += h00 + h01; pq0 = fmaf(h00, h00, fmaf(h01, h01, pq0));
        ps1 += h10 + h11; pq1 = fmaf(h10, h10, fmaf(h11, h11, pq1));
    }

    // ---- fused z = relu(LN_{next}(h)) (wz layers only) ----
    if (wz) {
        ps0 += __shfl_xor_sync(0xffffffffu, ps0, 1); ps0 += __shfl_xor_sync(0xffffffffu, ps0, 2);
        pq0 += __shfl_xor_sync(0xffffffffu, pq0, 1); pq0 += __shfl_xor_sync(0xffffffffu, pq0, 2);
        ps1 += __shfl_xor_sync(0xffffffffu, ps1, 1); ps1 += __shfl_xor_sync(0xffffffffu, ps1, 2);
        pq1 += __shfl_xor_sync(0xffffffffu, pq1, 1); pq1 += __shfl_xor_sync(0xffffffffu, pq1, 2);
        if (t4 == 0) {
            smf[W_PSUM + wn * 64 + r0] = ps0;  smf[W_PSQ + wn * 64 + r0] = pq0;
            smf[W_PSUM + wn * 64 + r1] = ps1;  smf[W_PSQ + wn * 64 + r1] = pq1;
        }
        __syncthreads();
        float S0 = smf[W_PSUM + r0] + smf[W_PSUM + 64 + r0];
        float Q0 = smf[W_PSQ + r0]  + smf[W_PSQ + 64 + r0];
        float S1 = smf[W_PSUM + r1] + smf[W_PSUM + 64 + r1];
        float Q1 = smf[W_PSQ + r1]  + smf[W_PSQ + 64 + r1];
        float m0 = S0 * (1.f / 64.f), m1 = S1 * (1.f / 64.f);
        float v0 = rsqrtf(Q0 * (1.f / 64.f) - m0 * m0 + 1e-5f);
        float v1 = rsqrtf(Q1 * (1.f / 64.f) - m1 * m1 + 1e-5f);
#pragma unroll
        for (int j = 0; j < 4; j++) {
            int cb = 32 * wn + 8 * j + 2 * t4;
            float gx = __ldg(&lngN[cb]), gy = __ldg(&lngN[cb + 1]);
            float ex = __ldg(&lnbN[cb]), ey = __ldg(&lnbN[cb + 1]);
            if (node0 < NN) {
                float z0 = fmaxf((c2[j][0] - m0) * v0 * gx + ex, 0.f);
                float z1 = fmaxf((c2[j][1] - m0) * v0 * gy + ey, 0.f);
                *(float2*)(g_z + node0 * HH + cb) = make_float2(z0, z1);
            }
            if (node1 < NN) {
                float z0 = fmaxf((c2[j][2] - m1) * v1 * gx + ex, 0.f);
                float z1 = fmaxf((c2[j][3] - m1) * v1 * gy + ey, 0.f);
                *(float2*)(g_z + node1 * HH + cb) = make_float2(z0, z1);
            }
        }
    }
}

// -------- final: relu(LN(h)) @ lin_W + lin_b ; also re-zero scratch --------
__global__ void k_final(const float* __restrict__ g, const float* __restrict__ b,
                        const float* __restrict__ lw, const float* __restrict__ lb,
                        float* __restrict__ out) {
    int gw = (blockIdx.x * blockDim.x + threadIdx.x) >> 5;
    if (gw >= NN) return;
    int lane = threadIdx.x & 31;
    if (lane == 1) g_wp[gw] = 0;
    if (gw < 128 && lane == 2) g_sflag[gw] = 0;

    float2 v = *(const float2*)(g_h + gw * HH + 2 * lane);
    float s = v.x + v.y, sq = v.x * v.x + v.y * v.y;
    for (int o = 16; o; o >>= 1) {
        s  += __shfl_xor_sync(0xffffffffu, s, o);
        sq += __shfl_xor_sync(0xffffffffu, sq, o);
    }
    float mu = s * 0.015625f;
    float var = sq * 0.015625f - mu * mu;
    float rs = rsqrtf(var + 1e-5f);
    float a0 = fmaxf((v.x - mu) * rs * g[2 * lane]     + b[2 * lane],     0.f);
    float a1 = fmaxf((v.y - mu) * rs * g[2 * lane + 1] + b[2 * lane + 1], 0.f);
    float o0 = a0 * lw[(2 * lane) * 3 + 0] + a1 * lw[(2 * lane + 1) * 3 + 0];
    float o1 = a0 * lw[(2 * lane) * 3 + 1] + a1 * lw[(2 * lane + 1) * 3 + 1];
    float o2 = a0 * lw[(2 * lane) * 3 + 2] + a1 * lw[(2 * lane + 1) * 3 + 2];
    for (int ww = 16; ww; ww >>= 1) {
        o0 += __shfl_xor_sync(0xffffffffu, o0, ww);
        o1 += __shfl_xor_sync(0xffffffffu, o1, ww);
        o2 += __shfl_xor_sync(0xffffffffu, o2, ww);
    }
    if (lane == 0) {
        out[gw * 3 + 0] = o0 + lb[0];
        out[gw * 3 + 1] = o1 + lb[1];
        out[gw * 3 + 2] = o2 + lb[2];
    }
}

// ---------------- launch ----------------
extern "C" void kernel_launch(void* const* d_in, const int* in_sizes, int n_in,
                              void* d_out, int out_size) {
    const float* x    = (const float*)d_in[0];
    const int*   ei   = (const int*)  d_in[1];
    const float* encW = (const float*)d_in[2];
    const float* encb = (const float*)d_in[3];
    const float* t    = (const float*)d_in[4];
    const float* W1   = (const float*)d_in[5];
    const float* b1   = (const float*)d_in[6];
    const float* mg   = (const float*)d_in[7];
    const float* mb   = (const float*)d_in[8];
    const float* W2   = (const float*)d_in[9];
    const float* b2   = (const float*)d_in[10];
    const float* lng  = (const float*)d_in[11];
    const float* lnb  = (const float*)d_in[12];
    const float* lw   = (const float*)d_in[13];
    const float* lb   = (const float*)d_in[14];
    float* out = (float*)d_out;

    cudaFuncSetAttribute(k_mlp, cudaFuncAttributeMaxDynamicSharedMemorySize, SMEM_MLP_BYTES);

    const int WARP_BLOCKS = (NN * 32 + 255) / 256;
    const int MLP_BLOCKS  = (NN + 63) / 64;
    const int EH_BLOCKS   = (NN * 16 + 255) / 256;   // covers NE and 3*4096 too

    // CSR build + encoder + weight pre-split (launches 0..2)
    k_enc_hist<<<EH_BLOCKS, 256>>>(x, encW, encb, ei, W1, W2);
    k_scan<<<NB_SCAN, 1024>>>();
    k_scatter<<<(NE + 255) / 256, 256>>>(ei);

    // layer 0 (launch index 3 = k_agg -> profiled slot); mlp fuses z for layer 1
    k_agg<<<WARP_BLOCKS, 256>>>(t + 0);
    k_mlp<<<MLP_BLOCKS, 256, SMEM_MLP_BYTES>>>(b1, mg, mb, b2,
                                               lng + HH, lnb + HH, 0, 0, 1);

    // layer 1 (mlp fuses z for layer 2), layer 2 (no z)
    k_agg<<<WARP_BLOCKS, 256>>>(t + 1);
    k_mlp<<<MLP_BLOCKS, 256, SMEM_MLP_BYTES>>>(b1 + H2, mg + H2, mb + H2, b2 + HH,
                                               lng + 2 * HH, lnb + 2 * HH, 1, 1, 1);
    k_agg<<<WARP_BLOCKS, 256>>>(t + 2);
    k_mlp<<<MLP_BLOCKS, 256, SMEM_MLP_BYTES>>>(b1 + 2 * H2, mg + 2 * H2, mb + 2 * H2,
                                               b2 + 2 * HH, lng, lnb, 2, 1, 0);

    // final projection (+ scratch re-zero for next replay)
    k_final<<<WARP_BLOCKS, 256>>>(lng, lnb, lw, lb, out);
}

// round 12
// speedup vs baseline: 1.1026x; 1.0516x over previous
#include <cuda_runtime.h>
#include <cuda_bf16.h>
#include <cstdint>

#define NN 100000
#define NE 1200000
#define HH 64
#define H2 128
#define NB_SCAN 98

// ---------------- device scratch (no allocations allowed) ----------------
__device__ float g_z[NN * HH];      // layer input features (fp32)
__device__ float g_h[NN * HH];      // residual stream (fp32)
__device__ unsigned g_uh[NN * 32];  // MLP input, bf16x2 hi words (k-pairs)
__device__ unsigned g_ul[NN * 32];  // MLP input, bf16x2 lo words
__device__ int   g_rowptr[NN + 1];
__device__ int   g_wp[NN];          // zeroed by previous replay's k_final
__device__ int   g_srcs[NE];        // src ids PRE-SCALED by 64
__device__ int   g_sval[128];
__device__ int   g_sincl[128];
__device__ int   g_sflag[128];      // tail-zeroed by k_final
// pre-split weights, [n][kp] rows (k contiguous as bf16):
__device__ unsigned g_w1h[3 * 4096], g_w1l[3 * 4096];
__device__ unsigned g_w2h[3 * 4096], g_w2l[3 * 4096];

// ---------------- helpers ----------------
__device__ __forceinline__ float ex2(float x) {
    float r; asm("ex2.approx.f32 %0, %1;" : "=f"(r) : "f"(x)); return r;
}
__device__ __forceinline__ unsigned pk_bf2(float xe, float xo) {
    unsigned d;
    asm("cvt.rn.bf16x2.f32 %0, %1, %2;" : "=r"(d) : "f"(xo), "f"(xe));
    return d;
}
__device__ __forceinline__ float lo16f(unsigned w) { return __uint_as_float(w << 16); }
__device__ __forceinline__ float hi16f(unsigned w) { return __uint_as_float(w & 0xffff0000u); }
__device__ __forceinline__ void split_pair(float xe, float xo, unsigned& hw, unsigned& lw) {
    hw = pk_bf2(xe, xo);
    lw = pk_bf2(xe - lo16f(hw), xo - hi16f(hw));
}
__device__ __forceinline__ uint32_t smem_u32(const void* p) {
    uint32_t a;
    asm("{ .reg .u64 t; cvta.to.shared.u64 t, %1; cvt.u32.u64 %0, t; }" : "=r"(a) : "l"(p));
    return a;
}
__device__ __forceinline__ void mma16(float* c, unsigned a0, unsigned a1,
                                      unsigned a2, unsigned a3,
                                      unsigned b0, unsigned b1) {
    asm("mma.sync.aligned.m16n8k16.row.col.f32.bf16.bf16.f32 "
        "{%0,%1,%2,%3}, {%4,%5,%6,%7}, {%8,%9}, {%0,%1,%2,%3};"
        : "+f"(c[0]), "+f"(c[1]), "+f"(c[2]), "+f"(c[3])
        : "r"(a0), "r"(a1), "r"(a2), "r"(a3), "r"(b0), "r"(b1));
}
__device__ __forceinline__ void ldsm4(unsigned& r0, unsigned& r1, unsigned& r2,
                                      unsigned& r3, uint32_t addr) {
    asm volatile("ldmatrix.sync.aligned.m8n8.x4.shared.b16 {%0,%1,%2,%3}, [%4];"
                 : "=r"(r0), "=r"(r1), "=r"(r2), "=r"(r3) : "r"(addr));
}

// ------ launch 0: encoder (x4 vectorized) + histogram + weight pre-split ---
__global__ void k_enc_hist(const float* __restrict__ x, const float* __restrict__ W,
                           const float* __restrict__ b, const int* __restrict__ ei,
                           const float* __restrict__ W1g, const float* __restrict__ W2g) {
    int idx = blockIdx.x * blockDim.x + threadIdx.x;
    if (idx == 0) g_rowptr[NN] = NE;
    if (idx < NE) atomicAdd(&g_wp[ei[NE + idx]], 1);
    if (idx < NN * 16) {
        int n = idx >> 4, c = (idx & 15) * 4;
        float x0 = x[n * 3], x1 = x[n * 3 + 1], x2 = x[n * 3 + 2];
        float4 w0 = *(const float4*)&W[c];
        float4 w1 = *(const float4*)&W[HH + c];
        float4 w2 = *(const float4*)&W[2 * HH + c];
        float4 bb = *(const float4*)&b[c];
        float4 o;
        o.x = x0 * w0.x + x1 * w1.x + x2 * w2.x + bb.x;
        o.y = x0 * w0.y + x1 * w1.y + x2 * w2.y + bb.y;
        o.z = x0 * w0.z + x1 * w1.z + x2 * w2.z + bb.z;
        o.w = x0 * w0.w + x1 * w1.w + x2 * w2.w + bb.w;
        *(float4*)&g_z[n * HH + c] = o;
    }
    if (idx < 3 * 4096) {   // W1^T: idx = l*4096 + n*32 + kp
        int l = idx >> 12, r = idx & 4095, n = r >> 5, kp = r & 31;
        const float* Wl = W1g + l * (HH * H2);
        unsigned hw, lw;
        split_pair(Wl[(2 * kp) * H2 + n], Wl[(2 * kp + 1) * H2 + n], hw, lw);
        g_w1h[idx] = hw; g_w1l[idx] = lw;
    }
    if (idx < 3 * 4096) {   // W2^T: idx = l*4096 + n*64 + kp
        int l = idx >> 12, r = idx & 4095, n = r >> 6, kp = r & 63;
        const float* Wl = W2g + l * (H2 * HH);
        unsigned hw, lw;
        split_pair(Wl[(2 * kp) * HH + n], Wl[(2 * kp + 1) * HH + n], hw, lw);
        g_w2h[idx] = hw; g_w2l[idx] = lw;
    }
}

// ------------- launch 1: single-pass scan (decoupled lookback) -------------
__global__ void k_scan() {
    __shared__ int wsum[32];
    __shared__ int s_excl;
    int t = threadIdx.x, b = blockIdx.x;
    int lane = t & 31, wid = t >> 5;
    int i = b * 1024 + t;
    int x = (i < NN) ? g_wp[i] : 0;

    int v = x;
#pragma unroll
    for (int d = 1; d < 32; d <<= 1) {
        int u = __shfl_up_sync(0xffffffffu, v, d);
        if (lane >= d) v += u;
    }
    if (lane == 31) wsum[wid] = v;
    __syncthreads();
    if (wid == 0) {
        int w = wsum[lane];
#pragma unroll
        for (int d = 1; d < 32; d <<= 1) {
            int u = __shfl_up_sync(0xffffffffu, w, d);
            if (lane >= d) w += u;
        }
        wsum[lane] = w;
    }
    __syncthreads();
    int incl = v + (wid ? wsum[wid - 1] : 0);
    int bsum = wsum[31];

    if (t == 0) {
        if (b == 0) {
            g_sincl[0] = bsum; __threadfence(); g_sflag[0] = 2;
            s_excl = 0;
        } else {
            g_sval[b] = bsum; __threadfence(); g_sflag[b] = 1;
            int excl = 0, j = b - 1;
            while (true) {
                int f;
                do { f = ((volatile int*)g_sflag)[j]; } while (f == 0);
                __threadfence();
                if (f == 2) { excl += ((volatile int*)g_sincl)[j]; break; }
                excl += ((volatile int*)g_sval)[j]; j--;
            }
            g_sincl[b] = excl + bsum; __threadfence(); g_sflag[b] = 2;
            s_excl = excl;
        }
    }
    __syncthreads();
    if (i < NN) {
        int e = s_excl + incl - x;
        g_rowptr[i] = e;
        g_wp[i] = e;
    }
}

// ------------- launch 2: scatter src ids (pre-scaled) into CSR -------------
__global__ void k_scatter(const int* __restrict__ ei) {
    int e = blockIdx.x * blockDim.x + threadIdx.x;
    if (e < NE) {
        int d = ei[NE + e];
        int p = atomicAdd(&g_wp[d], 1);
        g_srcs[p] = ei[e] << 6;   // src * HH
    }
}

// ------- single-pass softmax aggregation (R9 scalar: 32 regs, 80% occ) -----
__global__ __launch_bounds__(256, 8) void k_agg(const float* __restrict__ tptr) {
    int gw = (blockIdx.x * blockDim.x + threadIdx.x) >> 5;
    if (gw >= NN) return;
    int lane = threadIdx.x & 31;
    int beg = g_rowptr[gw], end = g_rowptr[gw + 1];
    float tl2 = __ldg(tptr) * 1.44269504f;
    const float* zp = g_z + 2 * lane;

    float z0 = 0.f, z1 = 0.f, s0 = 0.f, s1 = 0.f;
    for (int base = beg; base < end; base += 32) {
        int nn = end - base; if (nn > 32) nn = 32;
        int sid = (base + lane < end) ? __ldg(&g_srcs[base + lane]) : 0;
#pragma unroll 4
        for (int j = 0; j < nn; j++) {
            int s = __shfl_sync(0xffffffffu, sid, j);
            float2 v = *(const float2*)(zp + s);
            float r0 = fmaxf(v.x, 0.f), r1 = fmaxf(v.y, 0.f);
            float w0 = ex2(r0 * tl2);
            float w1 = ex2(r1 * tl2);
            z0 += w0; z1 += w1;
            s0 = fmaf(r0, w0, s0);
            s1 = fmaf(r1, w1, s1);
        }
    }
    float2 zz = *(const float2*)(g_z + gw * HH + 2 * lane);
    float ox = zz.x, oy = zz.y;
    if (end > beg) {
        ox += __fdividef(s0, z0) + 1e-7f;
        oy += __fdividef(s1, z1) + 1e-7f;
    }
    unsigned hw, lw;
    split_pair(ox, oy, hw, lw);
    g_uh[gw * 32 + lane] = hw;
    g_ul[gw * 32 + lane] = lw;
}

// -------- fused MLP: bf16 mma.sync + ldmatrix, 3-term emulated fp32 -------
// W1 and W2 SHARE one smem region (W2 loaded after GEMM1). 74.5KB -> 3 blk/SM.
// also (wz=1) fuses the NEXT layer's z = relu(LN(h)) epilogue.
#define W_PSUM 0
#define W_PSQ  128
#define W_B1   256
#define W_GAM  384
#define W_BET  512
#define W_B2   640
#define W_A    704
#define W_UH   (W_A)
#define W_UL   (W_A + 2304)
#define W_HH   (W_A)
#define W_HL   (W_A + 4352)
#define W_W    9408
#define W_W1H  (W_W)
#define W_W1L  (W_W + 4608)
#define W_W2H  (W_W)
#define W_W2L  (W_W + 4352)
#define SMEM_MLP_WORDS 18624
#define SMEM_MLP_BYTES (SMEM_MLP_WORDS * 4)

extern __shared__ unsigned smw[];
__global__ __launch_bounds__(256, 3) void k_mlp(
    const float* __restrict__ b1g, const float* __restrict__ gamg,
    const float* __restrict__ betg, const float* __restrict__ b2g,
    const float* __restrict__ lngN, const float* __restrict__ lnbN,
    int layer, int addm, int wz)
{
    float* smf = (float*)smw;
    int tid = threadIdx.x, w = tid >> 5, lane = tid & 31;
    int g = lane >> 2, t4 = lane & 3;
    int wm = w & 3, wn = w >> 2;
    int n0 = blockIdx.x * 64;
    int lofs = layer * 4096;

    if (tid < 128) {
        smf[W_B1 + tid]  = b1g[tid];
        smf[W_GAM + tid] = gamg[tid];
        smf[W_BET + tid] = betg[tid];
        if (tid < 64) smf[W_B2 + tid] = b2g[tid];
    }
    for (int i = tid * 4; i < 2048; i += 1024) {
        int r = i >> 5, c = i & 31;
        int node = n0 + r;
        uint4 hv = make_uint4(0, 0, 0, 0), lv = hv;
        if (node < NN) {
            hv = *(const uint4*)&g_uh[node * 32 + c];
            lv = *(const uint4*)&g_ul[node * 32 + c];
        }
        *(uint4*)&smw[W_UH + r * 36 + c] = hv;
        *(uint4*)&smw[W_UL + r * 36 + c] = lv;
    }
    for (int i = tid * 4; i < 4096; i += 1024) {
        int r = i >> 5, c = i & 31;
        *(uint4*)&smw[W_W1H + r * 36 + c] = *(const uint4*)&g_w1h[lofs + i];
        *(uint4*)&smw[W_W1L + r * 36 + c] = *(const uint4*)&g_w1l[lofs + i];
    }
    __syncthreads();

    uint32_t sb = smem_u32(smw);
    int lr = (lane & 7) + ((lane >> 3) & 1) * 8;
    int lhalf = lane >> 4;
    int l8 = lane & 7, lg = lane >> 3;

    // ---- GEMM1 (k-outer / j-inner: only 16 A-frag regs live) ----
    uint32_t a1H = sb + W_UH * 4 + (16 * wm + lr) * 144 + lhalf * 16;
    uint32_t a1L = a1H + (W_UL - W_UH) * 4;
    uint32_t b1H = sb + W_W1H * 4 + (64 * wn + l8) * 144 + lg * 16;
    uint32_t b1L = b1H + (W_W1L - W_W1H) * 4;

    float c1[8][4];
#pragma unroll
    for (int j = 0; j < 8; j++)
#pragma unroll
        for (int q = 0; q < 4; q++) c1[j][q] = 0.f;

#pragma unroll
    for (int p = 0; p < 2; p++) {
        unsigned aH0[4], aH1[4], aL0[4], aL1[4];
        ldsm4(aH0[0], aH0[1], aH0[2], aH0[3], a1H + p * 64);
        ldsm4(aH1[0], aH1[1], aH1[2], aH1[3], a1H + p * 64 + 32);
        ldsm4(aL0[0], aL0[1], aL0[2], aL0[3], a1L + p * 64);
        ldsm4(aL1[0], aL1[1], aL1[2], aL1[3], a1L + p * 64 + 32);
#pragma unroll
        for (int j = 0; j < 8; j++) {
            unsigned h0, h1, h2, h3, l0, l1, l2, l3;
            ldsm4(h0, h1, h2, h3, b1H + j * 1152 + p * 64);
            ldsm4(l0, l1, l2, l3, b1L + j * 1152 + p * 64);
            mma16(c1[j], aH0[0], aH0[1], aH0[2], aH0[3], h0, h1);
            mma16(c1[j], aH0[0], aH0[1], aH0[2], aH0[3], l0, l1);
            mma16(c1[j], aL0[0], aL0[1], aL0[2], aL0[3], h0, h1);
            mma16(c1[j], aH1[0], aH1[1], aH1[2], aH1[3], h2, h3);
            mma16(c1[j], aH1[0], aH1[1], aH1[2], aH1[3], l2, l3);
            mma16(c1[j], aL1[0], aL1[1], aL1[2], aL1[3], h2, h3);
        }
    }

    // ---- epilogue 1: bias + LN(128) partial sums ----
    int r0 = 16 * wm + g, r1 = r0 + 8;
    float sA = 0.f, sqA = 0.f, sB = 0.f, sqB = 0.f;
#pragma unroll
    for (int j = 0; j < 8; j++) {
        int cb = 64 * wn + 8 * j + 2 * t4;
        float bx = smf[W_B1 + cb], by = smf[W_B1 + cb + 1];
        c1[j][0] += bx; c1[j][1] += by; c1[j][2] += bx; c1[j][3] += by;
        sA += c1[j][0] + c1[j][1];
        sqA = fmaf(c1[j][0], c1[j][0], fmaf(c1[j][1], c1[j][1], sqA));
        sB += c1[j][2] + c1[j][3];
        sqB = fmaf(c1[j][2], c1[j][2], fmaf(c1[j][3], c1[j][3], sqB));
    }
    sA += __shfl_xor_sync(0xffffffffu, sA, 1);  sA += __shfl_xor_sync(0xffffffffu, sA, 2);
    sqA += __shfl_xor_sync(0xffffffffu, sqA, 1); sqA += __shfl_xor_sync(0xffffffffu, sqA, 2);
    sB += __shfl_xor_sync(0xffffffffu, sB, 1);  sB += __shfl_xor_sync(0xffffffffu, sB, 2);
    sqB += __shfl_xor_sync(0xffffffffu, sqB, 1); sqB += __shfl_xor_sync(0xffffffffu, sqB, 2);
    if (t4 == 0) {
        smf[W_PSUM + wn * 64 + r0] = sA;  smf[W_PSQ + wn * 64 + r0] = sqA;
        smf[W_PSUM + wn * 64 + r1] = sB;  smf[W_PSQ + wn * 64 + r1] = sqB;
    }
    __syncthreads();   // all GEMM1 W1-reads done; W-region free for W2

    // ---- load W2 splits into the shared W region (overlaps LN math) ----
    for (int i = tid * 4; i < 4096; i += 1024) {
        int r = i >> 6, c = i & 63;
        *(uint4*)&smw[W_W2H + r * 68 + c] = *(const uint4*)&g_w2h[lofs + i];
        *(uint4*)&smw[W_W2L + r * 68 + c] = *(const uint4*)&g_w2l[lofs + i];
    }

    float s0 = smf[W_PSUM + r0] + smf[W_PSUM + 64 + r0];
    float q0 = smf[W_PSQ + r0]  + smf[W_PSQ + 64 + r0];
    float s1 = smf[W_PSUM + r1] + smf[W_PSUM + 64 + r1];
    float q1 = smf[W_PSQ + r1]  + smf[W_PSQ + 64 + r1];
    float mu0 = s0 * (1.f / 128.f), mu1 = s1 * (1.f / 128.f);
    float rs0 = rsqrtf(q0 * (1.f / 128.f) - mu0 * mu0 + 1e-5f);
    float rs1 = rsqrtf(q1 * (1.f / 128.f) - mu1 * mu1 + 1e-5f);

#pragma unroll
    for (int j = 0; j < 8; j++) {
        int cb = 64 * wn + 8 * j + 2 * t4;
        float gx = smf[W_GAM + cb], gy = smf[W_GAM + cb + 1];
        float ex = smf[W_BET + cb], ey = smf[W_BET + cb + 1];
        float h0 = fmaxf((c1[j][0] - mu0) * rs0 * gx + ex, 0.f);
        float h1 = fmaxf((c1[j][1] - mu0) * rs0 * gy + ey, 0.f);
        float h2 = fmaxf((c1[j][2] - mu1) * rs1 * gx + ex, 0.f);
        float h3 = fmaxf((c1[j][3] - mu1) * rs1 * gy + ey, 0.f);
        int kp = cb >> 1;
        unsigned hw, lw;
        split_pair(h0, h1, hw, lw);
        smw[W_HH + r0 * 68 + kp] = hw; smw[W_HL + r0 * 68 + kp] = lw;
        split_pair(h2, h3, hw, lw);
        smw[W_HH + r1 * 68 + kp] = hw; smw[W_HL + r1 * 68 + kp] = lw;
    }
    __syncthreads();   // act + W2 both visible

    // ---- GEMM2 ----
    uint32_t a2H = sb + W_HH * 4 + (16 * wm + lr) * 272 + lhalf * 16;
    uint32_t a2L = a2H + (W_HL - W_HH) * 4;
    uint32_t b2H = sb + W_W2H * 4 + (32 * wn + l8) * 272 + lg * 16;
    uint32_t b2L = b2H + (W_W2L - W_W2H) * 4;

    float c2[4][4];
#pragma unroll
    for (int j = 0; j < 4; j++)
#pragma unroll
        for (int q = 0; q < 4; q++) c2[j][q] = 0.f;

#pragma unroll
    for (int p = 0; p < 4; p++) {
        unsigned xh[8], xl[8];
        ldsm4(xh[0], xh[1], xh[2], xh[3], a2H + p * 64);
        ldsm4(xh[4], xh[5], xh[6], xh[7], a2H + p * 64 + 32);
        ldsm4(xl[0], xl[1], xl[2], xl[3], a2L + p * 64);
        ldsm4(xl[4], xl[5], xl[6], xl[7], a2L + p * 64 + 32);
#pragma unroll
        for (int j = 0; j < 4; j++) {
            unsigned h0, h1, h2, h3, l0, l1, l2, l3;
            ldsm4(h0, h1, h2, h3, b2H + j * 2176 + p * 64);
            ldsm4(l0, l1, l2, l3, b2L + j * 2176 + p * 64);
            mma16(c2[j], xh[0], xh[1], xh[2], xh[3], h0, h1);
            mma16(c2[j], xh[0], xh[1], xh[2], xh[3], l0, l1);
            mma16(c2[j], xl[0], xl[1], xl[2], xl[3], h0, h1);
            mma16(c2[j], xh[4], xh[5], xh[6], xh[7], h2, h3);
            mma16(c2[j], xh[4], xh[5], xh[6], xh[7], l2, l3);
            mma16(c2[j], xl[4], xl[5], xl[6], xl[7], h2, h3);
        }
    }

    // ---- epilogue 2: bias (+residual) -> g_h ; keep final h in c2 ----
    int node0 = n0 + r0, node1 = n0 + r1;
    float ps0 = 0.f, pq0 = 0.f, ps1 = 0.f, pq1 = 0.f;
#pragma unroll
    for (int j = 0; j < 4; j++) {
        int cb = 32 * wn + 8 * j + 2 * t4;
        float bx = smf[W_B2 + cb], by = smf[W_B2 + cb + 1];
        float h00 = c2[j][0] + bx, h01 = c2[j][1] + by;
        float h10 = c2[j][2] + bx, h11 = c2[j][3] + by;
        if (node0 < NN) {
            float* dst = g_h + node0 * HH + cb;
            if (addm) { float2 pv = *(const float2*)dst; h00 += pv.x; h01 += pv.y; }
            *(float2*)dst = make_float2(h00, h01);
        }
        if (node1 < NN) {
            float* dst = g_h + node1 * HH + cb;
            if (addm) { float2 pv = *(const float2*)dst; h10 += pv.x; h11 += pv.y; }
            *(float2*)dst = make_float2(h10, h11);
        }
        c2[j][0] = h00; c2[j][1] = h01; c2[j][2] = h10; c2[j][3] = h11;
        ps0 += h00 + h01; pq0 = fmaf(h00, h00, fmaf(h01, h01, pq0));
        ps1 += h10 + h11; pq1 = fmaf(h10, h10, fmaf(h11, h11, pq1));
    }

    // ---- fused z = relu(LN_{next}(h)) (wz layers only) ----
    if (wz) {
        ps0 += __shfl_xor_sync(0xffffffffu, ps0, 1); ps0 += __shfl_xor_sync(0xffffffffu, ps0, 2);
        pq0 += __shfl_xor_sync(0xffffffffu, pq0, 1); pq0 += __shfl_xor_sync(0xffffffffu, pq0, 2);
        ps1 += __shfl_xor_sync(0xffffffffu, ps1, 1); ps1 += __shfl_xor_sync(0xffffffffu, ps1, 2);
        pq1 += __shfl_xor_sync(0xffffffffu, pq1, 1); pq1 += __shfl_xor_sync(0xffffffffu, pq1, 2);
        if (t4 == 0) {
            smf[W_PSUM + wn * 64 + r0] = ps0;  smf[W_PSQ + wn * 64 + r0] = pq0;
            smf[W_PSUM + wn * 64 + r1] = ps1;  smf[W_PSQ + wn * 64 + r1] = pq1;
        }
        __syncthreads();
        float S0 = smf[W_PSUM + r0] + smf[W_PSUM + 64 + r0];
        float Q0 = smf[W_PSQ + r0]  + smf[W_PSQ + 64 + r0];
        float S1 = smf[W_PSUM + r1] + smf[W_PSUM + 64 + r1];
        float Q1 = smf[W_PSQ + r1]  + smf[W_PSQ + 64 + r1];
        float m0 = S0 * (1.f / 64.f), m1 = S1 * (1.f / 64.f);
        float v0 = rsqrtf(Q0 * (1.f / 64.f) - m0 * m0 + 1e-5f);
        float v1 = rsqrtf(Q1 * (1.f / 64.f) - m1 * m1 + 1e-5f);
#pragma unroll
        for (int j = 0; j < 4; j++) {
            int cb = 32 * wn + 8 * j + 2 * t4;
            float gx = __ldg(&lngN[cb]), gy = __ldg(&lngN[cb + 1]);
            float ex = __ldg(&lnbN[cb]), ey = __ldg(&lnbN[cb + 1]);
            if (node0 < NN) {
                float z0 = fmaxf((c2[j][0] - m0) * v0 * gx + ex, 0.f);
                float z1 = fmaxf((c2[j][1] - m0) * v0 * gy + ey, 0.f);
                *(float2*)(g_z + node0 * HH + cb) = make_float2(z0, z1);
            }
            if (node1 < NN) {
                float z0 = fmaxf((c2[j][2] - m1) * v1 * gx + ex, 0.f);
                float z1 = fmaxf((c2[j][3] - m1) * v1 * gy + ey, 0.f);
                *(float2*)(g_z + node1 * HH + cb) = make_float2(z0, z1);
            }
        }
    }
}

// -------- final: relu(LN(h)) @ lin_W + lin_b ; also re-zero scratch --------
__global__ void k_final(const float* __restrict__ g, const float* __restrict__ b,
                        const float* __restrict__ lw, const float* __restrict__ lb,
                        float* __restrict__ out) {
    int gw = (blockIdx.x * blockDim.x + threadIdx.x) >> 5;
    if (gw >= NN) return;
    int lane = threadIdx.x & 31;
    if (lane == 1) g_wp[gw] = 0;
    if (gw < 128 && lane == 2) g_sflag[gw] = 0;

    float2 v = *(const float2*)(g_h + gw * HH + 2 * lane);
    float s = v.x + v.y, sq = v.x * v.x + v.y * v.y;
    for (int o = 16; o; o >>= 1) {
        s  += __shfl_xor_sync(0xffffffffu, s, o);
        sq += __shfl_xor_sync(0xffffffffu, sq, o);
    }
    float mu = s * 0.015625f;
    float var = sq * 0.015625f - mu * mu;
    float rs = rsqrtf(var + 1e-5f);
    float a0 = fmaxf((v.x - mu) * rs * g[2 * lane]     + b[2 * lane],     0.f);
    float a1 = fmaxf((v.y - mu) * rs * g[2 * lane + 1] + b[2 * lane + 1], 0.f);
    float o0 = a0 * lw[(2 * lane) * 3 + 0] + a1 * lw[(2 * lane + 1) * 3 + 0];
    float o1 = a0 * lw[(2 * lane) * 3 + 1] + a1 * lw[(2 * lane + 1) * 3 + 1];
    float o2 = a0 * lw[(2 * lane) * 3 + 2] + a1 * lw[(2 * lane + 1) * 3 + 2];
    for (int ww = 16; ww; ww >>= 1) {
        o0 += __shfl_xor_sync(0xffffffffu, o0, ww);
        o1 += __shfl_xor_sync(0xffffffffu, o1, ww);
        o2 += __shfl_xor_sync(0xffffffffu, o2, ww);
    }
    if (lane == 0) {
        out[gw * 3 + 0] = o0 + lb[0];
        out[gw * 3 + 1] = o1 + lb[1];
        out[gw * 3 + 2] = o2 + lb[2];
    }
}

// ---------------- launch ----------------
extern "C" void kernel_launch(void* const* d_in, const int* in_sizes, int n_in,
                              void* d_out, int out_size) {
    const float* x    = (const float*)d_in[0];
    const int*   ei   = (const int*)  d_in[1];
    const float* encW = (const float*)d_in[2];
    const float* encb = (const float*)d_in[3];
    const float* t    = (const float*)d_in[4];
    const float* W1   = (const float*)d_in[5];
    const float* b1   = (const float*)d_in[6];
    const float* mg   = (const float*)d_in[7];
    const float* mb   = (const float*)d_in[8];
    const float* W2   = (const float*)d_in[9];
    const float* b2   = (const float*)d_in[10];
    const float* lng  = (const float*)d_in[11];
    const float* lnb  = (const float*)d_in[12];
    const float* lw   = (const float*)d_in[13];
    const float* lb   = (const float*)d_in[14];
    float* out = (float*)d_out;

    cudaFuncSetAttribute(k_mlp, cudaFuncAttributeMaxDynamicSharedMemorySize, SMEM_MLP_BYTES);

    const int WARP_BLOCKS = (NN * 32 + 255) / 256;
    const int MLP_BLOCKS  = (NN + 63) / 64;
    const int EH_BLOCKS   = (NN * 16 + 255) / 256;   // covers NE and 3*4096 too

    // CSR build + encoder + weight pre-split (launches 0..2)
    k_enc_hist<<<EH_BLOCKS, 256>>>(x, encW, encb, ei, W1, W2);
    k_scan<<<NB_SCAN, 1024>>>();
    k_scatter<<<(NE + 255) / 256, 256>>>(ei);

    // layer 0 (launch index 3 = k_agg -> profiled slot); mlp fuses z for layer 1
    k_agg<<<WARP_BLOCKS, 256>>>(t + 0);
    k_mlp<<<MLP_BLOCKS, 256, SMEM_MLP_BYTES>>>(b1, mg, mb, b2,
                                               lng + HH, lnb + HH, 0, 0, 1);

    // layer 1 (mlp fuses z for layer 2), layer 2 (no z)
    k_agg<<<WARP_BLOCKS, 256>>>(t + 1);
    k_mlp<<<MLP_BLOCKS, 256, SMEM_MLP_BYTES>>>(b1 + H2, mg + H2, mb + H2, b2 + HH,
                                               lng + 2 * HH, lnb + 2 * HH, 1, 1, 1);
    k_agg<<<WARP_BLOCKS, 256>>>(t + 2);
    k_mlp<<<MLP_BLOCKS, 256, SMEM_MLP_BYTES>>>(b1 + 2 * H2, mg + 2 * H2, mb + 2 * H2,
                                               b2 + 2 * HH, lng, lnb, 2, 1, 0);

    // final projection (+ scratch re-zero for next replay)
    k_final<<<WARP_BLOCKS, 256>>>(lng, lnb, lw, lb, out);
}

// round 13
// speedup vs baseline: 1.1062x; 1.0033x over previous
#include <cuda_runtime.h>
#include <cuda_bf16.h>
#include <cstdint>

#define NN 100000
#define NE 1200000
#define HH 64
#define H2 128
#define NB_SCAN 98
#define LOG2E 1.44269504f

// ---------------- device scratch (no allocations allowed) ----------------
// g_z holds layer input PRE-SCALED by t_layer * log2(e)
__device__ float g_z[NN * HH];
__device__ float g_h[NN * HH];      // residual stream (fp32, unscaled)
__device__ unsigned g_uh[NN * 32];  // MLP input, bf16x2 hi words (k-pairs)
__device__ unsigned g_ul[NN * 32];  // MLP input, bf16x2 lo words
__device__ int   g_rowptr[NN + 1];
__device__ int   g_wp[NN];          // zeroed by previous replay's k_final
__device__ int   g_srcs[NE];        // src ids PRE-SCALED by 64
__device__ int   g_sval[128];
__device__ int   g_sincl[128];
__device__ int   g_sflag[128];      // tail-zeroed by k_final
// pre-split weights, [n][kp] rows (k contiguous as bf16):
__device__ unsigned g_w1h[3 * 4096], g_w1l[3 * 4096];
__device__ unsigned g_w2h[3 * 4096], g_w2l[3 * 4096];

// ---------------- helpers ----------------
__device__ __forceinline__ float ex2(float x) {
    float r; asm("ex2.approx.f32 %0, %1;" : "=f"(r) : "f"(x)); return r;
}
__device__ __forceinline__ unsigned pk_bf2(float xe, float xo) {
    unsigned d;
    asm("cvt.rn.bf16x2.f32 %0, %1, %2;" : "=r"(d) : "f"(xo), "f"(xe));
    return d;
}
__device__ __forceinline__ float lo16f(unsigned w) { return __uint_as_float(w << 16); }
__device__ __forceinline__ float hi16f(unsigned w) { return __uint_as_float(w & 0xffff0000u); }
__device__ __forceinline__ void split_pair(float xe, float xo, unsigned& hw, unsigned& lw) {
    hw = pk_bf2(xe, xo);
    lw = pk_bf2(xe - lo16f(hw), xo - hi16f(hw));
}
__device__ __forceinline__ uint32_t smem_u32(const void* p) {
    uint32_t a;
    asm("{ .reg .u64 t; cvta.to.shared.u64 t, %1; cvt.u32.u64 %0, t; }" : "=r"(a) : "l"(p));
    return a;
}
__device__ __forceinline__ void mma16(float* c, unsigned a0, unsigned a1,
                                      unsigned a2, unsigned a3,
                                      unsigned b0, unsigned b1) {
    asm("mma.sync.aligned.m16n8k16.row.col.f32.bf16.bf16.f32 "
        "{%0,%1,%2,%3}, {%4,%5,%6,%7}, {%8,%9}, {%0,%1,%2,%3};"
        : "+f"(c[0]), "+f"(c[1]), "+f"(c[2]), "+f"(c[3])
        : "r"(a0), "r"(a1), "r"(a2), "r"(a3), "r"(b0), "r"(b1));
}
__device__ __forceinline__ void ldsm4(unsigned& r0, unsigned& r1, unsigned& r2,
                                      unsigned& r3, uint32_t addr) {
    asm volatile("ldmatrix.sync.aligned.m8n8.x4.shared.b16 {%0,%1,%2,%3}, [%4];"
                 : "=r"(r0), "=r"(r1), "=r"(r2), "=r"(r3) : "r"(addr));
}

// ------ launch 0: encoder (scaled by t0*log2e) + histogram + W pre-split ---
__global__ void k_enc_hist(const float* __restrict__ x, const float* __restrict__ W,
                           const float* __restrict__ b, const int* __restrict__ ei,
                           const float* __restrict__ W1g, const float* __restrict__ W2g,
                           const float* __restrict__ t) {
    int idx = blockIdx.x * blockDim.x + threadIdx.x;
    if (idx == 0) g_rowptr[NN] = NE;
    if (idx < NE) atomicAdd(&g_wp[ei[NE + idx]], 1);
    if (idx < NN * 16) {
        float tl0 = __ldg(t) * LOG2E;
        int n = idx >> 4, c = (idx & 15) * 4;
        float x0 = x[n * 3], x1 = x[n * 3 + 1], x2 = x[n * 3 + 2];
        float4 w0 = *(const float4*)&W[c];
        float4 w1 = *(const float4*)&W[HH + c];
        float4 w2 = *(const float4*)&W[2 * HH + c];
        float4 bb = *(const float4*)&b[c];
        float4 o;
        o.x = (x0 * w0.x + x1 * w1.x + x2 * w2.x + bb.x) * tl0;
        o.y = (x0 * w0.y + x1 * w1.y + x2 * w2.y + bb.y) * tl0;
        o.z = (x0 * w0.z + x1 * w1.z + x2 * w2.z + bb.z) * tl0;
        o.w = (x0 * w0.w + x1 * w1.w + x2 * w2.w + bb.w) * tl0;
        *(float4*)&g_z[n * HH + c] = o;
    }
    if (idx < 3 * 4096) {   // W1^T: idx = l*4096 + n*32 + kp
        int l = idx >> 12, r = idx & 4095, n = r >> 5, kp = r & 31;
        const float* Wl = W1g + l * (HH * H2);
        unsigned hw, lw;
        split_pair(Wl[(2 * kp) * H2 + n], Wl[(2 * kp + 1) * H2 + n], hw, lw);
        g_w1h[idx] = hw; g_w1l[idx] = lw;
    }
    if (idx < 3 * 4096) {   // W2^T: idx = l*4096 + n*64 + kp
        int l = idx >> 12, r = idx & 4095, n = r >> 6, kp = r & 63;
        const float* Wl = W2g + l * (H2 * HH);
        unsigned hw, lw;
        split_pair(Wl[(2 * kp) * HH + n], Wl[(2 * kp + 1) * HH + n], hw, lw);
        g_w2h[idx] = hw; g_w2l[idx] = lw;
    }
}

// ------------- launch 1: single-pass scan (decoupled lookback) -------------
__global__ void k_scan() {
    __shared__ int wsum[32];
    __shared__ int s_excl;
    int t = threadIdx.x, b = blockIdx.x;
    int lane = t & 31, wid = t >> 5;
    int i = b * 1024 + t;
    int x = (i < NN) ? g_wp[i] : 0;

    int v = x;
#pragma unroll
    for (int d = 1; d < 32; d <<= 1) {
        int u = __shfl_up_sync(0xffffffffu, v, d);
        if (lane >= d) v += u;
    }
    if (lane == 31) wsum[wid] = v;
    __syncthreads();
    if (wid == 0) {
        int w = wsum[lane];
#pragma unroll
        for (int d = 1; d < 32; d <<= 1) {
            int u = __shfl_up_sync(0xffffffffu, w, d);
            if (lane >= d) w += u;
        }
        wsum[lane] = w;
    }
    __syncthreads();
    int incl = v + (wid ? wsum[wid - 1] : 0);
    int bsum = wsum[31];

    if (t == 0) {
        if (b == 0) {
            g_sincl[0] = bsum; __threadfence(); g_sflag[0] = 2;
            s_excl = 0;
        } else {
            g_sval[b] = bsum; __threadfence(); g_sflag[b] = 1;
            int excl = 0, j = b - 1;
            while (true) {
                int f;
                do { f = ((volatile int*)g_sflag)[j]; } while (f == 0);
                __threadfence();
                if (f == 2) { excl += ((volatile int*)g_sincl)[j]; break; }
                excl += ((volatile int*)g_sval)[j]; j--;
            }
            g_sincl[b] = excl + bsum; __threadfence(); g_sflag[b] = 2;
            s_excl = excl;
        }
    }
    __syncthreads();
    if (i < NN) {
        int e = s_excl + incl - x;
        g_rowptr[i] = e;
        g_wp[i] = e;
    }
}

// ------------- launch 2: scatter src ids (pre-scaled) into CSR -------------
__global__ void k_scatter(const int* __restrict__ ei) {
    int e = blockIdx.x * blockDim.x + threadIdx.x;
    if (e < NE) {
        int d = ei[NE + e];
        int p = atomicAdd(&g_wp[d], 1);
        g_srcs[p] = ei[e] << 6;   // src * HH
    }
}

// ------- single-pass softmax aggregation; g_z pre-scaled by t*log2e -------
// scaled domain: m = r*tl2; w = 2^m; msg = (sum m*w / sum w) / tl2
__global__ __launch_bounds__(256, 8) void k_agg(const float* __restrict__ tptr) {
    int gw = (blockIdx.x * blockDim.x + threadIdx.x) >> 5;
    if (gw >= NN) return;
    int lane = threadIdx.x & 31;
    int beg = g_rowptr[gw], end = g_rowptr[gw + 1];
    float tl2 = __ldg(tptr) * LOG2E;
    float inv_tl2 = __fdividef(1.f, tl2);
    const float* zp = g_z + 2 * lane;

    float z0 = 0.f, z1 = 0.f, s0 = 0.f, s1 = 0.f;
    for (int base = beg; base < end; base += 32) {
        int nn = end - base; if (nn > 32) nn = 32;
        int sid = (base + lane < end) ? __ldg(&g_srcs[base + lane]) : 0;
#pragma unroll 4
        for (int j = 0; j < nn; j++) {
            int s = __shfl_sync(0xffffffffu, sid, j);
            float2 v = *(const float2*)(zp + s);
            float m0 = fmaxf(v.x, 0.f), m1 = fmaxf(v.y, 0.f);
            float w0 = ex2(m0);
            float w1 = ex2(m1);
            z0 += w0; z1 += w1;
            s0 = fmaf(m0, w0, s0);
            s1 = fmaf(m1, w1, s1);
        }
    }
    float2 zz = *(const float2*)(g_z + gw * HH + 2 * lane);   // scaled self
    float ox, oy;
    if (end > beg) {
        ox = (zz.x + __fdividef(s0, z0)) * inv_tl2 + 1e-7f;
        oy = (zz.y + __fdividef(s1, z1)) * inv_tl2 + 1e-7f;
    } else {
        ox = zz.x * inv_tl2;
        oy = zz.y * inv_tl2;
    }
    unsigned hw, lw;
    split_pair(ox, oy, hw, lw);
    g_uh[gw * 32 + lane] = hw;
    g_ul[gw * 32 + lane] = lw;
}

// -------- fused MLP: bf16 mma.sync + ldmatrix, 3-term emulated fp32 -------
// W1/W2 share one smem region; wz=1 writes NEXT layer z PRE-SCALED by tN*log2e
#define W_PSUM 0
#define W_PSQ  128
#define W_B1   256
#define W_GAM  384
#define W_BET  512
#define W_B2   640
#define W_A    704
#define W_UH   (W_A)
#define W_UL   (W_A + 2304)
#define W_HH   (W_A)
#define W_HL   (W_A + 4352)
#define W_W    9408
#define W_W1H  (W_W)
#define W_W1L  (W_W + 4608)
#define W_W2H  (W_W)
#define W_W2L  (W_W + 4352)
#define SMEM_MLP_WORDS 18624
#define SMEM_MLP_BYTES (SMEM_MLP_WORDS * 4)

extern __shared__ unsigned smw[];
__global__ __launch_bounds__(256, 3) void k_mlp(
    const float* __restrict__ b1g, const float* __restrict__ gamg,
    const float* __restrict__ betg, const float* __restrict__ b2g,
    const float* __restrict__ lngN, const float* __restrict__ lnbN,
    const float* __restrict__ tN,
    int layer, int addm, int wz)
{
    float* smf = (float*)smw;
    int tid = threadIdx.x, w = tid >> 5, lane = tid & 31;
    int g = lane >> 2, t4 = lane & 3;
    int wm = w & 3, wn = w >> 2;
    int n0 = blockIdx.x * 64;
    int lofs = layer * 4096;

    if (tid < 128) {
        smf[W_B1 + tid]  = b1g[tid];
        smf[W_GAM + tid] = gamg[tid];
        smf[W_BET + tid] = betg[tid];
        if (tid < 64) smf[W_B2 + tid] = b2g[tid];
    }
    for (int i = tid * 4; i < 2048; i += 1024) {
        int r = i >> 5, c = i & 31;
        int node = n0 + r;
        uint4 hv = make_uint4(0, 0, 0, 0), lv = hv;
        if (node < NN) {
            hv = *(const uint4*)&g_uh[node * 32 + c];
            lv = *(const uint4*)&g_ul[node * 32 + c];
        }
        *(uint4*)&smw[W_UH + r * 36 + c] = hv;
        *(uint4*)&smw[W_UL + r * 36 + c] = lv;
    }
    for (int i = tid * 4; i < 4096; i += 1024) {
        int r = i >> 5, c = i & 31;
        *(uint4*)&smw[W_W1H + r * 36 + c] = *(const uint4*)&g_w1h[lofs + i];
        *(uint4*)&smw[W_W1L + r * 36 + c] = *(const uint4*)&g_w1l[lofs + i];
    }
    __syncthreads();

    uint32_t sb = smem_u32(smw);
    int lr = (lane & 7) + ((lane >> 3) & 1) * 8;
    int lhalf = lane >> 4;
    int l8 = lane & 7, lg = lane >> 3;

    // ---- GEMM1 (k-outer / j-inner) ----
    uint32_t a1H = sb + W_UH * 4 + (16 * wm + lr) * 144 + lhalf * 16;
    uint32_t a1L = a1H + (W_UL - W_UH) * 4;
    uint32_t b1H = sb + W_W1H * 4 + (64 * wn + l8) * 144 + lg * 16;
    uint32_t b1L = b1H + (W_W1L - W_W1H) * 4;

    float c1[8][4];
#pragma unroll
    for (int j = 0; j < 8; j++)
#pragma unroll
        for (int q = 0; q < 4; q++) c1[j][q] = 0.f;

#pragma unroll
    for (int p = 0; p < 2; p++) {
        unsigned aH0[4], aH1[4], aL0[4], aL1[4];
        ldsm4(aH0[0], aH0[1], aH0[2], aH0[3], a1H + p * 64);
        ldsm4(aH1[0], aH1[1], aH1[2], aH1[3], a1H + p * 64 + 32);
        ldsm4(aL0[0], aL0[1], aL0[2], aL0[3], a1L + p * 64);
        ldsm4(aL1[0], aL1[1], aL1[2], aL1[3], a1L + p * 64 + 32);
#pragma unroll
        for (int j = 0; j < 8; j++) {
            unsigned h0, h1, h2, h3, l0, l1, l2, l3;
            ldsm4(h0, h1, h2, h3, b1H + j * 1152 + p * 64);
            ldsm4(l0, l1, l2, l3, b1L + j * 1152 + p * 64);
            mma16(c1[j], aH0[0], aH0[1], aH0[2], aH0[3], h0, h1);
            mma16(c1[j], aH0[0], aH0[1], aH0[2], aH0[3], l0, l1);
            mma16(c1[j], aL0[0], aL0[1], aL0[2], aL0[3], h0, h1);
            mma16(c1[j], aH1[0], aH1[1], aH1[2], aH1[3], h2, h3);
            mma16(c1[j], aH1[0], aH1[1], aH1[2], aH1[3], l2, l3);
            mma16(c1[j], aL1[0], aL1[1], aL1[2], aL1[3], h2, h3);
        }
    }

    // ---- epilogue 1: bias + LN(128) partial sums ----
    int r0 = 16 * wm + g, r1 = r0 + 8;
    float sA = 0.f, sqA = 0.f, sB = 0.f, sqB = 0.f;
#pragma unroll
    for (int j = 0; j < 8; j++) {
        int cb = 64 * wn + 8 * j + 2 * t4;
        float bx = smf[W_B1 + cb], by = smf[W_B1 + cb + 1];
        c1[j][0] += bx; c1[j][1] += by; c1[j][2] += bx; c1[j][3] += by;
        sA += c1[j][0] + c1[j][1];
        sqA = fmaf(c1[j][0], c1[j][0], fmaf(c1[j][1], c1[j][1], sqA));
        sB += c1[j][2] + c1[j][3];
        sqB = fmaf(c1[j][2], c1[j][2], fmaf(c1[j][3], c1[j][3], sqB));
    }
    sA += __shfl_xor_sync(0xffffffffu, sA, 1);  sA += __shfl_xor_sync(0xffffffffu, sA, 2);
    sqA += __shfl_xor_sync(0xffffffffu, sqA, 1); sqA += __shfl_xor_sync(0xffffffffu, sqA, 2);
    sB += __shfl_xor_sync(0xffffffffu, sB, 1);  sB += __shfl_xor_sync(0xffffffffu, sB, 2);
    sqB += __shfl_xor_sync(0xffffffffu, sqB, 1); sqB += __shfl_xor_sync(0xffffffffu, sqB, 2);
    if (t4 == 0) {
        smf[W_PSUM + wn * 64 + r0] = sA;  smf[W_PSQ + wn * 64 + r0] = sqA;
        smf[W_PSUM + wn * 64 + r1] = sB;  smf[W_PSQ + wn * 64 + r1] = sqB;
    }
    __syncthreads();   // all GEMM1 W1-reads done; W-region free for W2

    // ---- load W2 splits into the shared W region (overlaps LN math) ----
    for (int i = tid * 4; i < 4096; i += 1024) {
        int r = i >> 6, c = i & 63;
        *(uint4*)&smw[W_W2H + r * 68 + c] = *(const uint4*)&g_w2h[lofs + i];
        *(uint4*)&smw[W_W2L + r * 68 + c] = *(const uint4*)&g_w2l[lofs + i];
    }

    float s0 = smf[W_PSUM + r0] + smf[W_PSUM + 64 + r0];
    float q0 = smf[W_PSQ + r0]  + smf[W_PSQ + 64 + r0];
    float s1 = smf[W_PSUM + r1] + smf[W_PSUM + 64 + r1];
    float q1 = smf[W_PSQ + r1]  + smf[W_PSQ + 64 + r1];
    float mu0 = s0 * (1.f / 128.f), mu1 = s1 * (1.f / 128.f);
    float rs0 = rsqrtf(q0 * (1.f / 128.f) - mu0 * mu0 + 1e-5f);
    float rs1 = rsqrtf(q1 * (1.f / 128.f) - mu1 * mu1 + 1e-5f);

#pragma unroll
    for (int j = 0; j < 8; j++) {
        int cb = 64 * wn + 8 * j + 2 * t4;
        float gx = smf[W_GAM + cb], gy = smf[W_GAM + cb + 1];
        float ex = smf[W_BET + cb], ey = smf[W_BET + cb + 1];
        float h0 = fmaxf((c1[j][0] - mu0) * rs0 * gx + ex, 0.f);
        float h1 = fmaxf((c1[j][1] - mu0) * rs0 * gy + ey, 0.f);
        float h2 = fmaxf((c1[j][2] - mu1) * rs1 * gx + ex, 0.f);
        float h3 = fmaxf((c1[j][3] - mu1) * rs1 * gy + ey, 0.f);
        int kp = cb >> 1;
        unsigned hw, lw;
        split_pair(h0, h1, hw, lw);
        smw[W_HH + r0 * 68 + kp] = hw; smw[W_HL + r0 * 68 + kp] = lw;
        split_pair(h2, h3, hw, lw);
        smw[W_HH + r1 * 68 + kp] = hw; smw[W_HL + r1 * 68 + kp] = lw;
    }
    __syncthreads();   // act + W2 both visible

    // ---- GEMM2 ----
    uint32_t a2H = sb + W_HH * 4 + (16 * wm + lr) * 272 + lhalf * 16;
    uint32_t a2L = a2H + (W_HL - W_HH) * 4;
    uint32_t b2H = sb + W_W2H * 4 + (32 * wn + l8) * 272 + lg * 16;
    uint32_t b2L = b2H + (W_W2L - W_W2H) * 4;

    float c2[4][4];
#pragma unroll
    for (int j = 0; j < 4; j++)
#pragma unroll
        for (int q = 0; q < 4; q++) c2[j][q] = 0.f;

#pragma unroll
    for (int p = 0; p < 4; p++) {
        unsigned xh[8], xl[8];
        ldsm4(xh[0], xh[1], xh[2], xh[3], a2H + p * 64);
        ldsm4(xh[4], xh[5], xh[6], xh[7], a2H + p * 64 + 32);
        ldsm4(xl[0], xl[1], xl[2], xl[3], a2L + p * 64);
        ldsm4(xl[4], xl[5], xl[6], xl[7], a2L + p * 64 + 32);
#pragma unroll
        for (int j = 0; j < 4; j++) {
            unsigned h0, h1, h2, h3, l0, l1, l2, l3;
            ldsm4(h0, h1, h2, h3, b2H + j * 2176 + p * 64);
            ldsm4(l0, l1, l2, l3, b2L + j * 2176 + p * 64);
            mma16(c2[j], xh[0], xh[1], xh[2], xh[3], h0, h1);
            mma16(c2[j], xh[0], xh[1], xh[2], xh[3], l0, l1);
            mma16(c2[j], xl[0], xl[1], xl[2], xl[3], h0, h1);
            mma16(c2[j], xh[4], xh[5], xh[6], xh[7], h2, h3);
            mma16(c2[j], xh[4], xh[5], xh[6], xh[7], l2, l3);
            mma16(c2[j], xl[4], xl[5], xl[6], xl[7], h2, h3);
        }
    }

    // ---- epilogue 2: bias (+residual) -> g_h ; keep final h in c2 ----
    int node0 = n0 + r0, node1 = n0 + r1;
    float ps0 = 0.f, pq0 = 0.f, ps1 = 0.f, pq1 = 0.f;
#pragma unroll
    for (int j = 0; j < 4; j++) {
        int cb = 32 * wn + 8 * j + 2 * t4;
        float bx = smf[W_B2 + cb], by = smf[W_B2 + cb + 1];
        float h00 = c2[j][0] + bx, h01 = c2[j][1] + by;
        float h10 = c2[j][2] + bx, h11 = c2[j][3] + by;
        if (node0 < NN) {
            float* dst = g_h + node0 * HH + cb;
            if (addm) { float2 pv = *(const float2*)dst; h00 += pv.x; h01 += pv.y; }
            *(float2*)dst = make_float2(h00, h01);
        }
        if (node1 < NN) {
            float* dst = g_h + node1 * HH + cb;
            if (addm) { float2 pv = *(const float2*)dst; h10 += pv.x; h11 += pv.y; }
            *(float2*)dst = make_float2(h10, h11);
        }
        c2[j][0] = h00; c2[j][1] = h01; c2[j][2] = h10; c2[j][3] = h11;
        ps0 += h00 + h01; pq0 = fmaf(h00, h00, fmaf(h01, h01, pq0));
        ps1 += h10 + h11; pq1 = fmaf(h10, h10, fmaf(h11, h11, pq1));
    }

    // ---- fused z = relu(LN_{next}(h)) * tN*log2e (wz layers only) ----
    if (wz) {
        float tlN = __ldg(tN) * LOG2E;
        ps0 += __shfl_xor_sync(0xffffffffu, ps0, 1); ps0 += __shfl_xor_sync(0xffffffffu, ps0, 2);
        pq0 += __shfl_xor_sync(0xffffffffu, pq0, 1); pq0 += __shfl_xor_sync(0xffffffffu, pq0, 2);
        ps1 += __shfl_xor_sync(0xffffffffu, ps1, 1); ps1 += __shfl_xor_sync(0xffffffffu, ps1, 2);
        pq1 += __shfl_xor_sync(0xffffffffu, pq1, 1); pq1 += __shfl_xor_sync(0xffffffffu, pq1, 2);
        if (t4 == 0) {
            smf[W_PSUM + wn * 64 + r0] = ps0;  smf[W_PSQ + wn * 64 + r0] = pq0;
            smf[W_PSUM + wn * 64 + r1] = ps1;  smf[W_PSQ + wn * 64 + r1] = pq1;
        }
        __syncthreads();
        float S0 = smf[W_PSUM + r0] + smf[W_PSUM + 64 + r0];
        float Q0 = smf[W_PSQ + r0]  + smf[W_PSQ + 64 + r0];
        float S1 = smf[W_PSUM + r1] + smf[W_PSUM + 64 + r1];
        float Q1 = smf[W_PSQ + r1]  + smf[W_PSQ + 64 + r1];
        float m0 = S0 * (1.f / 64.f), m1 = S1 * (1.f / 64.f);
        float v0 = rsqrtf(Q0 * (1.f / 64.f) - m0 * m0 + 1e-5f);
        float v1 = rsqrtf(Q1 * (1.f / 64.f) - m1 * m1 + 1e-5f);
#pragma unroll
        for (int j = 0; j < 4; j++) {
            int cb = 32 * wn + 8 * j + 2 * t4;
            // fold the tN*log2e pre-scale into gamma/beta (tlN > 0, relu-safe)
            float gx = __ldg(&lngN[cb]) * tlN,     gy = __ldg(&lngN[cb + 1]) * tlN;
            float ex = __ldg(&lnbN[cb]) * tlN,     ey = __ldg(&lnbN[cb + 1]) * tlN;
            if (node0 < NN) {
                float z0 = fmaxf((c2[j][0] - m0) * v0 * gx + ex, 0.f);
                float z1 = fmaxf((c2[j][1] - m0) * v0 * gy + ey, 0.f);
                *(float2*)(g_z + node0 * HH + cb) = make_float2(z0, z1);
            }
            if (node1 < NN) {
                float z0 = fmaxf((c2[j][2] - m1) * v1 * gx + ex, 0.f);
                float z1 = fmaxf((c2[j][3] - m1) * v1 * gy + ey, 0.f);
                *(float2*)(g_z + node1 * HH + cb) = make_float2(z0, z1);
            }
        }
    }
}

// -------- final: relu(LN(h)) @ lin_W + lin_b ; also re-zero scratch --------
__global__ void k_final(const float* __restrict__ g, const float* __restrict__ b,
                        const float* __restrict__ lw, const float* __restrict__ lb,
                        float* __restrict__ out) {
    int gw = (blockIdx.x * blockDim.x + threadIdx.x) >> 5;
    if (gw >= NN) return;
    int lane = threadIdx.x & 31;
    if (lane == 1) g_wp[gw] = 0;
    if (gw < 128 && lane == 2) g_sflag[gw] = 0;

    float2 v = *(const float2*)(g_h + gw * HH + 2 * lane);
    float s = v.x + v.y, sq = v.x * v.x + v.y * v.y;
    for (int o = 16; o; o >>= 1) {
        s  += __shfl_xor_sync(0xffffffffu, s, o);
        sq += __shfl_xor_sync(0xffffffffu, sq, o);
    }
    float mu = s * 0.015625f;
    float var = sq * 0.015625f - mu * mu;
    float rs = rsqrtf(var + 1e-5f);
    float a0 = fmaxf((v.x - mu) * rs * g[2 * lane]     + b[2 * lane],     0.f);
    float a1 = fmaxf((v.y - mu) * rs * g[2 * lane + 1] + b[2 * lane + 1], 0.f);
    float o0 = a0 * lw[(2 * lane) * 3 + 0] + a1 * lw[(2 * lane + 1) * 3 + 0];
    float o1 = a0 * lw[(2 * lane) * 3 + 1] + a1 * lw[(2 * lane + 1) * 3 + 1];
    float o2 = a0 * lw[(2 * lane) * 3 + 2] + a1 * lw[(2 * lane + 1) * 3 + 2];
    for (int ww = 16; ww; ww >>= 1) {
        o0 += __shfl_xor_sync(0xffffffffu, o0, ww);
        o1 += __shfl_xor_sync(0xffffffffu, o1, ww);
        o2 += __shfl_xor_sync(0xffffffffu, o2, ww);
    }
    if (lane == 0) {
        out[gw * 3 + 0] = o0 + lb[0];
        out[gw * 3 + 1] = o1 + lb[1];
        out[gw * 3 + 2] = o2 + lb[2];
    }
}

// ---------------- launch ----------------
extern "C" void kernel_launch(void* const* d_in, const int* in_sizes, int n_in,
                              void* d_out, int out_size) {
    const float* x    = (const float*)d_in[0];
    const int*   ei   = (const int*)  d_in[1];
    const float* encW = (const float*)d_in[2];
    const float* encb = (const float*)d_in[3];
    const float* t    = (const float*)d_in[4];
    const float* W1   = (const float*)d_in[5];
    const float* b1   = (const float*)d_in[6];
    const float* mg   = (const float*)d_in[7];
    const float* mb   = (const float*)d_in[8];
    const float* W2   = (const float*)d_in[9];
    const float* b2   = (const float*)d_in[10];
    const float* lng  = (const float*)d_in[11];
    const float* lnb  = (const float*)d_in[12];
    const float* lw   = (const float*)d_in[13];
    const float* lb   = (const float*)d_in[14];
    float* out = (float*)d_out;

    cudaFuncSetAttribute(k_mlp, cudaFuncAttributeMaxDynamicSharedMemorySize, SMEM_MLP_BYTES);

    const int WARP_BLOCKS = (NN * 32 + 255) / 256;
    const int MLP_BLOCKS  = (NN + 63) / 64;
    const int EH_BLOCKS   = (NN * 16 + 255) / 256;   // covers NE and 3*4096 too

    // CSR build + encoder + weight pre-split (launches 0..2)
    k_enc_hist<<<EH_BLOCKS, 256>>>(x, encW, encb, ei, W1, W2, t);
    k_scan<<<NB_SCAN, 1024>>>();
    k_scatter<<<(NE + 255) / 256, 256>>>(ei);

    // layer 0 (launch index 3 = k_agg -> profiled slot); mlp fuses z for layer 1
    k_agg<<<WARP_BLOCKS, 256>>>(t + 0);
    k_mlp<<<MLP_BLOCKS, 256, SMEM_MLP_BYTES>>>(b1, mg, mb, b2,
                                               lng + HH, lnb + HH, t + 1, 0, 0, 1);

    // layer 1 (mlp fuses z for layer 2), layer 2 (no z)
    k_agg<<<WARP_BLOCKS, 256>>>(t + 1);
    k_mlp<<<MLP_BLOCKS, 256, SMEM_MLP_BYTES>>>(b1 + H2, mg + H2, mb + H2, b2 + HH,
                                               lng + 2 * HH, lnb + 2 * HH, t + 2, 1, 1, 1);
    k_agg<<<WARP_BLOCKS, 256>>>(t + 2);
    k_mlp<<<MLP_BLOCKS, 256, SMEM_MLP_BYTES>>>(b1 + 2 * H2, mg + 2 * H2, mb + 2 * H2,
                                               b2 + 2 * HH, lng, lnb, t, 2, 1, 0);

    // final projection (+ scratch re-zero for next replay)
    k_final<<<WARP_BLOCKS, 256>>>(lng, lnb, lw, lb, out);
}

// round 14
// speedup vs baseline: 1.1587x; 1.0474x over previous
#include <cuda_runtime.h>
#include <cuda_bf16.h>
#include <cstdint>

#define NN 100000
#define NE 1200000
#define HH 64
#define H2 128
#define NB_SCAN 98
#define LOG2E 1.44269504f

// ---------------- device scratch (no allocations allowed) ----------------
// g_z holds layer input PRE-SCALED by t_layer * log2(e)
__device__ float g_z[NN * HH];
__device__ float g_h[NN * HH];      // residual stream (fp32, unscaled)
__device__ unsigned g_uh[NN * 32];  // MLP input, bf16x2 hi words (k-pairs)
__device__ unsigned g_ul[NN * 32];  // MLP input, bf16x2 lo words
__device__ int   g_rowptr[NN + 1];
__device__ int   g_wp[NN];          // zeroed by previous replay's last k_mlp
__device__ int   g_srcs[NE];        // src ids PRE-SCALED by 64
__device__ int   g_sval[128];
__device__ int   g_sincl[128];
__device__ int   g_sflag[128];      // tail-zeroed by last k_mlp
// pre-split weights, [n][kp] rows (k contiguous as bf16):
__device__ unsigned g_w1h[3 * 4096], g_w1l[3 * 4096];
__device__ unsigned g_w2h[3 * 4096], g_w2l[3 * 4096];

// ---------------- helpers ----------------
__device__ __forceinline__ float ex2(float x) {
    float r; asm("ex2.approx.f32 %0, %1;" : "=f"(r) : "f"(x)); return r;
}
__device__ __forceinline__ unsigned pk_bf2(float xe, float xo) {
    unsigned d;
    asm("cvt.rn.bf16x2.f32 %0, %1, %2;" : "=r"(d) : "f"(xo), "f"(xe));
    return d;
}
__device__ __forceinline__ float lo16f(unsigned w) { return __uint_as_float(w << 16); }
__device__ __forceinline__ float hi16f(unsigned w) { return __uint_as_float(w & 0xffff0000u); }
__device__ __forceinline__ void split_pair(float xe, float xo, unsigned& hw, unsigned& lw) {
    hw = pk_bf2(xe, xo);
    lw = pk_bf2(xe - lo16f(hw), xo - hi16f(hw));
}
__device__ __forceinline__ uint32_t smem_u32(const void* p) {
    uint32_t a;
    asm("{ .reg .u64 t; cvta.to.shared.u64 t, %1; cvt.u32.u64 %0, t; }" : "=r"(a) : "l"(p));
    return a;
}
__device__ __forceinline__ void mma16(float* c, unsigned a0, unsigned a1,
                                      unsigned a2, unsigned a3,
                                      unsigned b0, unsigned b1) {
    asm("mma.sync.aligned.m16n8k16.row.col.f32.bf16.bf16.f32 "
        "{%0,%1,%2,%3}, {%4,%5,%6,%7}, {%8,%9}, {%0,%1,%2,%3};"
        : "+f"(c[0]), "+f"(c[1]), "+f"(c[2]), "+f"(c[3])
        : "r"(a0), "r"(a1), "r"(a2), "r"(a3), "r"(b0), "r"(b1));
}
__device__ __forceinline__ void ldsm4(unsigned& r0, unsigned& r1, unsigned& r2,
                                      unsigned& r3, uint32_t addr) {
    asm volatile("ldmatrix.sync.aligned.m8n8.x4.shared.b16 {%0,%1,%2,%3}, [%4];"
                 : "=r"(r0), "=r"(r1), "=r"(r2), "=r"(r3) : "r"(addr));
}

// ------ launch 0: encoder (scaled by t0*log2e) + histogram + W pre-split ---
__global__ void k_enc_hist(const float* __restrict__ x, const float* __restrict__ W,
                           const float* __restrict__ b, const int* __restrict__ ei,
                           const float* __restrict__ W1g, const float* __restrict__ W2g,
                           const float* __restrict__ t) {
    int idx = blockIdx.x * blockDim.x + threadIdx.x;
    if (idx == 0) g_rowptr[NN] = NE;
    if (idx < NE) atomicAdd(&g_wp[ei[NE + idx]], 1);
    if (idx < NN * 16) {
        float tl0 = __ldg(t) * LOG2E;
        int n = idx >> 4, c = (idx & 15) * 4;
        float x0 = x[n * 3], x1 = x[n * 3 + 1], x2 = x[n * 3 + 2];
        float4 w0 = *(const float4*)&W[c];
        float4 w1 = *(const float4*)&W[HH + c];
        float4 w2 = *(const float4*)&W[2 * HH + c];
        float4 bb = *(const float4*)&b[c];
        float4 o;
        o.x = (x0 * w0.x + x1 * w1.x + x2 * w2.x + bb.x) * tl0;
        o.y = (x0 * w0.y + x1 * w1.y + x2 * w2.y + bb.y) * tl0;
        o.z = (x0 * w0.z + x1 * w1.z + x2 * w2.z + bb.z) * tl0;
        o.w = (x0 * w0.w + x1 * w1.w + x2 * w2.w + bb.w) * tl0;
        *(float4*)&g_z[n * HH + c] = o;
    }
    if (idx < 3 * 4096) {   // W1^T: idx = l*4096 + n*32 + kp
        int l = idx >> 12, r = idx & 4095, n = r >> 5, kp = r & 31;
        const float* Wl = W1g + l * (HH * H2);
        unsigned hw, lw;
        split_pair(Wl[(2 * kp) * H2 + n], Wl[(2 * kp + 1) * H2 + n], hw, lw);
        g_w1h[idx] = hw; g_w1l[idx] = lw;
    }
    if (idx < 3 * 4096) {   // W2^T: idx = l*4096 + n*64 + kp
        int l = idx >> 12, r = idx & 4095, n = r >> 6, kp = r & 63;
        const float* Wl = W2g + l * (H2 * HH);
        unsigned hw, lw;
        split_pair(Wl[(2 * kp) * HH + n], Wl[(2 * kp + 1) * HH + n], hw, lw);
        g_w2h[idx] = hw; g_w2l[idx] = lw;
    }
}

// ------------- launch 1: single-pass scan (decoupled lookback) -------------
__global__ void k_scan() {
    __shared__ int wsum[32];
    __shared__ int s_excl;
    int t = threadIdx.x, b = blockIdx.x;
    int lane = t & 31, wid = t >> 5;
    int i = b * 1024 + t;
    int x = (i < NN) ? g_wp[i] : 0;

    int v = x;
#pragma unroll
    for (int d = 1; d < 32; d <<= 1) {
        int u = __shfl_up_sync(0xffffffffu, v, d);
        if (lane >= d) v += u;
    }
    if (lane == 31) wsum[wid] = v;
    __syncthreads();
    if (wid == 0) {
        int w = wsum[lane];
#pragma unroll
        for (int d = 1; d < 32; d <<= 1) {
            int u = __shfl_up_sync(0xffffffffu, w, d);
            if (lane >= d) w += u;
        }
        wsum[lane] = w;
    }
    __syncthreads();
    int incl = v + (wid ? wsum[wid - 1] : 0);
    int bsum = wsum[31];

    if (t == 0) {
        if (b == 0) {
            g_sincl[0] = bsum; __threadfence(); g_sflag[0] = 2;
            s_excl = 0;
        } else {
            g_sval[b] = bsum; __threadfence(); g_sflag[b] = 1;
            int excl = 0, j = b - 1;
            while (true) {
                int f;
                do { f = ((volatile int*)g_sflag)[j]; } while (f == 0);
                __threadfence();
                if (f == 2) { excl += ((volatile int*)g_sincl)[j]; break; }
                excl += ((volatile int*)g_sval)[j]; j--;
            }
            g_sincl[b] = excl + bsum; __threadfence(); g_sflag[b] = 2;
            s_excl = excl;
        }
    }
    __syncthreads();
    if (i < NN) {
        int e = s_excl + incl - x;
        g_rowptr[i] = e;
        g_wp[i] = e;
    }
}

// ------------- launch 2: scatter src ids (pre-scaled) into CSR -------------
__global__ void k_scatter(const int* __restrict__ ei) {
    int e = blockIdx.x * blockDim.x + threadIdx.x;
    if (e < NE) {
        int d = ei[NE + e];
        int p = atomicAdd(&g_wp[d], 1);
        g_srcs[p] = ei[e] << 6;   // src * HH
    }
}

// ------- single-pass softmax aggregation; g_z pre-scaled by t*log2e -------
__global__ __launch_bounds__(256, 8) void k_agg(const float* __restrict__ tptr) {
    int gw = (blockIdx.x * blockDim.x + threadIdx.x) >> 5;
    if (gw >= NN) return;
    int lane = threadIdx.x & 31;
    int beg = g_rowptr[gw], end = g_rowptr[gw + 1];
    float tl2 = __ldg(tptr) * LOG2E;
    float inv_tl2 = __fdividef(1.f, tl2);
    const float* zp = g_z + 2 * lane;

    float z0 = 0.f, z1 = 0.f, s0 = 0.f, s1 = 0.f;
    for (int base = beg; base < end; base += 32) {
        int nn = end - base; if (nn > 32) nn = 32;
        int sid = (base + lane < end) ? __ldg(&g_srcs[base + lane]) : 0;
#pragma unroll 4
        for (int j = 0; j < nn; j++) {
            int s = __shfl_sync(0xffffffffu, sid, j);
            float2 v = *(const float2*)(zp + s);
            float m0 = fmaxf(v.x, 0.f), m1 = fmaxf(v.y, 0.f);
            float w0 = ex2(m0);
            float w1 = ex2(m1);
            z0 += w0; z1 += w1;
            s0 = fmaf(m0, w0, s0);
            s1 = fmaf(m1, w1, s1);
        }
    }
    float2 zz = *(const float2*)(g_z + gw * HH + 2 * lane);   // scaled self
    float ox, oy;
    if (end > beg) {
        ox = (zz.x + __fdividef(s0, z0)) * inv_tl2 + 1e-7f;
        oy = (zz.y + __fdividef(s1, z1)) * inv_tl2 + 1e-7f;
    } else {
        ox = zz.x * inv_tl2;
        oy = zz.y * inv_tl2;
    }
    unsigned hw, lw;
    split_pair(ox, oy, hw, lw);
    g_uh[gw * 32 + lane] = hw;
    g_ul[gw * 32 + lane] = lw;
}

// -------- fused MLP: bf16 mma.sync + ldmatrix, 3-term emulated fp32 -------
// wz=0: plain; wz=1: write NEXT-layer z pre-scaled; wz=2: FINAL (LN0+proj->out)
#define W_PSUM 0
#define W_PSQ  128
#define W_B1   256
#define W_GAM  384
#define W_BET  512
#define W_B2   640
#define W_A    704
#define W_UH   (W_A)
#define W_UL   (W_A + 2304)
#define W_HH   (W_A)
#define W_HL   (W_A + 4352)
#define W_W    9408
#define W_W1H  (W_W)
#define W_W1L  (W_W + 4608)
#define W_W2H  (W_W)
#define W_W2L  (W_W + 4352)
#define W_SCR  (W_W)          /* final-projection scratch: [2][64][3] floats */
#define SMEM_MLP_WORDS 18624
#define SMEM_MLP_BYTES (SMEM_MLP_WORDS * 4)

extern __shared__ unsigned smw[];
__global__ __launch_bounds__(256, 3) void k_mlp(
    const float* __restrict__ b1g, const float* __restrict__ gamg,
    const float* __restrict__ betg, const float* __restrict__ b2g,
    const float* __restrict__ lngN, const float* __restrict__ lnbN,
    const float* __restrict__ tN,
    const float* __restrict__ lwg, const float* __restrict__ lbg,
    float* __restrict__ outp,
    int layer, int addm, int wz)
{
    float* smf = (float*)smw;
    int tid = threadIdx.x, w = tid >> 5, lane = tid & 31;
    int g = lane >> 2, t4 = lane & 3;
    int wm = w & 3, wn = w >> 2;
    int n0 = blockIdx.x * 64;
    int lofs = layer * 4096;

    if (wz == 2) {   // scratch re-zero for next replay (CSR phase long done)
        int n = n0 + tid;
        if (tid < 64 && n < NN) g_wp[n] = 0;
        if (blockIdx.x == 0 && tid >= 64 && tid < 192) g_sflag[tid - 64] = 0;
    }
    if (tid < 128) {
        smf[W_B1 + tid]  = b1g[tid];
        smf[W_GAM + tid] = gamg[tid];
        smf[W_BET + tid] = betg[tid];
        if (tid < 64) smf[W_B2 + tid] = b2g[tid];
    }
    for (int i = tid * 4; i < 2048; i += 1024) {
        int r = i >> 5, c = i & 31;
        int node = n0 + r;
        uint4 hv = make_uint4(0, 0, 0, 0), lv = hv;
        if (node < NN) {
            hv = *(const uint4*)&g_uh[node * 32 + c];
            lv = *(const uint4*)&g_ul[node * 32 + c];
        }
        *(uint4*)&smw[W_UH + r * 36 + c] = hv;
        *(uint4*)&smw[W_UL + r * 36 + c] = lv;
    }
    for (int i = tid * 4; i < 4096; i += 1024) {
        int r = i >> 5, c = i & 31;
        *(uint4*)&smw[W_W1H + r * 36 + c] = *(const uint4*)&g_w1h[lofs + i];
        *(uint4*)&smw[W_W1L + r * 36 + c] = *(const uint4*)&g_w1l[lofs + i];
    }
    __syncthreads();

    uint32_t sb = smem_u32(smw);
    int lr = (lane & 7) + ((lane >> 3) & 1) * 8;
    int lhalf = lane >> 4;
    int l8 = lane & 7, lg = lane >> 3;

    // ---- GEMM1 (k-outer / j-inner) ----
    uint32_t a1H = sb + W_UH * 4 + (16 * wm + lr) * 144 + lhalf * 16;
    uint32_t a1L = a1H + (W_UL - W_UH) * 4;
    uint32_t b1H = sb + W_W1H * 4 + (64 * wn + l8) * 144 + lg * 16;
    uint32_t b1L = b1H + (W_W1L - W_W1H) * 4;

    float c1[8][4];
#pragma unroll
    for (int j = 0; j < 8; j++)
#pragma unroll
        for (int q = 0; q < 4; q++) c1[j][q] = 0.f;

#pragma unroll
    for (int p = 0; p < 2; p++) {
        unsigned aH0[4], aH1[4], aL0[4], aL1[4];
        ldsm4(aH0[0], aH0[1], aH0[2], aH0[3], a1H + p * 64);
        ldsm4(aH1[0], aH1[1], aH1[2], aH1[3], a1H + p * 64 + 32);
        ldsm4(aL0[0], aL0[1], aL0[2], aL0[3], a1L + p * 64);
        ldsm4(aL1[0], aL1[1], aL1[2], aL1[3], a1L + p * 64 + 32);
#pragma unroll
        for (int j = 0; j < 8; j++) {
            unsigned h0, h1, h2, h3, l0, l1, l2, l3;
            ldsm4(h0, h1, h2, h3, b1H + j * 1152 + p * 64);
            ldsm4(l0, l1, l2, l3, b1L + j * 1152 + p * 64);
            mma16(c1[j], aH0[0], aH0[1], aH0[2], aH0[3], h0, h1);
            mma16(c1[j], aH0[0], aH0[1], aH0[2], aH0[3], l0, l1);
            mma16(c1[j], aL0[0], aL0[1], aL0[2], aL0[3], h0, h1);
            mma16(c1[j], aH1[0], aH1[1], aH1[2], aH1[3], h2, h3);
            mma16(c1[j], aH1[0], aH1[1], aH1[2], aH1[3], l2, l3);
            mma16(c1[j], aL1[0], aL1[1], aL1[2], aL1[3], h2, h3);
        }
    }

    // ---- epilogue 1: bias + LN(128) partial sums ----
    int r0 = 16 * wm + g, r1 = r0 + 8;
    float sA = 0.f, sqA = 0.f, sB = 0.f, sqB = 0.f;
#pragma unroll
    for (int j = 0; j < 8; j++) {
        int cb = 64 * wn + 8 * j + 2 * t4;
        float bx = smf[W_B1 + cb], by = smf[W_B1 + cb + 1];
        c1[j][0] += bx; c1[j][1] += by; c1[j][2] += bx; c1[j][3] += by;
        sA += c1[j][0] + c1[j][1];
        sqA = fmaf(c1[j][0], c1[j][0], fmaf(c1[j][1], c1[j][1], sqA));
        sB += c1[j][2] + c1[j][3];
        sqB = fmaf(c1[j][2], c1[j][2], fmaf(c1[j][3], c1[j][3], sqB));
    }
    sA += __shfl_xor_sync(0xffffffffu, sA, 1);  sA += __shfl_xor_sync(0xffffffffu, sA, 2);
    sqA += __shfl_xor_sync(0xffffffffu, sqA, 1); sqA += __shfl_xor_sync(0xffffffffu, sqA, 2);
    sB += __shfl_xor_sync(0xffffffffu, sB, 1);  sB += __shfl_xor_sync(0xffffffffu, sB, 2);
    sqB += __shfl_xor_sync(0xffffffffu, sqB, 1); sqB += __shfl_xor_sync(0xffffffffu, sqB, 2);
    if (t4 == 0) {
        smf[W_PSUM + wn * 64 + r0] = sA;  smf[W_PSQ + wn * 64 + r0] = sqA;
        smf[W_PSUM + wn * 64 + r1] = sB;  smf[W_PSQ + wn * 64 + r1] = sqB;
    }
    __syncthreads();   // all GEMM1 W1-reads done; W-region free for W2

    // ---- load W2 splits into the shared W region (overlaps LN math) ----
    for (int i = tid * 4; i < 4096; i += 1024) {
        int r = i >> 6, c = i & 63;
        *(uint4*)&smw[W_W2H + r * 68 + c] = *(const uint4*)&g_w2h[lofs + i];
        *(uint4*)&smw[W_W2L + r * 68 + c] = *(const uint4*)&g_w2l[lofs + i];
    }

    float s0 = smf[W_PSUM + r0] + smf[W_PSUM + 64 + r0];
    float q0 = smf[W_PSQ + r0]  + smf[W_PSQ + 64 + r0];
    float s1 = smf[W_PSUM + r1] + smf[W_PSUM + 64 + r1];
    float q1 = smf[W_PSQ + r1]  + smf[W_PSQ + 64 + r1];
    float mu0 = s0 * (1.f / 128.f), mu1 = s1 * (1.f / 128.f);
    float rs0 = rsqrtf(q0 * (1.f / 128.f) - mu0 * mu0 + 1e-5f);
    float rs1 = rsqrtf(q1 * (1.f / 128.f) - mu1 * mu1 + 1e-5f);

#pragma unroll
    for (int j = 0; j < 8; j++) {
        int cb = 64 * wn + 8 * j + 2 * t4;
        float gx = smf[W_GAM + cb], gy = smf[W_GAM + cb + 1];
        float ex = smf[W_BET + cb], ey = smf[W_BET + cb + 1];
        float h0 = fmaxf((c1[j][0] - mu0) * rs0 * gx + ex, 0.f);
        float h1 = fmaxf((c1[j][1] - mu0) * rs0 * gy + ey, 0.f);
        float h2 = fmaxf((c1[j][2] - mu1) * rs1 * gx + ex, 0.f);
        float h3 = fmaxf((c1[j][3] - mu1) * rs1 * gy + ey, 0.f);
        int kp = cb >> 1;
        unsigned hw, lw;
        split_pair(h0, h1, hw, lw);
        smw[W_HH + r0 * 68 + kp] = hw; smw[W_HL + r0 * 68 + kp] = lw;
        split_pair(h2, h3, hw, lw);
        smw[W_HH + r1 * 68 + kp] = hw; smw[W_HL + r1 * 68 + kp] = lw;
    }
    __syncthreads();   // act + W2 both visible

    // ---- GEMM2 ----
    uint32_t a2H = sb + W_HH * 4 + (16 * wm + lr) * 272 + lhalf * 16;
    uint32_t a2L = a2H + (W_HL - W_HH) * 4;
    uint32_t b2H = sb + W_W2H * 4 + (32 * wn + l8) * 272 + lg * 16;
    uint32_t b2L = b2H + (W_W2L - W_W2H) * 4;

    float c2[4][4];
#pragma unroll
    for (int j = 0; j < 4; j++)
#pragma unroll
        for (int q = 0; q < 4; q++) c2[j][q] = 0.f;

#pragma unroll
    for (int p = 0; p < 4; p++) {
        unsigned xh[8], xl[8];
        ldsm4(xh[0], xh[1], xh[2], xh[3], a2H + p * 64);
        ldsm4(xh[4], xh[5], xh[6], xh[7], a2H + p * 64 + 32);
        ldsm4(xl[0], xl[1], xl[2], xl[3], a2L + p * 64);
        ldsm4(xl[4], xl[5], xl[6], xl[7], a2L + p * 64 + 32);
#pragma unroll
        for (int j = 0; j < 4; j++) {
            unsigned h0, h1, h2, h3, l0, l1, l2, l3;
            ldsm4(h0, h1, h2, h3, b2H + j * 2176 + p * 64);
            ldsm4(l0, l1, l2, l3, b2L + j * 2176 + p * 64);
            mma16(c2[j], xh[0], xh[1], xh[2], xh[3], h0, h1);
            mma16(c2[j], xh[0], xh[1], xh[2], xh[3], l0, l1);
            mma16(c2[j], xl[0], xl[1], xl[2], xl[3], h0, h1);
            mma16(c2[j], xh[4], xh[5], xh[6], xh[7], h2, h3);
            mma16(c2[j], xh[4], xh[5], xh[6], xh[7], l2, l3);
            mma16(c2[j], xl[4], xl[5], xl[6], xl[7], h2, h3);
        }
    }

    // ---- epilogue 2: bias (+residual); store g_h unless FINAL ----
    int node0 = n0 + r0, node1 = n0 + r1;
    float ps0 = 0.f, pq0 = 0.f, ps1 = 0.f, pq1 = 0.f;
#pragma unroll
    for (int j = 0; j < 4; j++) {
        int cb = 32 * wn + 8 * j + 2 * t4;
        float bx = smf[W_B2 + cb], by = smf[W_B2 + cb + 1];
        float h00 = c2[j][0] + bx, h01 = c2[j][1] + by;
        float h10 = c2[j][2] + bx, h11 = c2[j][3] + by;
        if (node0 < NN) {
            float* dst = g_h + node0 * HH + cb;
            if (addm) { float2 pv = *(const float2*)dst; h00 += pv.x; h01 += pv.y; }
            if (wz != 2) *(float2*)dst = make_float2(h00, h01);
        }
        if (node1 < NN) {
            float* dst = g_h + node1 * HH + cb;
            if (addm) { float2 pv = *(const float2*)dst; h10 += pv.x; h11 += pv.y; }
            if (wz != 2) *(float2*)dst = make_float2(h10, h11);
        }
        c2[j][0] = h00; c2[j][1] = h01; c2[j][2] = h10; c2[j][3] = h11;
        ps0 += h00 + h01; pq0 = fmaf(h00, h00, fmaf(h01, h01, pq0));
        ps1 += h10 + h11; pq1 = fmaf(h10, h10, fmaf(h11, h11, pq1));
    }

    // ---- LN over 64 ch of final h (wz=1: z-write; wz=2: projection) ----
    if (wz) {
        float tlN = (wz == 1) ? __ldg(tN) * LOG2E : 1.f;
        ps0 += __shfl_xor_sync(0xffffffffu, ps0, 1); ps0 += __shfl_xor_sync(0xffffffffu, ps0, 2);
        pq0 += __shfl_xor_sync(0xffffffffu, pq0, 1); pq0 += __shfl_xor_sync(0xffffffffu, pq0, 2);
        ps1 += __shfl_xor_sync(0xffffffffu, ps1, 1); ps1 += __shfl_xor_sync(0xffffffffu, ps1, 2);
        pq1 += __shfl_xor_sync(0xffffffffu, pq1, 1); pq1 += __shfl_xor_sync(0xffffffffu, pq1, 2);
        if (t4 == 0) {
            smf[W_PSUM + wn * 64 + r0] = ps0;  smf[W_PSQ + wn * 64 + r0] = pq0;
            smf[W_PSUM + wn * 64 + r1] = ps1;  smf[W_PSQ + wn * 64 + r1] = pq1;
        }
        __syncthreads();   // also: all warps done with GEMM2 (W region reusable)
        float S0 = smf[W_PSUM + r0] + smf[W_PSUM + 64 + r0];
        float Q0 = smf[W_PSQ + r0]  + smf[W_PSQ + 64 + r0];
        float S1 = smf[W_PSUM + r1] + smf[W_PSUM + 64 + r1];
        float Q1 = smf[W_PSQ + r1]  + smf[W_PSQ + 64 + r1];
        float m0 = S0 * (1.f / 64.f), m1 = S1 * (1.f / 64.f);
        float v0 = rsqrtf(Q0 * (1.f / 64.f) - m0 * m0 + 1e-5f);
        float v1 = rsqrtf(Q1 * (1.f / 64.f) - m1 * m1 + 1e-5f);

        if (wz == 1) {
#pragma unroll
            for (int j = 0; j < 4; j++) {
                int cb = 32 * wn + 8 * j + 2 * t4;
                float gx = __ldg(&lngN[cb]) * tlN, gy = __ldg(&lngN[cb + 1]) * tlN;
                float ex = __ldg(&lnbN[cb]) * tlN, ey = __ldg(&lnbN[cb + 1]) * tlN;
                if (node0 < NN) {
                    float z0 = fmaxf((c2[j][0] - m0) * v0 * gx + ex, 0.f);
                    float z1 = fmaxf((c2[j][1] - m0) * v0 * gy + ey, 0.f);
                    *(float2*)(g_z + node0 * HH + cb) = make_float2(z0, z1);
                }
                if (node1 < NN) {
                    float z0 = fmaxf((c2[j][2] - m1) * v1 * gx + ex, 0.f);
                    float z1 = fmaxf((c2[j][3] - m1) * v1 * gy + ey, 0.f);
                    *(float2*)(g_z + node1 * HH + cb) = make_float2(z0, z1);
                }
            }
        } else {
            // FINAL: a = relu(LN0(h)); out = a @ lw + lb
            float oA[3] = {0.f, 0.f, 0.f}, oB[3] = {0.f, 0.f, 0.f};
#pragma unroll
            for (int j = 0; j < 4; j++) {
                int cb = 32 * wn + 8 * j + 2 * t4;
                float gx = __ldg(&lngN[cb]), gy = __ldg(&lngN[cb + 1]);
                float ex = __ldg(&lnbN[cb]), ey = __ldg(&lnbN[cb + 1]);
                float a0 = fmaxf((c2[j][0] - m0) * v0 * gx + ex, 0.f);
                float a1 = fmaxf((c2[j][1] - m0) * v0 * gy + ey, 0.f);
                float b0 = fmaxf((c2[j][2] - m1) * v1 * gx + ex, 0.f);
                float b1 = fmaxf((c2[j][3] - m1) * v1 * gy + ey, 0.f);
#pragma unroll
                for (int k = 0; k < 3; k++) {
                    float w0 = __ldg(&lwg[cb * 3 + k]);
                    float w1 = __ldg(&lwg[(cb + 1) * 3 + k]);
                    oA[k] = fmaf(a0, w0, fmaf(a1, w1, oA[k]));
                    oB[k] = fmaf(b0, w0, fmaf(b1, w1, oB[k]));
                }
            }
#pragma unroll
            for (int k = 0; k < 3; k++) {
                oA[k] += __shfl_xor_sync(0xffffffffu, oA[k], 1);
                oA[k] += __shfl_xor_sync(0xffffffffu, oA[k], 2);
                oB[k] += __shfl_xor_sync(0xffffffffu, oB[k], 1);
                oB[k] += __shfl_xor_sync(0xffffffffu, oB[k], 2);
            }
            if (t4 == 0) {
#pragma unroll
                for (int k = 0; k < 3; k++) {
                    smf[W_SCR + wn * 192 + r0 * 3 + k] = oA[k];
                    smf[W_SCR + wn * 192 + r1 * 3 + k] = oB[k];
                }
            }
            __syncthreads();
            if (tid < 192) {
                int row = tid / 3, k = tid - row * 3;
                int node = n0 + row;
                if (node < NN) {
                    outp[node * 3 + k] = smf[W_SCR + row * 3 + k]
                                       + smf[W_SCR + 192 + row * 3 + k]
                                       + __ldg(&lbg[k]);
                }
            }
        }
    }
}

// ---------------- launch ----------------
extern "C" void kernel_launch(void* const* d_in, const int* in_sizes, int n_in,
                              void* d_out, int out_size) {
    const float* x    = (const float*)d_in[0];
    const int*   ei   = (const int*)  d_in[1];
    const float* encW = (const float*)d_in[2];
    const float* encb = (const float*)d_in[3];
    const float* t    = (const float*)d_in[4];
    const float* W1   = (const float*)d_in[5];
    const float* b1   = (const float*)d_in[6];
    const float* mg   = (const float*)d_in[7];
    const float* mb   = (const float*)d_in[8];
    const float* W2   = (const float*)d_in[9];
    const float* b2   = (const float*)d_in[10];
    const float* lng  = (const float*)d_in[11];
    const float* lnb  = (const float*)d_in[12];
    const float* lw   = (const float*)d_in[13];
    const float* lb   = (const float*)d_in[14];
    float* out = (float*)d_out;

    cudaFuncSetAttribute(k_mlp, cudaFuncAttributeMaxDynamicSharedMemorySize, SMEM_MLP_BYTES);

    const int WARP_BLOCKS = (NN * 32 + 255) / 256;
    const int MLP_BLOCKS  = (NN + 63) / 64;
    const int EH_BLOCKS   = (NN * 16 + 255) / 256;   // covers NE and 3*4096 too

    // CSR build + encoder + weight pre-split (launches 0..2)
    k_enc_hist<<<EH_BLOCKS, 256>>>(x, encW, encb, ei, W1, W2, t);
    k_scan<<<NB_SCAN, 1024>>>();
    k_scatter<<<(NE + 255) / 256, 256>>>(ei);

    // layer 0 (launch index 3 = k_agg -> profiled slot); mlp fuses z for layer 1
    k_agg<<<WARP_BLOCKS, 256>>>(t + 0);
    k_mlp<<<MLP_BLOCKS, 256, SMEM_MLP_BYTES>>>(b1, mg, mb, b2,
                                               lng + HH, lnb + HH, t + 1,
                                               lw, lb, out, 0, 0, 1);

    // layer 1 (mlp fuses z for layer 2)
    k_agg<<<WARP_BLOCKS, 256>>>(t + 1);
    k_mlp<<<MLP_BLOCKS, 256, SMEM_MLP_BYTES>>>(b1 + H2, mg + H2, mb + H2, b2 + HH,
                                               lng + 2 * HH, lnb + 2 * HH, t + 2,
                                               lw, lb, out, 1, 1, 1);
    // layer 2: FINAL mode — LN0 + projection fused, no g_h write, no k_final
    k_agg<<<WARP_BLOCKS, 256>>>(t + 2);
    k_mlp<<<MLP_BLOCKS, 256, SMEM_MLP_BYTES>>>(b1 + 2 * H2, mg + 2 * H2, mb + 2 * H2,
                                               b2 + 2 * HH, lng, lnb, t,
                                               lw, lb, out, 2, 1, 2);
}

// round 15
// speedup vs baseline: 1.2094x; 1.0438x over previous
#include <cuda_runtime.h>
#include <cuda_fp16.h>
#include <cstdint>

#define NN 100000
#define NE 1200000
#define HH 64
#define H2 128
#define NB_SCAN 98
#define LOG2E 1.44269504f

// ---------------- device scratch (no allocations allowed) ----------------
// g_z holds layer input PRE-SCALED by t_layer * log2(e)
__device__ float g_z[NN * HH];
__device__ float g_h[NN * HH];      // residual stream (fp32, unscaled)
__device__ unsigned g_uh[NN * 32];  // MLP input, f16x2 k-pair words (single prec)
__device__ int   g_rowptr[NN + 1];
__device__ int   g_wp[NN];          // zeroed by previous replay's last k_mlp
__device__ int   g_srcs[NE];        // src ids PRE-SCALED by 64
__device__ int   g_sval[128];
__device__ int   g_sincl[128];
__device__ int   g_sflag[128];      // tail-zeroed by last k_mlp
__device__ int   g_cnt2, g_done2;   // scan->scatter handoff (tail-zeroed)
// pre-split fp16 weights, [n][kp] rows (k contiguous):
__device__ unsigned g_w1h[3 * 4096], g_w1l[3 * 4096];
__device__ unsigned g_w2h[3 * 4096], g_w2l[3 * 4096];

// ---------------- helpers ----------------
__device__ __forceinline__ float ex2(float x) {
    float r; asm("ex2.approx.f32 %0, %1;" : "=f"(r) : "f"(x)); return r;
}
// pack pair (even k -> lo16, odd k -> hi16) as fp16x2
__device__ __forceinline__ unsigned pk_h2(float xe, float xo) {
    __half2 h = __floats2half2_rn(xe, xo);   // .x = lo = xe, .y = hi = xo
    return *reinterpret_cast<unsigned*>(&h);
}
__device__ __forceinline__ void split_pair_h(float xe, float xo, unsigned& hw, unsigned& lw) {
    __half2 h = __floats2half2_rn(xe, xo);
    hw = *reinterpret_cast<unsigned*>(&h);
    float2 bk = __half22float2(h);
    __half2 l = __floats2half2_rn(xe - bk.x, xo - bk.y);
    lw = *reinterpret_cast<unsigned*>(&l);
}
__device__ __forceinline__ uint32_t smem_u32(const void* p) {
    uint32_t a;
    asm("{ .reg .u64 t; cvta.to.shared.u64 t, %1; cvt.u32.u64 %0, t; }" : "=r"(a) : "l"(p));
    return a;
}
__device__ __forceinline__ void mma16(float* c, unsigned a0, unsigned a1,
                                      unsigned a2, unsigned a3,
                                      unsigned b0, unsigned b1) {
    asm("mma.sync.aligned.m16n8k16.row.col.f32.f16.f16.f32 "
        "{%0,%1,%2,%3}, {%4,%5,%6,%7}, {%8,%9}, {%0,%1,%2,%3};"
        : "+f"(c[0]), "+f"(c[1]), "+f"(c[2]), "+f"(c[3])
        : "r"(a0), "r"(a1), "r"(a2), "r"(a3), "r"(b0), "r"(b1));
}
__device__ __forceinline__ void ldsm4(unsigned& r0, unsigned& r1, unsigned& r2,
                                      unsigned& r3, uint32_t addr) {
    asm volatile("ldmatrix.sync.aligned.m8n8.x4.shared.b16 {%0,%1,%2,%3}, [%4];"
                 : "=r"(r0), "=r"(r1), "=r"(r2), "=r"(r3) : "r"(addr));
}

// ------ launch 0: encoder (scaled by t0*log2e) + histogram + W pre-split ---
__global__ void k_enc_hist(const float* __restrict__ x, const float* __restrict__ W,
                           const float* __restrict__ b, const int* __restrict__ ei,
                           const float* __restrict__ W1g, const float* __restrict__ W2g,
                           const float* __restrict__ t) {
    int idx = blockIdx.x * blockDim.x + threadIdx.x;
    if (idx == 0) g_rowptr[NN] = NE;
    if (idx < NE) atomicAdd(&g_wp[ei[NE + idx]], 1);
    if (idx < NN * 16) {
        float tl0 = __ldg(t) * LOG2E;
        int n = idx >> 4, c = (idx & 15) * 4;
        float x0 = x[n * 3], x1 = x[n * 3 + 1], x2 = x[n * 3 + 2];
        float4 w0 = *(const float4*)&W[c];
        float4 w1 = *(const float4*)&W[HH + c];
        float4 w2 = *(const float4*)&W[2 * HH + c];
        float4 bb = *(const float4*)&b[c];
        float4 o;
        o.x = (x0 * w0.x + x1 * w1.x + x2 * w2.x + bb.x) * tl0;
        o.y = (x0 * w0.y + x1 * w1.y + x2 * w2.y + bb.y) * tl0;
        o.z = (x0 * w0.z + x1 * w1.z + x2 * w2.z + bb.z) * tl0;
        o.w = (x0 * w0.w + x1 * w1.w + x2 * w2.w + bb.w) * tl0;
        *(float4*)&g_z[n * HH + c] = o;
    }
    if (idx < 3 * 4096) {   // W1^T: idx = l*4096 + n*32 + kp
        int l = idx >> 12, r = idx & 4095, n = r >> 5, kp = r & 31;
        const float* Wl = W1g + l * (HH * H2);
        unsigned hw, lw;
        split_pair_h(Wl[(2 * kp) * H2 + n], Wl[(2 * kp + 1) * H2 + n], hw, lw);
        g_w1h[idx] = hw; g_w1l[idx] = lw;
    }
    if (idx < 3 * 4096) {   // W2^T: idx = l*4096 + n*64 + kp
        int l = idx >> 12, r = idx & 4095, n = r >> 6, kp = r & 63;
        const float* Wl = W2g + l * (H2 * HH);
        unsigned hw, lw;
        split_pair_h(Wl[(2 * kp) * HH + n], Wl[(2 * kp + 1) * HH + n], hw, lw);
        g_w2h[idx] = hw; g_w2l[idx] = lw;
    }
}

// -------- launch 1: fused scan (decoupled lookback) + scatter --------------
// blocks 0..97 scan 1024 nodes each (256 thr x 4); all 1172 blocks resident,
// spin on g_done2, then grid-stride scatter.
__global__ __launch_bounds__(256, 8) void k_scan_scatter(const int* __restrict__ ei) {
    __shared__ int wsum[8];
    __shared__ int s_excl;
    int tid = threadIdx.x, b = blockIdx.x;
    int lane = tid & 31, wid = tid >> 5;

    if (b < NB_SCAN) {
        int i0 = b * 1024 + tid * 4;
        int a0 = (i0     < NN) ? g_wp[i0]     : 0;
        int a1 = (i0 + 1 < NN) ? g_wp[i0 + 1] : 0;
        int a2 = (i0 + 2 < NN) ? g_wp[i0 + 2] : 0;
        int a3 = (i0 + 3 < NN) ? g_wp[i0 + 3] : 0;
        int ts = a0 + a1 + a2 + a3;
        int v = ts;
#pragma unroll
        for (int d = 1; d < 32; d <<= 1) {
            int u = __shfl_up_sync(0xffffffffu, v, d);
            if (lane >= d) v += u;
        }
        if (lane == 31) wsum[wid] = v;
        __syncthreads();
        if (wid == 0 && lane < 8) {
            int w = wsum[lane];
#pragma unroll
            for (int d = 1; d < 8; d <<= 1) {
                int u = __shfl_up_sync(0xffu, w, d);
                if (lane >= d) w += u;
            }
            wsum[lane] = w;
        }
        __syncthreads();
        int tex = (v - ts) + (wid ? wsum[wid - 1] : 0);
        int bsum = wsum[7];
        if (tid == 0) {
            if (b == 0) {
                g_sincl[0] = bsum; __threadfence(); g_sflag[0] = 2;
                s_excl = 0;
            } else {
                g_sval[b] = bsum; __threadfence(); g_sflag[b] = 1;
                int excl = 0, j = b - 1;
                while (true) {
                    int f;
                    do { f = ((volatile int*)g_sflag)[j]; } while (f == 0);
                    __threadfence();
                    if (f == 2) { excl += ((volatile int*)g_sincl)[j]; break; }
                    excl += ((volatile int*)g_sval)[j]; j--;
                }
                g_sincl[b] = excl + bsum; __threadfence(); g_sflag[b] = 2;
                s_excl = excl;
            }
        }
        __syncthreads();
        int base = s_excl + tex;
        if (i0     < NN) { g_rowptr[i0]     = base;                g_wp[i0]     = base; }
        if (i0 + 1 < NN) { g_rowptr[i0 + 1] = base + a0;           g_wp[i0 + 1] = base + a0; }
        if (i0 + 2 < NN) { g_rowptr[i0 + 2] = base + a0 + a1;      g_wp[i0 + 2] = base + a0 + a1; }
        if (i0 + 3 < NN) { g_rowptr[i0 + 3] = base + a0 + a1 + a2; g_wp[i0 + 3] = base + a0 + a1 + a2; }
        __syncthreads();
        if (tid == 0) {
            __threadfence();
            int p = atomicAdd(&g_cnt2, 1);
            if (p == NB_SCAN - 1) atomicExch(&g_done2, 1);
        }
    }
    if (tid == 0) {
        while (atomicAdd(&g_done2, 0) == 0) { }
    }
    __syncthreads();
    for (int e = b * 256 + tid; e < NE; e += gridDim.x * 256) {
        int d = ei[NE + e];
        int p = atomicAdd(&g_wp[d], 1);
        g_srcs[p] = ei[e] << 6;   // src * HH
    }
}

// ------- single-pass softmax aggregation; g_z pre-scaled by t*log2e -------
__global__ __launch_bounds__(256, 8) void k_agg(const float* __restrict__ tptr) {
    int gw = (blockIdx.x * blockDim.x + threadIdx.x) >> 5;
    if (gw >= NN) return;
    int lane = threadIdx.x & 31;
    int beg = g_rowptr[gw], end = g_rowptr[gw + 1];
    float tl2 = __ldg(tptr) * LOG2E;
    float inv_tl2 = __fdividef(1.f, tl2);
    const float* zp = g_z + 2 * lane;

    float z0 = 0.f, z1 = 0.f, s0 = 0.f, s1 = 0.f;
    for (int base = beg; base < end; base += 32) {
        int nn = end - base; if (nn > 32) nn = 32;
        int sid = (base + lane < end) ? __ldg(&g_srcs[base + lane]) : 0;
#pragma unroll 4
        for (int j = 0; j < nn; j++) {
            int s = __shfl_sync(0xffffffffu, sid, j);
            float2 v = *(const float2*)(zp + s);
            float m0 = fmaxf(v.x, 0.f), m1 = fmaxf(v.y, 0.f);
            float w0 = ex2(m0);
            float w1 = ex2(m1);
            z0 += w0; z1 += w1;
            s0 = fmaf(m0, w0, s0);
            s1 = fmaf(m1, w1, s1);
        }
    }
    float2 zz = *(const float2*)(g_z + gw * HH + 2 * lane);   // scaled self
    float ox, oy;
    if (end > beg) {
        ox = (zz.x + __fdividef(s0, z0)) * inv_tl2 + 1e-7f;
        oy = (zz.y + __fdividef(s1, z1)) * inv_tl2 + 1e-7f;
    } else {
        ox = zz.x * inv_tl2;
        oy = zz.y * inv_tl2;
    }
    g_uh[gw * 32 + lane] = pk_h2(ox, oy);
}

// ---- fused MLP: fp16 mma.sync + ldmatrix, 2-term (A single, B split) ----
// wz=0: plain; wz=1: write NEXT-layer z pre-scaled; wz=2: FINAL (LN0+proj->out)
#define W_PSUM 0
#define W_PSQ  128
#define W_B1   256
#define W_GAM  384
#define W_BET  512
#define W_B2   640
#define W_A    704            // sUH [64][36] -> sHH [64][68] (4352 words)
#define W_UH   (W_A)
#define W_HH   (W_A)
#define W_W    (W_A + 4352)   // 5056
#define W_W1H  (W_W)          // [128][36] = 4608
#define W_W1L  (W_W + 4608)
#define W_W2H  (W_W)          // [64][68] = 4352
#define W_W2L  (W_W + 4352)
#define W_SCR  (W_W)          // final-projection scratch
#define SMEM_MLP_WORDS 14272
#define SMEM_MLP_BYTES (SMEM_MLP_WORDS * 4)

extern __shared__ unsigned smw[];
__global__ __launch_bounds__(256, 3) void k_mlp(
    const float* __restrict__ b1g, const float* __restrict__ gamg,
    const float* __restrict__ betg, const float* __restrict__ b2g,
    const float* __restrict__ lngN, const float* __restrict__ lnbN,
    const float* __restrict__ tN,
    const float* __restrict__ lwg, const float* __restrict__ lbg,
    float* __restrict__ outp,
    int layer, int addm, int wz)
{
    float* smf = (float*)smw;
    int tid = threadIdx.x, w = tid >> 5, lane = tid & 31;
    int g = lane >> 2, t4 = lane & 3;
    int wm = w & 3, wn = w >> 2;
    int n0 = blockIdx.x * 64;
    int lofs = layer * 4096;

    if (wz == 2) {   // scratch re-zero for next replay
        int n = n0 + tid;
        if (tid < 64 && n < NN) g_wp[n] = 0;
        if (blockIdx.x == 0) {
            if (tid >= 64 && tid < 192) g_sflag[tid - 64] = 0;
            if (tid == 192) { g_cnt2 = 0; g_done2 = 0; }
        }
    }
    if (tid < 128) {
        smf[W_B1 + tid]  = b1g[tid];
        smf[W_GAM + tid] = gamg[tid];
        smf[W_BET + tid] = betg[tid];
        if (tid < 64) smf[W_B2 + tid] = b2g[tid];
    }
    // U (single fp16) [64][36]
    for (int i = tid * 4; i < 2048; i += 1024) {
        int r = i >> 5, c = i & 31;
        int node = n0 + r;
        uint4 hv = make_uint4(0, 0, 0, 0);
        if (node < NN) hv = *(const uint4*)&g_uh[node * 32 + c];
        *(uint4*)&smw[W_UH + r * 36 + c] = hv;
    }
    // W1 split [128][36] x2
    for (int i = tid * 4; i < 4096; i += 1024) {
        int r = i >> 5, c = i & 31;
        *(uint4*)&smw[W_W1H + r * 36 + c] = *(const uint4*)&g_w1h[lofs + i];
        *(uint4*)&smw[W_W1L + r * 36 + c] = *(const uint4*)&g_w1l[lofs + i];
    }
    __syncthreads();

    uint32_t sb = smem_u32(smw);
    int lr = (lane & 7) + ((lane >> 3) & 1) * 8;
    int lhalf = lane >> 4;
    int l8 = lane & 7, lg = lane >> 3;

    // ---- GEMM1: 2-term fp16 ----
    uint32_t a1H = sb + W_UH * 4 + (16 * wm + lr) * 144 + lhalf * 16;
    uint32_t b1H = sb + W_W1H * 4 + (64 * wn + l8) * 144 + lg * 16;
    uint32_t b1L = b1H + 4608 * 4;

    float c1[8][4];
#pragma unroll
    for (int j = 0; j < 8; j++)
#pragma unroll
        for (int q = 0; q < 4; q++) c1[j][q] = 0.f;

#pragma unroll
    for (int p = 0; p < 2; p++) {
        unsigned aH0[4], aH1[4];
        ldsm4(aH0[0], aH0[1], aH0[2], aH0[3], a1H + p * 64);
        ldsm4(aH1[0], aH1[1], aH1[2], aH1[3], a1H + p * 64 + 32);
#pragma unroll
        for (int j = 0; j < 8; j++) {
            unsigned h0, h1, h2, h3, l0, l1, l2, l3;
            ldsm4(h0, h1, h2, h3, b1H + j * 1152 + p * 64);
            ldsm4(l0, l1, l2, l3, b1L + j * 1152 + p * 64);
            mma16(c1[j], aH0[0], aH0[1], aH0[2], aH0[3], h0, h1);
            mma16(c1[j], aH0[0], aH0[1], aH0[2], aH0[3], l0, l1);
            mma16(c1[j], aH1[0], aH1[1], aH1[2], aH1[3], h2, h3);
            mma16(c1[j], aH1[0], aH1[1], aH1[2], aH1[3], l2, l3);
        }
    }

    // ---- epilogue 1: bias + LN(128) partial sums ----
    int r0 = 16 * wm + g, r1 = r0 + 8;
    float sA = 0.f, sqA = 0.f, sB = 0.f, sqB = 0.f;
#pragma unroll
    for (int j = 0; j < 8; j++) {
        int cb = 64 * wn + 8 * j + 2 * t4;
        float bx = smf[W_B1 + cb], by = smf[W_B1 + cb + 1];
        c1[j][0] += bx; c1[j][1] += by; c1[j][2] += bx; c1[j][3] += by;
        sA += c1[j][0] + c1[j][1];
        sqA = fmaf(c1[j][0], c1[j][0], fmaf(c1[j][1], c1[j][1], sqA));
        sB += c1[j][2] + c1[j][3];
        sqB = fmaf(c1[j][2], c1[j][2], fmaf(c1[j][3], c1[j][3], sqB));
    }
    sA += __shfl_xor_sync(0xffffffffu, sA, 1);  sA += __shfl_xor_sync(0xffffffffu, sA, 2);
    sqA += __shfl_xor_sync(0xffffffffu, sqA, 1); sqA += __shfl_xor_sync(0xffffffffu, sqA, 2);
    sB += __shfl_xor_sync(0xffffffffu, sB, 1);  sB += __shfl_xor_sync(0xffffffffu, sB, 2);
    sqB += __shfl_xor_sync(0xffffffffu, sqB, 1); sqB += __shfl_xor_sync(0xffffffffu, sqB, 2);
    if (t4 == 0) {
        smf[W_PSUM + wn * 64 + r0] = sA;  smf[W_PSQ + wn * 64 + r0] = sqA;
        smf[W_PSUM + wn * 64 + r1] = sB;  smf[W_PSQ + wn * 64 + r1] = sqB;
    }
    __syncthreads();   // GEMM1 reads done; W region free for W2

    for (int i = tid * 4; i < 4096; i += 1024) {
        int r = i >> 6, c = i & 63;
        *(uint4*)&smw[W_W2H + r * 68 + c] = *(const uint4*)&g_w2h[lofs + i];
        *(uint4*)&smw[W_W2L + r * 68 + c] = *(const uint4*)&g_w2l[lofs + i];
    }

    float s0 = smf[W_PSUM + r0] + smf[W_PSUM + 64 + r0];
    float q0 = smf[W_PSQ + r0]  + smf[W_PSQ + 64 + r0];
    float s1 = smf[W_PSUM + r1] + smf[W_PSUM + 64 + r1];
    float q1 = smf[W_PSQ + r1]  + smf[W_PSQ + 64 + r1];
    float mu0 = s0 * (1.f / 128.f), mu1 = s1 * (1.f / 128.f);
    float rs0 = rsqrtf(q0 * (1.f / 128.f) - mu0 * mu0 + 1e-5f);
    float rs1 = rsqrtf(q1 * (1.f / 128.f) - mu1 * mu1 + 1e-5f);

#pragma unroll
    for (int j = 0; j < 8; j++) {
        int cb = 64 * wn + 8 * j + 2 * t4;
        float gx = smf[W_GAM + cb], gy = smf[W_GAM + cb + 1];
        float ex = smf[W_BET + cb], ey = smf[W_BET + cb + 1];
        float h0 = fmaxf((c1[j][0] - mu0) * rs0 * gx + ex, 0.f);
        float h1 = fmaxf((c1[j][1] - mu0) * rs0 * gy + ey, 0.f);
        float h2 = fmaxf((c1[j][2] - mu1) * rs1 * gx + ex, 0.f);
        float h3 = fmaxf((c1[j][3] - mu1) * rs1 * gy + ey, 0.f);
        int kp = cb >> 1;
        smw[W_HH + r0 * 68 + kp] = pk_h2(h0, h1);
        smw[W_HH + r1 * 68 + kp] = pk_h2(h2, h3);
    }
    __syncthreads();   // act + W2 both visible

    // ---- GEMM2: 2-term fp16 ----
    uint32_t a2H = sb + W_HH * 4 + (16 * wm + lr) * 272 + lhalf * 16;
    uint32_t b2H = sb + W_W2H * 4 + (32 * wn + l8) * 272 + lg * 16;
    uint32_t b2L = b2H + 4352 * 4;

    float c2[4][4];
#pragma unroll
    for (int j = 0; j < 4; j++)
#pragma unroll
        for (int q = 0; q < 4; q++) c2[j][q] = 0.f;

#pragma unroll
    for (int p = 0; p < 4; p++) {
        unsigned xh[8];
        ldsm4(xh[0], xh[1], xh[2], xh[3], a2H + p * 64);
        ldsm4(xh[4], xh[5], xh[6], xh[7], a2H + p * 64 + 32);
#pragma unroll
        for (int j = 0; j < 4; j++) {
            unsigned h0, h1, h2, h3, l0, l1, l2, l3;
            ldsm4(h0, h1, h2, h3, b2H + j * 2176 + p * 64);
            ldsm4(l0, l1, l2, l3, b2L + j * 2176 + p * 64);
            mma16(c2[j], xh[0], xh[1], xh[2], xh[3], h0, h1);
            mma16(c2[j], xh[0], xh[1], xh[2], xh[3], l0, l1);
            mma16(c2[j], xh[4], xh[5], xh[6], xh[7], h2, h3);
            mma16(c2[j], xh[4], xh[5], xh[6], xh[7], l2, l3);
        }
    }

    // ---- epilogue 2: bias (+residual); store g_h unless FINAL ----
    int node0 = n0 + r0, node1 = n0 + r1;
    float ps0 = 0.f, pq0 = 0.f, ps1 = 0.f, pq1 = 0.f;
#pragma unroll
    for (int j = 0; j < 4; j++) {
        int cb = 32 * wn + 8 * j + 2 * t4;
        float bx = smf[W_B2 + cb], by = smf[W_B2 + cb + 1];
        float h00 = c2[j][0] + bx, h01 = c2[j][1] + by;
        float h10 = c2[j][2] + bx, h11 = c2[j][3] + by;
        if (node0 < NN) {
            float* dst = g_h + node0 * HH + cb;
            if (addm) { float2 pv = *(const float2*)dst; h00 += pv.x; h01 += pv.y; }
            if (wz != 2) *(float2*)dst = make_float2(h00, h01);
        }
        if (node1 < NN) {
            float* dst = g_h + node1 * HH + cb;
            if (addm) { float2 pv = *(const float2*)dst; h10 += pv.x; h11 += pv.y; }
            if (wz != 2) *(float2*)dst = make_float2(h10, h11);
        }
        c2[j][0] = h00; c2[j][1] = h01; c2[j][2] = h10; c2[j][3] = h11;
        ps0 += h00 + h01; pq0 = fmaf(h00, h00, fmaf(h01, h01, pq0));
        ps1 += h10 + h11; pq1 = fmaf(h10, h10, fmaf(h11, h11, pq1));
    }

    // ---- LN over 64 ch of final h (wz=1: z-write; wz=2: projection) ----
    if (wz) {
        float tlN = (wz == 1) ? __ldg(tN) * LOG2E : 1.f;
        ps0 += __shfl_xor_sync(0xffffffffu, ps0, 1); ps0 += __shfl_xor_sync(0xffffffffu, ps0, 2);
        pq0 += __shfl_xor_sync(0xffffffffu, pq0, 1); pq0 += __shfl_xor_sync(0xffffffffu, pq0, 2);
        ps1 += __shfl_xor_sync(0xffffffffu, ps1, 1); ps1 += __shfl_xor_sync(0xffffffffu, ps1, 2);
        pq1 += __shfl_xor_sync(0xffffffffu, pq1, 1); pq1 += __shfl_xor_sync(0xffffffffu, pq1, 2);
        if (t4 == 0) {
            smf[W_PSUM + wn * 64 + r0] = ps0;  smf[W_PSQ + wn * 64 + r0] = pq0;
            smf[W_PSUM + wn * 64 + r1] = ps1;  smf[W_PSQ + wn * 64 + r1] = pq1;
        }
        __syncthreads();   // also: GEMM2 done -> W region reusable as scratch
        float S0 = smf[W_PSUM + r0] + smf[W_PSUM + 64 + r0];
        float Q0 = smf[W_PSQ + r0]  + smf[W_PSQ + 64 + r0];
        float S1 = smf[W_PSUM + r1] + smf[W_PSUM + 64 + r1];
        float Q1 = smf[W_PSQ + r1]  + smf[W_PSQ + 64 + r1];
        float m0 = S0 * (1.f / 64.f), m1 = S1 * (1.f / 64.f);
        float v0 = rsqrtf(Q0 * (1.f / 64.f) - m0 * m0 + 1e-5f);
        float v1 = rsqrtf(Q1 * (1.f / 64.f) - m1 * m1 + 1e-5f);

        if (wz == 1) {
#pragma unroll
            for (int j = 0; j < 4; j++) {
                int cb = 32 * wn + 8 * j + 2 * t4;
                float gx = __ldg(&lngN[cb]) * tlN, gy = __ldg(&lngN[cb + 1]) * tlN;
                float ex = __ldg(&lnbN[cb]) * tlN, ey = __ldg(&lnbN[cb + 1]) * tlN;
                if (node0 < NN) {
                    float z0 = fmaxf((c2[j][0] - m0) * v0 * gx + ex, 0.f);
                    float z1 = fmaxf((c2[j][1] - m0) * v0 * gy + ey, 0.f);
                    *(float2*)(g_z + node0 * HH + cb) = make_float2(z0, z1);
                }
                if (node1 < NN) {
                    float z0 = fmaxf((c2[j][2] - m1) * v1 * gx + ex, 0.f);
                    float z1 = fmaxf((c2[j][3] - m1) * v1 * gy + ey, 0.f);
                    *(float2*)(g_z + node1 * HH + cb) = make_float2(z0, z1);
                }
            }
        } else {
            float oA[3] = {0.f, 0.f, 0.f}, oB[3] = {0.f, 0.f, 0.f};
#pragma unroll
            for (int j = 0; j < 4; j++) {
                int cb = 32 * wn + 8 * j + 2 * t4;
                float gx = __ldg(&lngN[cb]), gy = __ldg(&lngN[cb + 1]);
                float ex = __ldg(&lnbN[cb]), ey = __ldg(&lnbN[cb + 1]);
                float a0 = fmaxf((c2[j][0] - m0) * v0 * gx + ex, 0.f);
                float a1 = fmaxf((c2[j][1] - m0) * v0 * gy + ey, 0.f);
                float b0 = fmaxf((c2[j][2] - m1) * v1 * gx + ex, 0.f);
                float b1 = fmaxf((c2[j][3] - m1) * v1 * gy + ey, 0.f);
#pragma unroll
                for (int k = 0; k < 3; k++) {
                    float w0 = __ldg(&lwg[cb * 3 + k]);
                    float w1 = __ldg(&lwg[(cb + 1) * 3 + k]);
                    oA[k] = fmaf(a0, w0, fmaf(a1, w1, oA[k]));
                    oB[k] = fmaf(b0, w0, fmaf(b1, w1, oB[k]));
                }
            }
#pragma unroll
            for (int k = 0; k < 3; k++) {
                oA[k] += __shfl_xor_sync(0xffffffffu, oA[k], 1);
                oA[k] += __shfl_xor_sync(0xffffffffu, oA[k], 2);
                oB[k] += __shfl_xor_sync(0xffffffffu, oB[k], 1);
                oB[k] += __shfl_xor_sync(0xffffffffu, oB[k], 2);
            }
            if (t4 == 0) {
#pragma unroll
                for (int k = 0; k < 3; k++) {
                    smf[W_SCR + wn * 192 + r0 * 3 + k] = oA[k];
                    smf[W_SCR + wn * 192 + r1 * 3 + k] = oB[k];
                }
            }
            __syncthreads();
            if (tid < 192) {
                int row = tid / 3, k = tid - row * 3;
                int node = n0 + row;
                if (node < NN) {
                    outp[node * 3 + k] = smf[W_SCR + row * 3 + k]
                                       + smf[W_SCR + 192 + row * 3 + k]
                                       + __ldg(&lbg[k]);
                }
            }
        }
    }
}

// ---------------- launch ----------------
extern "C" void kernel_launch(void* const* d_in, const int* in_sizes, int n_in,
                              void* d_out, int out_size) {
    const float* x    = (const float*)d_in[0];
    const int*   ei   = (const int*)  d_in[1];
    const float* encW = (const float*)d_in[2];
    const float* encb = (const float*)d_in[3];
    const float* t    = (const float*)d_in[4];
    const float* W1   = (const float*)d_in[5];
    const float* b1   = (const float*)d_in[6];
    const float* mg   = (const float*)d_in[7];
    const float* mb   = (const float*)d_in[8];
    const float* W2   = (const float*)d_in[9];
    const float* b2   = (const float*)d_in[10];
    const float* lng  = (const float*)d_in[11];
    const float* lnb  = (const float*)d_in[12];
    const float* lw   = (const float*)d_in[13];
    const float* lb   = (const float*)d_in[14];
    float* out = (float*)d_out;

    cudaFuncSetAttribute(k_mlp, cudaFuncAttributeMaxDynamicSharedMemorySize, SMEM_MLP_BYTES);

    const int WARP_BLOCKS = (NN * 32 + 255) / 256;
    const int MLP_BLOCKS  = (NN + 63) / 64;
    const int EH_BLOCKS   = (NN * 16 + 255) / 256;   // covers NE and 3*4096 too
    const int SS_BLOCKS   = 1172;                    // all-resident (256thr, 8/SM)

    // launch 0: encoder + histogram + weight pre-split
    k_enc_hist<<<EH_BLOCKS, 256>>>(x, encW, encb, ei, W1, W2, t);
    // launch 1: fused scan + scatter
    k_scan_scatter<<<SS_BLOCKS, 256>>>(ei);

    // layer 0 (launch 2 = agg, launch 3 = mlp -> profiled slot)
    k_agg<<<WARP_BLOCKS, 256>>>(t + 0);
    k_mlp<<<MLP_BLOCKS, 256, SMEM_MLP_BYTES>>>(b1, mg, mb, b2,
                                               lng + HH, lnb + HH, t + 1,
                                               lw, lb, out, 0, 0, 1);

    // layer 1 (fuses z for layer 2)
    k_agg<<<WARP_BLOCKS, 256>>>(t + 1);
    k_mlp<<<MLP_BLOCKS, 256, SMEM_MLP_BYTES>>>(b1 + H2, mg + H2, mb + H2, b2 + HH,
                                               lng + 2 * HH, lnb + 2 * HH, t + 2,
                                               lw, lb, out, 1, 1, 1);
    // layer 2: FINAL mode (LN0 + projection fused; also re-zeroes scratch)
    k_agg<<<WARP_BLOCKS, 256>>>(t + 2);
    k_mlp<<<MLP_BLOCKS, 256, SMEM_MLP_BYTES>>>(b1 + 2 * H2, mg + 2 * H2, mb + 2 * H2,
                                               b2 + 2 * HH, lng, lnb, t,
                                               lw, lb, out, 2, 1, 2);
}

// round 16
// speedup vs baseline: 1.2273x; 1.0148x over previous
#include <cuda_runtime.h>
#include <cuda_fp16.h>
#include <cstdint>

#define NN 100000
#define NE 1200000
#define HH 64
#define H2 128
#define NB_SCAN 98
#define LOG2E 1.44269504f

// ---------------- device scratch (no allocations allowed) ----------------
// g_z holds layer input PRE-SCALED by t_layer * log2(e)
__device__ float g_z[NN * HH];
__device__ float g_h[NN * HH];      // residual stream (fp32, unscaled)
__device__ unsigned g_uh[NN * 32];  // MLP input, f16x2 k-pair words
__device__ int   g_rowptr[NN + 1];
__device__ int   g_wp[NN];          // zeroed by previous replay's last k_mlp
__device__ int   g_srcs[NE];        // src ids PRE-SCALED by 64
__device__ int   g_sval[128];
__device__ int   g_sincl[128];
__device__ int   g_sflag[128];      // tail-zeroed by last k_mlp
__device__ int   g_cnt2, g_done2;   // scan->scatter handoff (tail-zeroed)
// pre-split fp16 weights, [n][kp] rows (k contiguous):
__device__ unsigned g_w1h[3 * 4096], g_w1l[3 * 4096];
__device__ unsigned g_w2h[3 * 4096], g_w2l[3 * 4096];

// ---------------- helpers ----------------
__device__ __forceinline__ float ex2(float x) {
    float r; asm("ex2.approx.f32 %0, %1;" : "=f"(r) : "f"(x)); return r;
}
__device__ __forceinline__ unsigned pk_h2(float xe, float xo) {
    __half2 h = __floats2half2_rn(xe, xo);
    return *reinterpret_cast<unsigned*>(&h);
}
__device__ __forceinline__ void split_pair_h(float xe, float xo, unsigned& hw, unsigned& lw) {
    __half2 h = __floats2half2_rn(xe, xo);
    hw = *reinterpret_cast<unsigned*>(&h);
    float2 bk = __half22float2(h);
    __half2 l = __floats2half2_rn(xe - bk.x, xo - bk.y);
    lw = *reinterpret_cast<unsigned*>(&l);
}
__device__ __forceinline__ uint32_t smem_u32(const void* p) {
    uint32_t a;
    asm("{ .reg .u64 t; cvta.to.shared.u64 t, %1; cvt.u32.u64 %0, t; }" : "=r"(a) : "l"(p));
    return a;
}
__device__ __forceinline__ void mma16(float* c, unsigned a0, unsigned a1,
                                      unsigned a2, unsigned a3,
                                      unsigned b0, unsigned b1) {
    asm("mma.sync.aligned.m16n8k16.row.col.f32.f16.f16.f32 "
        "{%0,%1,%2,%3}, {%4,%5,%6,%7}, {%8,%9}, {%0,%1,%2,%3};"
        : "+f"(c[0]), "+f"(c[1]), "+f"(c[2]), "+f"(c[3])
        : "r"(a0), "r"(a1), "r"(a2), "r"(a3), "r"(b0), "r"(b1));
}
__device__ __forceinline__ void ldsm4(unsigned& r0, unsigned& r1, unsigned& r2,
                                      unsigned& r3, uint32_t addr) {
    asm volatile("ldmatrix.sync.aligned.m8n8.x4.shared.b16 {%0,%1,%2,%3}, [%4];"
                 : "=r"(r0), "=r"(r1), "=r"(r2), "=r"(r3) : "r"(addr));
}

// ------ launch 0: encoder (scaled by t0*log2e) + histogram + W pre-split ---
__global__ void k_enc_hist(const float* __restrict__ x, const float* __restrict__ W,
                           const float* __restrict__ b, const int* __restrict__ ei,
                           const float* __restrict__ W1g, const float* __restrict__ W2g,
                           const float* __restrict__ t) {
    int idx = blockIdx.x * blockDim.x + threadIdx.x;
    if (idx == 0) g_rowptr[NN] = NE;
    if (idx < NE) atomicAdd(&g_wp[ei[NE + idx]], 1);
    if (idx < NN * 16) {
        float tl0 = __ldg(t) * LOG2E;
        int n = idx >> 4, c = (idx & 15) * 4;
        float x0 = x[n * 3], x1 = x[n * 3 + 1], x2 = x[n * 3 + 2];
        float4 w0 = *(const float4*)&W[c];
        float4 w1 = *(const float4*)&W[HH + c];
        float4 w2 = *(const float4*)&W[2 * HH + c];
        float4 bb = *(const float4*)&b[c];
        float4 o;
        o.x = (x0 * w0.x + x1 * w1.x + x2 * w2.x + bb.x) * tl0;
        o.y = (x0 * w0.y + x1 * w1.y + x2 * w2.y + bb.y) * tl0;
        o.z = (x0 * w0.z + x1 * w1.z + x2 * w2.z + bb.z) * tl0;
        o.w = (x0 * w0.w + x1 * w1.w + x2 * w2.w + bb.w) * tl0;
        *(float4*)&g_z[n * HH + c] = o;
    }
    if (idx < 3 * 4096) {   // W1^T: idx = l*4096 + n*32 + kp
        int l = idx >> 12, r = idx & 4095, n = r >> 5, kp = r & 31;
        const float* Wl = W1g + l * (HH * H2);
        unsigned hw, lw;
        split_pair_h(Wl[(2 * kp) * H2 + n], Wl[(2 * kp + 1) * H2 + n], hw, lw);
        g_w1h[idx] = hw; g_w1l[idx] = lw;
    }
    if (idx < 3 * 4096) {   // W2^T: idx = l*4096 + n*64 + kp
        int l = idx >> 12, r = idx & 4095, n = r >> 6, kp = r & 63;
        const float* Wl = W2g + l * (H2 * HH);
        unsigned hw, lw;
        split_pair_h(Wl[(2 * kp) * HH + n], Wl[(2 * kp + 1) * HH + n], hw, lw);
        g_w2h[idx] = hw; g_w2l[idx] = lw;
    }
}

// -------- launch 1: fused scan (decoupled lookback) + scatter --------------
__global__ __launch_bounds__(256, 8) void k_scan_scatter(const int* __restrict__ ei) {
    __shared__ int wsum[8];
    __shared__ int s_excl;
    int tid = threadIdx.x, b = blockIdx.x;
    int lane = tid & 31, wid = tid >> 5;

    if (b < NB_SCAN) {
        int i0 = b * 1024 + tid * 4;
        int a0 = (i0     < NN) ? g_wp[i0]     : 0;
        int a1 = (i0 + 1 < NN) ? g_wp[i0 + 1] : 0;
        int a2 = (i0 + 2 < NN) ? g_wp[i0 + 2] : 0;
        int a3 = (i0 + 3 < NN) ? g_wp[i0 + 3] : 0;
        int ts = a0 + a1 + a2 + a3;
        int v = ts;
#pragma unroll
        for (int d = 1; d < 32; d <<= 1) {
            int u = __shfl_up_sync(0xffffffffu, v, d);
            if (lane >= d) v += u;
        }
        if (lane == 31) wsum[wid] = v;
        __syncthreads();
        if (wid == 0 && lane < 8) {
            int w = wsum[lane];
#pragma unroll
            for (int d = 1; d < 8; d <<= 1) {
                int u = __shfl_up_sync(0xffu, w, d);
                if (lane >= d) w += u;
            }
            wsum[lane] = w;
        }
        __syncthreads();
        int tex = (v - ts) + (wid ? wsum[wid - 1] : 0);
        int bsum = wsum[7];
        if (tid == 0) {
            if (b == 0) {
                g_sincl[0] = bsum; __threadfence(); g_sflag[0] = 2;
                s_excl = 0;
            } else {
                g_sval[b] = bsum; __threadfence(); g_sflag[b] = 1;
                int excl = 0, j = b - 1;
                while (true) {
                    int f;
                    do { f = ((volatile int*)g_sflag)[j]; } while (f == 0);
                    __threadfence();
                    if (f == 2) { excl += ((volatile int*)g_sincl)[j]; break; }
                    excl += ((volatile int*)g_sval)[j]; j--;
                }
                g_sincl[b] = excl + bsum; __threadfence(); g_sflag[b] = 2;
                s_excl = excl;
            }
        }
        __syncthreads();
        int base = s_excl + tex;
        if (i0     < NN) { g_rowptr[i0]     = base;                g_wp[i0]     = base; }
        if (i0 + 1 < NN) { g_rowptr[i0 + 1] = base + a0;           g_wp[i0 + 1] = base + a0; }
        if (i0 + 2 < NN) { g_rowptr[i0 + 2] = base + a0 + a1;      g_wp[i0 + 2] = base + a0 + a1; }
        if (i0 + 3 < NN) { g_rowptr[i0 + 3] = base + a0 + a1 + a2; g_wp[i0 + 3] = base + a0 + a1 + a2; }
        __syncthreads();
        if (tid == 0) {
            __threadfence();
            int p = atomicAdd(&g_cnt2, 1);
            if (p == NB_SCAN - 1) atomicExch(&g_done2, 1);
        }
    }
    if (tid == 0) {
        while (atomicAdd(&g_done2, 0) == 0) { }
    }
    __syncthreads();
    for (int e = b * 256 + tid; e < NE; e += gridDim.x * 256) {
        int d = ei[NE + e];
        int p = atomicAdd(&g_wp[d], 1);
        g_srcs[p] = ei[e] << 6;   // src * HH
    }
}

// ------- single-pass softmax aggregation; g_z pre-scaled by t*log2e -------
__global__ __launch_bounds__(256, 8) void k_agg(const float* __restrict__ tptr) {
    int gw = (blockIdx.x * blockDim.x + threadIdx.x) >> 5;
    if (gw >= NN) return;
    int lane = threadIdx.x & 31;
    int beg = g_rowptr[gw], end = g_rowptr[gw + 1];
    float tl2 = __ldg(tptr) * LOG2E;
    float inv_tl2 = __fdividef(1.f, tl2);
    const float* zp = g_z + 2 * lane;

    float z0 = 0.f, z1 = 0.f, s0 = 0.f, s1 = 0.f;
    for (int base = beg; base < end; base += 32) {
        int nn = end - base; if (nn > 32) nn = 32;
        int sid = (base + lane < end) ? __ldg(&g_srcs[base + lane]) : 0;
#pragma unroll 4
        for (int j = 0; j < nn; j++) {
            int s = __shfl_sync(0xffffffffu, sid, j);
            float2 v = *(const float2*)(zp + s);
            float m0 = fmaxf(v.x, 0.f), m1 = fmaxf(v.y, 0.f);
            float w0 = ex2(m0);
            float w1 = ex2(m1);
            z0 += w0; z1 += w1;
            s0 = fmaf(m0, w0, s0);
            s1 = fmaf(m1, w1, s1);
        }
    }
    float2 zz = *(const float2*)(g_z + gw * HH + 2 * lane);
    float ox, oy;
    if (end > beg) {
        ox = (zz.x + __fdividef(s0, z0)) * inv_tl2 + 1e-7f;
        oy = (zz.y + __fdividef(s1, z1)) * inv_tl2 + 1e-7f;
    } else {
        ox = zz.x * inv_tl2;
        oy = zz.y * inv_tl2;
    }
    g_uh[gw * 32 + lane] = pk_h2(ox, oy);
}

// ---- fused MLP: fp16 mma.sync + ldmatrix; warp tile M32xN32 (B reuse) ----
// wz=0: plain; wz=1: write NEXT-layer z pre-scaled; wz=2: FINAL (LN0+proj->out)
#define W_PSUM 0              // [4][64]
#define W_PSQ  256            // [4][64]
#define W_B1   512
#define W_GAM  640
#define W_BET  768
#define W_B2   896
#define W_A    960            // sUH [64][36] -> sHH [64][68] (4352 words)
#define W_UH   (W_A)
#define W_HH   (W_A)
#define W_W    (W_A + 4352)   // 5312
#define W_W1H  (W_W)          // [128][36] = 4608
#define W_W1L  (W_W + 4608)
#define W_W2H  (W_W)          // [64][68] = 4352
#define W_W2L  (W_W + 4352)
#define W_SCR  (W_W)          // final-projection scratch [4][64][3]
#define SMEM_MLP_WORDS 14528
#define SMEM_MLP_BYTES (SMEM_MLP_WORDS * 4)

extern __shared__ unsigned smw[];
__global__ __launch_bounds__(256, 3) void k_mlp(
    const float* __restrict__ b1g, const float* __restrict__ gamg,
    const float* __restrict__ betg, const float* __restrict__ b2g,
    const float* __restrict__ lngN, const float* __restrict__ lnbN,
    const float* __restrict__ tN,
    const float* __restrict__ lwg, const float* __restrict__ lbg,
    float* __restrict__ outp,
    int layer, int addm, int wz)
{
    float* smf = (float*)smw;
    int tid = threadIdx.x, w = tid >> 5, lane = tid & 31;
    int g = lane >> 2, t4 = lane & 3;
    int wm = w & 1, wn = w >> 1;          // M32 x N32 warp tile
    int n0 = blockIdx.x * 64;
    int lofs = layer * 4096;

    if (wz == 2) {   // scratch re-zero for next replay
        int n = n0 + tid;
        if (tid < 64 && n < NN) g_wp[n] = 0;
        if (blockIdx.x == 0) {
            if (tid >= 64 && tid < 192) g_sflag[tid - 64] = 0;
            if (tid == 192) { g_cnt2 = 0; g_done2 = 0; }
        }
    }
    if (tid < 128) {
        smf[W_B1 + tid]  = b1g[tid];
        smf[W_GAM + tid] = gamg[tid];
        smf[W_BET + tid] = betg[tid];
        if (tid < 64) smf[W_B2 + tid] = b2g[tid];
    }
    // U (single fp16) [64][36]
    for (int i = tid * 4; i < 2048; i += 1024) {
        int r = i >> 5, c = i & 31;
        int node = n0 + r;
        uint4 hv = make_uint4(0, 0, 0, 0);
        if (node < NN) hv = *(const uint4*)&g_uh[node * 32 + c];
        *(uint4*)&smw[W_UH + r * 36 + c] = hv;
    }
    // W1 split [128][36] x2
    for (int i = tid * 4; i < 4096; i += 1024) {
        int r = i >> 5, c = i & 31;
        *(uint4*)&smw[W_W1H + r * 36 + c] = *(const uint4*)&g_w1h[lofs + i];
        *(uint4*)&smw[W_W1L + r * 36 + c] = *(const uint4*)&g_w1l[lofs + i];
    }
    __syncthreads();

    uint32_t sb = smem_u32(smw);
    int lr = (lane & 7) + ((lane >> 3) & 1) * 8;
    int lhalf = lane >> 4;
    int l8 = lane & 7, lg = lane >> 3;

    // ---- GEMM1: warp rows 32wm..+31, cols 32wn..+31 ----
    uint32_t a1H0 = sb + W_UH * 4 + (32 * wm + lr) * 144 + lhalf * 16;
    uint32_t a1H1 = a1H0 + 16 * 144;
    uint32_t b1H = sb + W_W1H * 4 + (32 * wn + l8) * 144 + lg * 16;
    uint32_t b1L = b1H + 4608 * 4;

    float c1[2][4][4];
#pragma unroll
    for (int sm = 0; sm < 2; sm++)
#pragma unroll
        for (int j = 0; j < 4; j++)
#pragma unroll
            for (int q = 0; q < 4; q++) c1[sm][j][q] = 0.f;

#pragma unroll
    for (int p = 0; p < 2; p++) {
        unsigned aA0[4], aB0[4], aA1[4], aB1[4];
        ldsm4(aA0[0], aA0[1], aA0[2], aA0[3], a1H0 + p * 64);
        ldsm4(aB0[0], aB0[1], aB0[2], aB0[3], a1H0 + p * 64 + 32);
        ldsm4(aA1[0], aA1[1], aA1[2], aA1[3], a1H1 + p * 64);
        ldsm4(aB1[0], aB1[1], aB1[2], aB1[3], a1H1 + p * 64 + 32);
#pragma unroll
        for (int j = 0; j < 4; j++) {
            unsigned h0, h1, h2, h3, l0, l1, l2, l3;
            ldsm4(h0, h1, h2, h3, b1H + j * 1152 + p * 64);
            ldsm4(l0, l1, l2, l3, b1L + j * 1152 + p * 64);
            mma16(c1[0][j], aA0[0], aA0[1], aA0[2], aA0[3], h0, h1);
            mma16(c1[0][j], aA0[0], aA0[1], aA0[2], aA0[3], l0, l1);
            mma16(c1[0][j], aB0[0], aB0[1], aB0[2], aB0[3], h2, h3);
            mma16(c1[0][j], aB0[0], aB0[1], aB0[2], aB0[3], l2, l3);
            mma16(c1[1][j], aA1[0], aA1[1], aA1[2], aA1[3], h0, h1);
            mma16(c1[1][j], aA1[0], aA1[1], aA1[2], aA1[3], l0, l1);
            mma16(c1[1][j], aB1[0], aB1[1], aB1[2], aB1[3], h2, h3);
            mma16(c1[1][j], aB1[0], aB1[1], aB1[2], aB1[3], l2, l3);
        }
    }

    // ---- epilogue 1: bias + LN(128) partial sums (4 rows/thread) ----
    int rA0 = 32 * wm + g;            // sm=0 rows: rA0, rA0+8
    int rA1 = rA0 + 16;               // sm=1 rows: rA1, rA1+8
    float ps[2][2], pq[2][2];
#pragma unroll
    for (int sm = 0; sm < 2; sm++) { ps[sm][0] = ps[sm][1] = pq[sm][0] = pq[sm][1] = 0.f; }
#pragma unroll
    for (int sm = 0; sm < 2; sm++)
#pragma unroll
    for (int j = 0; j < 4; j++) {
        int cb = 32 * wn + 8 * j + 2 * t4;
        float bx = smf[W_B1 + cb], by = smf[W_B1 + cb + 1];
        c1[sm][j][0] += bx; c1[sm][j][1] += by;
        c1[sm][j][2] += bx; c1[sm][j][3] += by;
        ps[sm][0] += c1[sm][j][0] + c1[sm][j][1];
        pq[sm][0] = fmaf(c1[sm][j][0], c1[sm][j][0], fmaf(c1[sm][j][1], c1[sm][j][1], pq[sm][0]));
        ps[sm][1] += c1[sm][j][2] + c1[sm][j][3];
        pq[sm][1] = fmaf(c1[sm][j][2], c1[sm][j][2], fmaf(c1[sm][j][3], c1[sm][j][3], pq[sm][1]));
    }
#pragma unroll
    for (int sm = 0; sm < 2; sm++)
#pragma unroll
    for (int hh = 0; hh < 2; hh++) {
        ps[sm][hh] += __shfl_xor_sync(0xffffffffu, ps[sm][hh], 1);
        ps[sm][hh] += __shfl_xor_sync(0xffffffffu, ps[sm][hh], 2);
        pq[sm][hh] += __shfl_xor_sync(0xffffffffu, pq[sm][hh], 1);
        pq[sm][hh] += __shfl_xor_sync(0xffffffffu, pq[sm][hh], 2);
    }
    if (t4 == 0) {
        smf[W_PSUM + wn * 64 + rA0]      = ps[0][0];  smf[W_PSQ + wn * 64 + rA0]      = pq[0][0];
        smf[W_PSUM + wn * 64 + rA0 + 8]  = ps[0][1];  smf[W_PSQ + wn * 64 + rA0 + 8]  = pq[0][1];
        smf[W_PSUM + wn * 64 + rA1]      = ps[1][0];  smf[W_PSQ + wn * 64 + rA1]      = pq[1][0];
        smf[W_PSUM + wn * 64 + rA1 + 8]  = ps[1][1];  smf[W_PSQ + wn * 64 + rA1 + 8]  = pq[1][1];
    }
    __syncthreads();   // GEMM1 reads done; W region free for W2

    for (int i = tid * 4; i < 4096; i += 1024) {
        int r = i >> 6, c = i & 63;
        *(uint4*)&smw[W_W2H + r * 68 + c] = *(const uint4*)&g_w2h[lofs + i];
        *(uint4*)&smw[W_W2L + r * 68 + c] = *(const uint4*)&g_w2l[lofs + i];
    }

    float mu[2][2], rs[2][2];
#pragma unroll
    for (int sm = 0; sm < 2; sm++)
#pragma unroll
    for (int hh = 0; hh < 2; hh++) {
        int r = 32 * wm + 16 * sm + 8 * hh + g;
        float S = smf[W_PSUM + r] + smf[W_PSUM + 64 + r]
                + smf[W_PSUM + 128 + r] + smf[W_PSUM + 192 + r];
        float Q = smf[W_PSQ + r] + smf[W_PSQ + 64 + r]
                + smf[W_PSQ + 128 + r] + smf[W_PSQ + 192 + r];
        float m = S * (1.f / 128.f);
        mu[sm][hh] = m;
        rs[sm][hh] = rsqrtf(Q * (1.f / 128.f) - m * m + 1e-5f);
    }

#pragma unroll
    for (int sm = 0; sm < 2; sm++)
#pragma unroll
    for (int j = 0; j < 4; j++) {
        int cb = 32 * wn + 8 * j + 2 * t4;
        float gx = smf[W_GAM + cb], gy = smf[W_GAM + cb + 1];
        float ex = smf[W_BET + cb], ey = smf[W_BET + cb + 1];
        float h0 = fmaxf((c1[sm][j][0] - mu[sm][0]) * rs[sm][0] * gx + ex, 0.f);
        float h1 = fmaxf((c1[sm][j][1] - mu[sm][0]) * rs[sm][0] * gy + ey, 0.f);
        float h2 = fmaxf((c1[sm][j][2] - mu[sm][1]) * rs[sm][1] * gx + ex, 0.f);
        float h3 = fmaxf((c1[sm][j][3] - mu[sm][1]) * rs[sm][1] * gy + ey, 0.f);
        int kp = cb >> 1;
        int r = 32 * wm + 16 * sm + g;
        smw[W_HH + r * 68 + kp] = pk_h2(h0, h1);
        smw[W_HH + (r + 8) * 68 + kp] = pk_h2(h2, h3);
    }
    __syncthreads();   // act + W2 both visible

    // ---- GEMM2: warp rows 32wm..+31, cols 16wn..+15 ----
    uint32_t a2H0 = sb + W_HH * 4 + (32 * wm + lr) * 272 + lhalf * 16;
    uint32_t a2H1 = a2H0 + 16 * 272;
    uint32_t b2H = sb + W_W2H * 4 + (16 * wn + l8) * 272 + lg * 16;
    uint32_t b2L = b2H + 4352 * 4;

    float c2[2][2][4];
#pragma unroll
    for (int sm = 0; sm < 2; sm++)
#pragma unroll
        for (int j = 0; j < 2; j++)
#pragma unroll
            for (int q = 0; q < 4; q++) c2[sm][j][q] = 0.f;

#pragma unroll
    for (int p = 0; p < 4; p++) {
        unsigned xA0[4], xB0[4], xA1[4], xB1[4];
        ldsm4(xA0[0], xA0[1], xA0[2], xA0[3], a2H0 + p * 64);
        ldsm4(xB0[0], xB0[1], xB0[2], xB0[3], a2H0 + p * 64 + 32);
        ldsm4(xA1[0], xA1[1], xA1[2], xA1[3], a2H1 + p * 64);
        ldsm4(xB1[0], xB1[1], xB1[2], xB1[3], a2H1 + p * 64 + 32);
#pragma unroll
        for (int j = 0; j < 2; j++) {
            unsigned h0, h1, h2, h3, l0, l1, l2, l3;
            ldsm4(h0, h1, h2, h3, b2H + j * 2176 + p * 64);
            ldsm4(l0, l1, l2, l3, b2L + j * 2176 + p * 64);
            mma16(c2[0][j], xA0[0], xA0[1], xA0[2], xA0[3], h0, h1);
            mma16(c2[0][j], xA0[0], xA0[1], xA0[2], xA0[3], l0, l1);
            mma16(c2[0][j], xB0[0], xB0[1], xB0[2], xB0[3], h2, h3);
            mma16(c2[0][j], xB0[0], xB0[1], xB0[2], xB0[3], l2, l3);
            mma16(c2[1][j], xA1[0], xA1[1], xA1[2], xA1[3], h0, h1);
            mma16(c2[1][j], xA1[0], xA1[1], xA1[2], xA1[3], l0, l1);
            mma16(c2[1][j], xB1[0], xB1[1], xB1[2], xB1[3], h2, h3);
            mme:;
            mma16(c2[1][j], xB1[0], xB1[1], xB1[2], xB1[3], l2, l3);
        }
    }

    // ---- epilogue 2: bias (+residual); store g_h unless FINAL ----
    float ps2[2][2], pq2[2][2];
#pragma unroll
    for (int sm = 0; sm < 2; sm++) { ps2[sm][0] = ps2[sm][1] = pq2[sm][0] = pq2[sm][1] = 0.f; }
#pragma unroll
    for (int sm = 0; sm < 2; sm++)
#pragma unroll
    for (int j = 0; j < 2; j++) {
        int cb = 16 * wn + 8 * j + 2 * t4;
        float bx = smf[W_B2 + cb], by = smf[W_B2 + cb + 1];
        int r = 32 * wm + 16 * sm + g;
        int nodeA = n0 + r, nodeB = nodeA + 8;
        float h00 = c2[sm][j][0] + bx, h01 = c2[sm][j][1] + by;
        float h10 = c2[sm][j][2] + bx, h11 = c2[sm][j][3] + by;
        if (nodeA < NN) {
            float* dst = g_h + nodeA * HH + cb;
            if (addm) { float2 pv = *(const float2*)dst; h00 += pv.x; h01 += pv.y; }
            if (wz != 2) *(float2*)dst = make_float2(h00, h01);
        }
        if (nodeB < NN) {
            float* dst = g_h + nodeB * HH + cb;
            if (addm) { float2 pv = *(const float2*)dst; h10 += pv.x; h11 += pv.y; }
            if (wz != 2) *(float2*)dst = make_float2(h10, h11);
        }
        c2[sm][j][0] = h00; c2[sm][j][1] = h01; c2[sm][j][2] = h10; c2[sm][j][3] = h11;
        ps2[sm][0] += h00 + h01; pq2[sm][0] = fmaf(h00, h00, fmaf(h01, h01, pq2[sm][0]));
        ps2[sm][1] += h10 + h11; pq2[sm][1] = fmaf(h10, h10, fmaf(h11, h11, pq2[sm][1]));
    }

    // ---- LN over 64 ch of final h (wz=1: z-write; wz=2: projection) ----
    if (wz) {
        float tlN = (wz == 1) ? __ldg(tN) * LOG2E : 1.f;
#pragma unroll
        for (int sm = 0; sm < 2; sm++)
#pragma unroll
        for (int hh = 0; hh < 2; hh++) {
            ps2[sm][hh] += __shfl_xor_sync(0xffffffffu, ps2[sm][hh], 1);
            ps2[sm][hh] += __shfl_xor_sync(0xffffffffu, ps2[sm][hh], 2);
            pq2[sm][hh] += __shfl_xor_sync(0xffffffffu, pq2[sm][hh], 1);
            pq2[sm][hh] += __shfl_xor_sync(0xffffffffu, pq2[sm][hh], 2);
        }
        if (t4 == 0) {
            smf[W_PSUM + wn * 64 + rA0]     = ps2[0][0];  smf[W_PSQ + wn * 64 + rA0]     = pq2[0][0];
            smf[W_PSUM + wn * 64 + rA0 + 8] = ps2[0][1];  smf[W_PSQ + wn * 64 + rA0 + 8] = pq2[0][1];
            smf[W_PSUM + wn * 64 + rA1]     = ps2[1][0];  smf[W_PSQ + wn * 64 + rA1]     = pq2[1][0];
            smf[W_PSUM + wn * 64 + rA1 + 8] = ps2[1][1];  smf[W_PSQ + wn * 64 + rA1 + 8] = pq2[1][1];
        }
        __syncthreads();   // also: GEMM2 done -> W region reusable as scratch
        float m2[2][2], v2[2][2];
#pragma unroll
        for (int sm = 0; sm < 2; sm++)
#pragma unroll
        for (int hh = 0; hh < 2; hh++) {
            int r = 32 * wm + 16 * sm + 8 * hh + g;
            float S = smf[W_PSUM + r] + smf[W_PSUM + 64 + r]
                    + smf[W_PSUM + 128 + r] + smf[W_PSUM + 192 + r];
            float Q = smf[W_PSQ + r] + smf[W_PSQ + 64 + r]
                    + smf[W_PSQ + 128 + r] + smf[W_PSQ + 192 + r];
            float m = S * (1.f / 64.f);
            m2[sm][hh] = m;
            v2[sm][hh] = rsqrtf(Q * (1.f / 64.f) - m * m + 1e-5f);
        }

        if (wz == 1) {
#pragma unroll
            for (int sm = 0; sm < 2; sm++)
#pragma unroll
            for (int j = 0; j < 2; j++) {
                int cb = 16 * wn + 8 * j + 2 * t4;
                float gx = __ldg(&lngN[cb]) * tlN, gy = __ldg(&lngN[cb + 1]) * tlN;
                float ex = __ldg(&lnbN[cb]) * tlN, ey = __ldg(&lnbN[cb + 1]) * tlN;
                int r = 32 * wm + 16 * sm + g;
                int nodeA = n0 + r, nodeB = nodeA + 8;
                if (nodeA < NN) {
                    float z0 = fmaxf((c2[sm][j][0] - m2[sm][0]) * v2[sm][0] * gx + ex, 0.f);
                    float z1 = fmaxf((c2[sm][j][1] - m2[sm][0]) * v2[sm][0] * gy + ey, 0.f);
                    *(float2*)(g_z + nodeA * HH + cb) = make_float2(z0, z1);
                }
                if (nodeB < NN) {
                    float z0 = fmaxf((c2[sm][j][2] - m2[sm][1]) * v2[sm][1] * gx + ex, 0.f);
                    float z1 = fmaxf((c2[sm][j][3] - m2[sm][1]) * v2[sm][1] * gy + ey, 0.f);
                    *(float2*)(g_z + nodeB * HH + cb) = make_float2(z0, z1);
                }
            }
        } else {
            float oo[2][2][3];
#pragma unroll
            for (int sm = 0; sm < 2; sm++)
#pragma unroll
                for (int hh = 0; hh < 2; hh++)
#pragma unroll
                    for (int k = 0; k < 3; k++) oo[sm][hh][k] = 0.f;
#pragma unroll
            for (int sm = 0; sm < 2; sm++)
#pragma unroll
            for (int j = 0; j < 2; j++) {
                int cb = 16 * wn + 8 * j + 2 * t4;
                float gx = __ldg(&lngN[cb]), gy = __ldg(&lngN[cb + 1]);
                float ex = __ldg(&lnbN[cb]), ey = __ldg(&lnbN[cb + 1]);
                float a0 = fmaxf((c2[sm][j][0] - m2[sm][0]) * v2[sm][0] * gx + ex, 0.f);
                float a1 = fmaxf((c2[sm][j][1] - m2[sm][0]) * v2[sm][0] * gy + ey, 0.f);
                float b0 = fmaxf((c2[sm][j][2] - m2[sm][1]) * v2[sm][1] * gx + ex, 0.f);
                float b1 = fmaxf((c2[sm][j][3] - m2[sm][1]) * v2[sm][1] * gy + ey, 0.f);
#pragma unroll
                for (int k = 0; k < 3; k++) {
                    float w0 = __ldg(&lwg[cb * 3 + k]);
                    float w1 = __ldg(&lwg[(cb + 1) * 3 + k]);
                    oo[sm][0][k] = fmaf(a0, w0, fmaf(a1, w1, oo[sm][0][k]));
                    oo[sm][1][k] = fmaf(b0, w0, fmaf(b1, w1, oo[sm][1][k]));
                }
            }
#pragma unroll
            for (int sm = 0; sm < 2; sm++)
#pragma unroll
            for (int hh = 0; hh < 2; hh++)
#pragma unroll
            for (int k = 0; k < 3; k++) {
                oo[sm][hh][k] += __shfl_xor_sync(0xffffffffu, oo[sm][hh][k], 1);
                oo[sm][hh][k] += __shfl_xor_sync(0xffffffffu, oo[sm][hh][k], 2);
            }
            if (t4 == 0) {
#pragma unroll
                for (int sm = 0; sm < 2; sm++)
#pragma unroll
                for (int hh = 0; hh < 2; hh++) {
                    int r = 32 * wm + 16 * sm + 8 * hh + g;
#pragma unroll
                    for (int k = 0; k < 3; k++)
                        smf[W_SCR + wn * 192 + r * 3 + k] = oo[sm][hh][k];
                }
            }
            __syncthreads();
            if (tid < 192) {
                int row = tid / 3, k = tid - row * 3;
                int node = n0 + row;
                if (node < NN) {
                    outp[node * 3 + k] = smf[W_SCR + row * 3 + k]
                                       + smf[W_SCR + 192 + row * 3 + k]
                                       + smf[W_SCR + 384 + row * 3 + k]
                                       + smf[W_SCR + 576 + row * 3 + k]
                                       + __ldg(&lbg[k]);
                }
            }
        }
    }
}

// ---------------- launch ----------------
extern "C" void kernel_launch(void* const* d_in, const int* in_sizes, int n_in,
                              void* d_out, int out_size) {
    const float* x    = (const float*)d_in[0];
    const int*   ei   = (const int*)  d_in[1];
    const float* encW = (const float*)d_in[2];
    const float* encb = (const float*)d_in[3];
    const float* t    = (const float*)d_in[4];
    const float* W1   = (const float*)d_in[5];
    const float* b1   = (const float*)d_in[6];
    const float* mg   = (const float*)d_in[7];
    const float* mb   = (const float*)d_in[8];
    const float* W2   = (const float*)d_in[9];
    const float* b2   = (const float*)d_in[10];
    const float* lng  = (const float*)d_in[11];
    const float* lnb  = (const float*)d_in[12];
    const float* lw   = (const float*)d_in[13];
    const float* lb   = (const float*)d_in[14];
    float* out = (float*)d_out;

    cudaFuncSetAttribute(k_mlp, cudaFuncAttributeMaxDynamicSharedMemorySize, SMEM_MLP_BYTES);

    const int WARP_BLOCKS = (NN * 32 + 255) / 256;
    const int MLP_BLOCKS  = (NN + 63) / 64;
    const int EH_BLOCKS   = (NN * 16 + 255) / 256;
    const int SS_BLOCKS   = 1172;

    k_enc_hist<<<EH_BLOCKS, 256>>>(x, encW, encb, ei, W1, W2, t);
    k_scan_scatter<<<SS_BLOCKS, 256>>>(ei);

    // layer 0 (launch 3 = mlp -> profiled slot)
    k_agg<<<WARP_BLOCKS, 256>>>(t + 0);
    k_mlp<<<MLP_BLOCKS, 256, SMEM_MLP_BYTES>>>(b1, mg, mb, b2,
                                               lng + HH, lnb + HH, t + 1,
                                               lw, lb, out, 0, 0, 1);

    k_agg<<<WARP_BLOCKS, 256>>>(t + 1);
    k_mlp<<<MLP_BLOCKS, 256, SMEM_MLP_BYTES>>>(b1 + H2, mg + H2, mb + H2, b2 + HH,
                                               lng + 2 * HH, lnb + 2 * HH, t + 2,
                                               lw, lb, out, 1, 1, 1);
    k_agg<<<WARP_BLOCKS, 256>>>(t + 2);
    k_mlp<<<MLP_BLOCKS, 256, SMEM_MLP_BYTES>>>(b1 + 2 * H2, mg + 2 * H2, mb + 2 * H2,
                                               b2 + 2 * HH, lng, lnb, t,
                                               lw, lb, out, 2, 1, 2);
}

// round 17
// speedup vs baseline: 1.3118x; 1.0688x over previous
#include <cuda_runtime.h>
#include <cuda_fp16.h>
#include <cstdint>

#define NN 100000
#define NE 1200000
#define HH 64
#define H2 128
#define NB_SCAN 98
#define LOG2E 1.44269504f

// ---------------- device scratch (no allocations allowed) ----------------
// g_z holds layer input PRE-SCALED by t_layer * log2(e)
__device__ float g_z[NN * HH];
__device__ float g_h[NN * HH];      // residual stream (fp32, unscaled)
__device__ unsigned g_uh[NN * 32];  // MLP input, f16x2 k-pair words
__device__ int   g_rowptr[NN + 1];
__device__ int   g_wp[NN];          // zeroed by previous replay's last k_mlp
__device__ int   g_srcs[NE];        // src ids PRE-SCALED by 64
__device__ int   g_sval[128];
__device__ int   g_sincl[128];
__device__ int   g_sflag[128];      // tail-zeroed by last k_mlp
__device__ int   g_cnt2, g_done2;   // scan->scatter handoff (tail-zeroed)
// fp16 weights (single precision), [n][kp] rows (k contiguous):
__device__ unsigned g_w1h[3 * 4096];
__device__ unsigned g_w2h[3 * 4096];

// ---------------- helpers ----------------
__device__ __forceinline__ float ex2(float x) {
    float r; asm("ex2.approx.f32 %0, %1;" : "=f"(r) : "f"(x)); return r;
}
__device__ __forceinline__ unsigned pk_h2(float xe, float xo) {
    __half2 h = __floats2half2_rn(xe, xo);
    return *reinterpret_cast<unsigned*>(&h);
}
__device__ __forceinline__ uint32_t smem_u32(const void* p) {
    uint32_t a;
    asm("{ .reg .u64 t; cvta.to.shared.u64 t, %1; cvt.u32.u64 %0, t; }" : "=r"(a) : "l"(p));
    return a;
}
__device__ __forceinline__ void mma16(float* c, unsigned a0, unsigned a1,
                                      unsigned a2, unsigned a3,
                                      unsigned b0, unsigned b1) {
    asm("mma.sync.aligned.m16n8k16.row.col.f32.f16.f16.f32 "
        "{%0,%1,%2,%3}, {%4,%5,%6,%7}, {%8,%9}, {%0,%1,%2,%3};"
        : "+f"(c[0]), "+f"(c[1]), "+f"(c[2]), "+f"(c[3])
        : "r"(a0), "r"(a1), "r"(a2), "r"(a3), "r"(b0), "r"(b1));
}
__device__ __forceinline__ void ldsm4(unsigned& r0, unsigned& r1, unsigned& r2,
                                      unsigned& r3, uint32_t addr) {
    asm volatile("ldmatrix.sync.aligned.m8n8.x4.shared.b16 {%0,%1,%2,%3}, [%4];"
                 : "=r"(r0), "=r"(r1), "=r"(r2), "=r"(r3) : "r"(addr));
}

// ------ launch 0: encoder (scaled by t0*log2e) + histogram + W pack -------
__global__ void k_enc_hist(const float* __restrict__ x, const float* __restrict__ W,
                           const float* __restrict__ b, const int* __restrict__ ei,
                           const float* __restrict__ W1g, const float* __restrict__ W2g,
                           const float* __restrict__ t) {
    int idx = blockIdx.x * blockDim.x + threadIdx.x;
    if (idx == 0) g_rowptr[NN] = NE;
    if (idx < NE) atomicAdd(&g_wp[ei[NE + idx]], 1);
    if (idx < NN * 16) {
        float tl0 = __ldg(t) * LOG2E;
        int n = idx >> 4, c = (idx & 15) * 4;
        float x0 = x[n * 3], x1 = x[n * 3 + 1], x2 = x[n * 3 + 2];
        float4 w0 = *(const float4*)&W[c];
        float4 w1 = *(const float4*)&W[HH + c];
        float4 w2 = *(const float4*)&W[2 * HH + c];
        float4 bb = *(const float4*)&b[c];
        float4 o;
        o.x = (x0 * w0.x + x1 * w1.x + x2 * w2.x + bb.x) * tl0;
        o.y = (x0 * w0.y + x1 * w1.y + x2 * w2.y + bb.y) * tl0;
        o.z = (x0 * w0.z + x1 * w1.z + x2 * w2.z + bb.z) * tl0;
        o.w = (x0 * w0.w + x1 * w1.w + x2 * w2.w + bb.w) * tl0;
        *(float4*)&g_z[n * HH + c] = o;
    }
    if (idx < 3 * 4096) {   // W1^T: idx = l*4096 + n*32 + kp
        int l = idx >> 12, r = idx & 4095, n = r >> 5, kp = r & 31;
        const float* Wl = W1g + l * (HH * H2);
        g_w1h[idx] = pk_h2(Wl[(2 * kp) * H2 + n], Wl[(2 * kp + 1) * H2 + n]);
    }
    if (idx < 3 * 4096) {   // W2^T: idx = l*4096 + n*64 + kp
        int l = idx >> 12, r = idx & 4095, n = r >> 6, kp = r & 63;
        const float* Wl = W2g + l * (H2 * HH);
        g_w2h[idx] = pk_h2(Wl[(2 * kp) * HH + n], Wl[(2 * kp + 1) * HH + n]);
    }
}

// -------- launch 1: fused scan (decoupled lookback) + scatter --------------
__global__ __launch_bounds__(256, 8) void k_scan_scatter(const int* __restrict__ ei) {
    __shared__ int wsum[8];
    __shared__ int s_excl;
    int tid = threadIdx.x, b = blockIdx.x;
    int lane = tid & 31, wid = tid >> 5;

    if (b < NB_SCAN) {
        int i0 = b * 1024 + tid * 4;
        int a0 = (i0     < NN) ? g_wp[i0]     : 0;
        int a1 = (i0 + 1 < NN) ? g_wp[i0 + 1] : 0;
        int a2 = (i0 + 2 < NN) ? g_wp[i0 + 2] : 0;
        int a3 = (i0 + 3 < NN) ? g_wp[i0 + 3] : 0;
        int ts = a0 + a1 + a2 + a3;
        int v = ts;
#pragma unroll
        for (int d = 1; d < 32; d <<= 1) {
            int u = __shfl_up_sync(0xffffffffu, v, d);
            if (lane >= d) v += u;
        }
        if (lane == 31) wsum[wid] = v;
        __syncthreads();
        if (wid == 0 && lane < 8) {
            int w = wsum[lane];
#pragma unroll
            for (int d = 1; d < 8; d <<= 1) {
                int u = __shfl_up_sync(0xffu, w, d);
                if (lane >= d) w += u;
            }
            wsum[lane] = w;
        }
        __syncthreads();
        int tex = (v - ts) + (wid ? wsum[wid - 1] : 0);
        int bsum = wsum[7];
        if (tid == 0) {
            if (b == 0) {
                g_sincl[0] = bsum; __threadfence(); g_sflag[0] = 2;
                s_excl = 0;
            } else {
                g_sval[b] = bsum; __threadfence(); g_sflag[b] = 1;
                int excl = 0, j = b - 1;
                while (true) {
                    int f;
                    do { f = ((volatile int*)g_sflag)[j]; } while (f == 0);
                    __threadfence();
                    if (f == 2) { excl += ((volatile int*)g_sincl)[j]; break; }
                    excl += ((volatile int*)g_sval)[j]; j--;
                }
                g_sincl[b] = excl + bsum; __threadfence(); g_sflag[b] = 2;
                s_excl = excl;
            }
        }
        __syncthreads();
        int base = s_excl + tex;
        if (i0     < NN) { g_rowptr[i0]     = base;                g_wp[i0]     = base; }
        if (i0 + 1 < NN) { g_rowptr[i0 + 1] = base + a0;           g_wp[i0 + 1] = base + a0; }
        if (i0 + 2 < NN) { g_rowptr[i0 + 2] = base + a0 + a1;      g_wp[i0 + 2] = base + a0 + a1; }
        if (i0 + 3 < NN) { g_rowptr[i0 + 3] = base + a0 + a1 + a2; g_wp[i0 + 3] = base + a0 + a1 + a2; }
        __syncthreads();
        if (tid == 0) {
            __threadfence();
            int p = atomicAdd(&g_cnt2, 1);
            if (p == NB_SCAN - 1) atomicExch(&g_done2, 1);
        }
    }
    if (tid == 0) {
        while (atomicAdd(&g_done2, 0) == 0) { }
    }
    __syncthreads();
    for (int e = b * 256 + tid; e < NE; e += gridDim.x * 256) {
        int d = ei[NE + e];
        int p = atomicAdd(&g_wp[d], 1);
        g_srcs[p] = ei[e] << 6;   // src * HH
    }
}

// ------- single-pass softmax aggregation; g_z pre-scaled by t*log2e -------
__global__ __launch_bounds__(256, 8) void k_agg(const float* __restrict__ tptr) {
    int gw = (blockIdx.x * blockDim.x + threadIdx.x) >> 5;
    if (gw >= NN) return;
    int lane = threadIdx.x & 31;
    int beg = g_rowptr[gw], end = g_rowptr[gw + 1];
    float tl2 = __ldg(tptr) * LOG2E;
    float inv_tl2 = __fdividef(1.f, tl2);
    const float* zp = g_z + 2 * lane;

    float z0 = 0.f, z1 = 0.f, s0 = 0.f, s1 = 0.f;
    for (int base = beg; base < end; base += 32) {
        int nn = end - base; if (nn > 32) nn = 32;
        int sid = (base + lane < end) ? __ldg(&g_srcs[base + lane]) : 0;
#pragma unroll 4
        for (int j = 0; j < nn; j++) {
            int s = __shfl_sync(0xffffffffu, sid, j);
            float2 v = *(const float2*)(zp + s);
            float m0 = fmaxf(v.x, 0.f), m1 = fmaxf(v.y, 0.f);
            float w0 = ex2(m0);
            float w1 = ex2(m1);
            z0 += w0; z1 += w1;
            s0 = fmaf(m0, w0, s0);
            s1 = fmaf(m1, w1, s1);
        }
    }
    float2 zz = *(const float2*)(g_z + gw * HH + 2 * lane);
    float ox, oy;
    if (end > beg) {
        ox = (zz.x + __fdividef(s0, z0)) * inv_tl2 + 1e-7f;
        oy = (zz.y + __fdividef(s1, z1)) * inv_tl2 + 1e-7f;
    } else {
        ox = zz.x * inv_tl2;
        oy = zz.y * inv_tl2;
    }
    g_uh[gw * 32 + lane] = pk_h2(ox, oy);
}

// ---- fused MLP: single-fp16 mma.sync + ldmatrix; warp tile M32xN32 ----
// wz=0: plain; wz=1: write NEXT-layer z pre-scaled; wz=2: FINAL (LN0+proj->out)
#define W_PSUM 0              // [4][64]
#define W_PSQ  256            // [4][64]
#define W_B1   512
#define W_GAM  640
#define W_BET  768
#define W_B2   896
#define W_A    960            // sUH [64][36] -> sHH [64][68] (4352 words)
#define W_UH   (W_A)
#define W_HH   (W_A)
#define W_W    (W_A + 4352)   // 5312
#define W_W1H  (W_W)          // [128][36] = 4608
#define W_W2H  (W_W)          // [64][68] = 4352
#define W_SCR  (W_W)          // final-projection scratch [4][64][3]
#define SMEM_MLP_WORDS 9920
#define SMEM_MLP_BYTES (SMEM_MLP_WORDS * 4)

extern __shared__ unsigned smw[];
__global__ __launch_bounds__(256, 3) void k_mlp(
    const float* __restrict__ b1g, const float* __restrict__ gamg,
    const float* __restrict__ betg, const float* __restrict__ b2g,
    const float* __restrict__ lngN, const float* __restrict__ lnbN,
    const float* __restrict__ tN,
    const float* __restrict__ lwg, const float* __restrict__ lbg,
    float* __restrict__ outp,
    int layer, int addm, int wz)
{
    float* smf = (float*)smw;
    int tid = threadIdx.x, w = tid >> 5, lane = tid & 31;
    int g = lane >> 2, t4 = lane & 3;
    int wm = w & 1, wn = w >> 1;          // M32 x N32 warp tile
    int n0 = blockIdx.x * 64;
    int lofs = layer * 4096;

    if (wz == 2) {   // scratch re-zero for next replay
        int n = n0 + tid;
        if (tid < 64 && n < NN) g_wp[n] = 0;
        if (blockIdx.x == 0) {
            if (tid >= 64 && tid < 192) g_sflag[tid - 64] = 0;
            if (tid == 192) { g_cnt2 = 0; g_done2 = 0; }
        }
    }
    if (tid < 128) {
        smf[W_B1 + tid]  = b1g[tid];
        smf[W_GAM + tid] = gamg[tid];
        smf[W_BET + tid] = betg[tid];
        if (tid < 64) smf[W_B2 + tid] = b2g[tid];
    }
    // U (single fp16) [64][36]
    for (int i = tid * 4; i < 2048; i += 1024) {
        int r = i >> 5, c = i & 31;
        int node = n0 + r;
        uint4 hv = make_uint4(0, 0, 0, 0);
        if (node < NN) hv = *(const uint4*)&g_uh[node * 32 + c];
        *(uint4*)&smw[W_UH + r * 36 + c] = hv;
    }
    // W1 [128][36]
    for (int i = tid * 4; i < 4096; i += 1024) {
        int r = i >> 5, c = i & 31;
        *(uint4*)&smw[W_W1H + r * 36 + c] = *(const uint4*)&g_w1h[lofs + i];
    }
    __syncthreads();

    uint32_t sb = smem_u32(smw);
    int lr = (lane & 7) + ((lane >> 3) & 1) * 8;
    int lhalf = lane >> 4;
    int l8 = lane & 7, lg = lane >> 3;

    // ---- GEMM1: warp rows 32wm..+31, cols 32wn..+31 ----
    uint32_t a1H0 = sb + W_UH * 4 + (32 * wm + lr) * 144 + lhalf * 16;
    uint32_t a1H1 = a1H0 + 16 * 144;
    uint32_t b1H = sb + W_W1H * 4 + (32 * wn + l8) * 144 + lg * 16;

    float c1[2][4][4];
#pragma unroll
    for (int sm = 0; sm < 2; sm++)
#pragma unroll
        for (int j = 0; j < 4; j++)
#pragma unroll
            for (int q = 0; q < 4; q++) c1[sm][j][q] = 0.f;

#pragma unroll
    for (int p = 0; p < 2; p++) {
        unsigned aA0[4], aB0[4], aA1[4], aB1[4];
        ldsm4(aA0[0], aA0[1], aA0[2], aA0[3], a1H0 + p * 64);
        ldsm4(aB0[0], aB0[1], aB0[2], aB0[3], a1H0 + p * 64 + 32);
        ldsm4(aA1[0], aA1[1], aA1[2], aA1[3], a1H1 + p * 64);
        ldsm4(aB1[0], aB1[1], aB1[2], aB1[3], a1H1 + p * 64 + 32);
#pragma unroll
        for (int j = 0; j < 4; j++) {
            unsigned h0, h1, h2, h3;
            ldsm4(h0, h1, h2, h3, b1H + j * 1152 + p * 64);
            mma16(c1[0][j], aA0[0], aA0[1], aA0[2], aA0[3], h0, h1);
            mma16(c1[0][j], aB0[0], aB0[1], aB0[2], aB0[3], h2, h3);
            mma16(c1[1][j], aA1[0], aA1[1], aA1[2], aA1[3], h0, h1);
            mma16(c1[1][j], aB1[0], aB1[1], aB1[2], aB1[3], h2, h3);
        }
    }

    // ---- epilogue 1: bias + LN(128) partial sums (4 rows/thread) ----
    int rA0 = 32 * wm + g;
    int rA1 = rA0 + 16;
    float ps[2][2], pq[2][2];
#pragma unroll
    for (int sm = 0; sm < 2; sm++) { ps[sm][0] = ps[sm][1] = pq[sm][0] = pq[sm][1] = 0.f; }
#pragma unroll
    for (int sm = 0; sm < 2; sm++)
#pragma unroll
    for (int j = 0; j < 4; j++) {
        int cb = 32 * wn + 8 * j + 2 * t4;
        float bx = smf[W_B1 + cb], by = smf[W_B1 + cb + 1];
        c1[sm][j][0] += bx; c1[sm][j][1] += by;
        c1[sm][j][2] += bx; c1[sm][j][3] += by;
        ps[sm][0] += c1[sm][j][0] + c1[sm][j][1];
        pq[sm][0] = fmaf(c1[sm][j][0], c1[sm][j][0], fmaf(c1[sm][j][1], c1[sm][j][1], pq[sm][0]));
        ps[sm][1] += c1[sm][j][2] + c1[sm][j][3];
        pq[sm][1] = fmaf(c1[sm][j][2], c1[sm][j][2], fmaf(c1[sm][j][3], c1[sm][j][3], pq[sm][1]));
    }
#pragma unroll
    for (int sm = 0; sm < 2; sm++)
#pragma unroll
    for (int hh = 0; hh < 2; hh++) {
        ps[sm][hh] += __shfl_xor_sync(0xffffffffu, ps[sm][hh], 1);
        ps[sm][hh] += __shfl_xor_sync(0xffffffffu, ps[sm][hh], 2);
        pq[sm][hh] += __shfl_xor_sync(0xffffffffu, pq[sm][hh], 1);
        pq[sm][hh] += __shfl_xor_sync(0xffffffffu, pq[sm][hh], 2);
    }
    if (t4 == 0) {
        smf[W_PSUM + wn * 64 + rA0]      = ps[0][0];  smf[W_PSQ + wn * 64 + rA0]      = pq[0][0];
        smf[W_PSUM + wn * 64 + rA0 + 8]  = ps[0][1];  smf[W_PSQ + wn * 64 + rA0 + 8]  = pq[0][1];
        smf[W_PSUM + wn * 64 + rA1]      = ps[1][0];  smf[W_PSQ + wn * 64 + rA1]      = pq[1][0];
        smf[W_PSUM + wn * 64 + rA1 + 8]  = ps[1][1];  smf[W_PSQ + wn * 64 + rA1 + 8]  = pq[1][1];
    }
    __syncthreads();   // GEMM1 reads done; W region free for W2

    for (int i = tid * 4; i < 4096; i += 1024) {
        int r = i >> 6, c = i & 63;
        *(uint4*)&smw[W_W2H + r * 68 + c] = *(const uint4*)&g_w2h[lofs + i];
    }

    float mu[2][2], rs[2][2];
#pragma unroll
    for (int sm = 0; sm < 2; sm++)
#pragma unroll
    for (int hh = 0; hh < 2; hh++) {
        int r = 32 * wm + 16 * sm + 8 * hh + g;
        float S = smf[W_PSUM + r] + smf[W_PSUM + 64 + r]
                + smf[W_PSUM + 128 + r] + smf[W_PSUM + 192 + r];
        float Q = smf[W_PSQ + r] + smf[W_PSQ + 64 + r]
                + smf[W_PSQ + 128 + r] + smf[W_PSQ + 192 + r];
        float m = S * (1.f / 128.f);
        mu[sm][hh] = m;
        rs[sm][hh] = rsqrtf(Q * (1.f / 128.f) - m * m + 1e-5f);
    }

#pragma unroll
    for (int sm = 0; sm < 2; sm++)
#pragma unroll
    for (int j = 0; j < 4; j++) {
        int cb = 32 * wn + 8 * j + 2 * t4;
        float gx = smf[W_GAM + cb], gy = smf[W_GAM + cb + 1];
        float ex = smf[W_BET + cb], ey = smf[W_BET + cb + 1];
        float h0 = fmaxf((c1[sm][j][0] - mu[sm][0]) * rs[sm][0] * gx + ex, 0.f);
        float h1 = fmaxf((c1[sm][j][1] - mu[sm][0]) * rs[sm][0] * gy + ey, 0.f);
        float h2 = fmaxf((c1[sm][j][2] - mu[sm][1]) * rs[sm][1] * gx + ex, 0.f);
        float h3 = fmaxf((c1[sm][j][3] - mu[sm][1]) * rs[sm][1] * gy + ey, 0.f);
        int kp = cb >> 1;
        int r = 32 * wm + 16 * sm + g;
        smw[W_HH + r * 68 + kp] = pk_h2(h0, h1);
        smw[W_HH + (r + 8) * 68 + kp] = pk_h2(h2, h3);
    }
    __syncthreads();   // act + W2 both visible

    // ---- GEMM2: warp rows 32wm..+31, cols 16wn..+15 ----
    uint32_t a2H0 = sb + W_HH * 4 + (32 * wm + lr) * 272 + lhalf * 16;
    uint32_t a2H1 = a2H0 + 16 * 272;
    uint32_t b2H = sb + W_W2H * 4 + (16 * wn + l8) * 272 + lg * 16;

    float c2[2][2][4];
#pragma unroll
    for (int sm = 0; sm < 2; sm++)
#pragma unroll
        for (int j = 0; j < 2; j++)
#pragma unroll
            for (int q = 0; q < 4; q++) c2[sm][j][q] = 0.f;

#pragma unroll
    for (int p = 0; p < 4; p++) {
        unsigned xA0[4], xB0[4], xA1[4], xB1[4];
        ldsm4(xA0[0], xA0[1], xA0[2], xA0[3], a2H0 + p * 64);
        ldsm4(xB0[0], xB0[1], xB0[2], xB0[3], a2H0 + p * 64 + 32);
        ldsm4(xA1[0], xA1[1], xA1[2], xA1[3], a2H1 + p * 64);
        ldsm4(xB1[0], xB1[1], xB1[2], xB1[3], a2H1 + p * 64 + 32);
#pragma unroll
        for (int j = 0; j < 2; j++) {
            unsigned h0, h1, h2, h3;
            ldsm4(h0, h1, h2, h3, b2H + j * 2176 + p * 64);
            mma16(c2[0][j], xA0[0], xA0[1], xA0[2], xA0[3], h0, h1);
            mma16(c2[0][j], xB0[0], xB0[1], xB0[2], xB0[3], h2, h3);
            mma16(c2[1][j], xA1[0], xA1[1], xA1[2], xA1[3], h0, h1);
            mma16(c2[1][j], xB1[0], xB1[1], xB1[2], xB1[3], h2, h3);
        }
    }

    // ---- epilogue 2: bias (+residual); store g_h unless FINAL ----
    float ps2[2][2], pq2[2][2];
#pragma unroll
    for (int sm = 0; sm < 2; sm++) { ps2[sm][0] = ps2[sm][1] = pq2[sm][0] = pq2[sm][1] = 0.f; }
#pragma unroll
    for (int sm = 0; sm < 2; sm++)
#pragma unroll
    for (int j = 0; j < 2; j++) {
        int cb = 16 * wn + 8 * j + 2 * t4;
        float bx = smf[W_B2 + cb], by = smf[W_B2 + cb + 1];
        int r = 32 * wm + 16 * sm + g;
        int nodeA = n0 + r, nodeB = nodeA + 8;
        float h00 = c2[sm][j][0] + bx, h01 = c2[sm][j][1] + by;
        float h10 = c2[sm][j][2] + bx, h11 = c2[sm][j][3] + by;
        if (nodeA < NN) {
            float* dst = g_h + nodeA * HH + cb;
            if (addm) { float2 pv = *(const float2*)dst; h00 += pv.x; h01 += pv.y; }
            if (wz != 2) *(float2*)dst = make_float2(h00, h01);
        }
        if (nodeB < NN) {
            float* dst = g_h + nodeB * HH + cb;
            if (addm) { float2 pv = *(const float2*)dst; h10 += pv.x; h11 += pv.y; }
            if (wz != 2) *(float2*)dst = make_float2(h10, h11);
        }
        c2[sm][j][0] = h00; c2[sm][j][1] = h01; c2[sm][j][2] = h10; c2[sm][j][3] = h11;
        ps2[sm][0] += h00 + h01; pq2[sm][0] = fmaf(h00, h00, fmaf(h01, h01, pq2[sm][0]));
        ps2[sm][1] += h10 + h11; pq2[sm][1] = fmaf(h10, h10, fmaf(h11, h11, pq2[sm][1]));
    }

    // ---- LN over 64 ch of final h (wz=1: z-write; wz=2: projection) ----
    if (wz) {
        float tlN = (wz == 1) ? __ldg(tN) * LOG2E : 1.f;
#pragma unroll
        for (int sm = 0; sm < 2; sm++)
#pragma unroll
        for (int hh = 0; hh < 2; hh++) {
            ps2[sm][hh] += __shfl_xor_sync(0xffffffffu, ps2[sm][hh], 1);
            ps2[sm][hh] += __shfl_xor_sync(0xffffffffu, ps2[sm][hh], 2);
            pq2[sm][hh] += __shfl_xor_sync(0xffffffffu, pq2[sm][hh], 1);
            pq2[sm][hh] += __shfl_xor_sync(0xffffffffu, pq2[sm][hh], 2);
        }
        if (t4 == 0) {
            smf[W_PSUM + wn * 64 + rA0]     = ps2[0][0];  smf[W_PSQ + wn * 64 + rA0]     = pq2[0][0];
            smf[W_PSUM + wn * 64 + rA0 + 8] = ps2[0][1];  smf[W_PSQ + wn * 64 + rA0 + 8] = pq2[0][1];
            smf[W_PSUM + wn * 64 + rA1]     = ps2[1][0];  smf[W_PSQ + wn * 64 + rA1]     = pq2[1][0];
            smf[W_PSUM + wn * 64 + rA1 + 8] = ps2[1][1];  smf[W_PSQ + wn * 64 + rA1 + 8] = pq2[1][1];
        }
        __syncthreads();   // also: GEMM2 done -> W region reusable as scratch
        float m2[2][2], v2[2][2];
#pragma unroll
        for (int sm = 0; sm < 2; sm++)
#pragma unroll
        for (int hh = 0; hh < 2; hh++) {
            int r = 32 * wm + 16 * sm + 8 * hh + g;
            float S = smf[W_PSUM + r] + smf[W_PSUM + 64 + r]
                    + smf[W_PSUM + 128 + r] + smf[W_PSUM + 192 + r];
            float Q = smf[W_PSQ + r] + smf[W_PSQ + 64 + r]
                    + smf[W_PSQ + 128 + r] + smf[W_PSQ + 192 + r];
            float m = S * (1.f / 64.f);
            m2[sm][hh] = m;
            v2[sm][hh] = rsqrtf(Q * (1.f / 64.f) - m * m + 1e-5f);
        }

        if (wz == 1) {
#pragma unroll
            for (int sm = 0; sm < 2; sm++)
#pragma unroll
            for (int j = 0; j < 2; j++) {
                int cb = 16 * wn + 8 * j + 2 * t4;
                float gx = __ldg(&lngN[cb]) * tlN, gy = __ldg(&lngN[cb + 1]) * tlN;
                float ex = __ldg(&lnbN[cb]) * tlN, ey = __ldg(&lnbN[cb + 1]) * tlN;
                int r = 32 * wm + 16 * sm + g;
                int nodeA = n0 + r, nodeB = nodeA + 8;
                if (nodeA < NN) {
                    float z0 = fmaxf((c2[sm][j][0] - m2[sm][0]) * v2[sm][0] * gx + ex, 0.f);
                    float z1 = fmaxf((c2[sm][j][1] - m2[sm][0]) * v2[sm][0] * gy + ey, 0.f);
                    *(float2*)(g_z + nodeA * HH + cb) = make_float2(z0, z1);
                }
                if (nodeB < NN) {
                    float z0 = fmaxf((c2[sm][j][2] - m2[sm][1]) * v2[sm][1] * gx + ex, 0.f);
                    float z1 = fmaxf((c2[sm][j][3] - m2[sm][1]) * v2[sm][1] * gy + ey, 0.f);
                    *(float2*)(g_z + nodeB * HH + cb) = make_float2(z0, z1);
                }
            }
        } else {
            float oo[2][2][3];
#pragma unroll
            for (int sm = 0; sm < 2; sm++)
#pragma unroll
                for (int hh = 0; hh < 2; hh++)
#pragma unroll
                    for (int k = 0; k < 3; k++) oo[sm][hh][k] = 0.f;
#pragma unroll
            for (int sm = 0; sm < 2; sm++)
#pragma unroll
            for (int j = 0; j < 2; j++) {
                int cb = 16 * wn + 8 * j + 2 * t4;
                float gx = __ldg(&lngN[cb]), gy = __ldg(&lngN[cb + 1]);
                float ex = __ldg(&lnbN[cb]), ey = __ldg(&lnbN[cb + 1]);
                float a0 = fmaxf((c2[sm][j][0] - m2[sm][0]) * v2[sm][0] * gx + ex, 0.f);
                float a1 = fmaxf((c2[sm][j][1] - m2[sm][0]) * v2[sm][0] * gy + ey, 0.f);
                float b0 = fmaxf((c2[sm][j][2] - m2[sm][1]) * v2[sm][1] * gx + ex, 0.f);
                float b1 = fmaxf((c2[sm][j][3] - m2[sm][1]) * v2[sm][1] * gy + ey, 0.f);
#pragma unroll
                for (int k = 0; k < 3; k++) {
                    float w0 = __ldg(&lwg[cb * 3 + k]);
                    float w1 = __ldg(&lwg[(cb + 1) * 3 + k]);
                    oo[sm][0][k] = fmaf(a0, w0, fmaf(a1, w1, oo[sm][0][k]));
                    oo[sm][1][k] = fmaf(b0, w0, fmaf(b1, w1, oo[sm][1][k]));
                }
            }
#pragma unroll
            for (int sm = 0; sm < 2; sm++)
#pragma unroll
            for (int hh = 0; hh < 2; hh++)
#pragma unroll
            for (int k = 0; k < 3; k++) {
                oo[sm][hh][k] += __shfl_xor_sync(0xffffffffu, oo[sm][hh][k], 1);
                oo[sm][hh][k] += __shfl_xor_sync(0xffffffffu, oo[sm][hh][k], 2);
            }
            if (t4 == 0) {
#pragma unroll
                for (int sm = 0; sm < 2; sm++)
#pragma unroll
                for (int hh = 0; hh < 2; hh++) {
                    int r = 32 * wm + 16 * sm + 8 * hh + g;
#pragma unroll
                    for (int k = 0; k < 3; k++)
                        smf[W_SCR + wn * 192 + r * 3 + k] = oo[sm][hh][k];
                }
            }
            __syncthreads();
            if (tid < 192) {
                int row = tid / 3, k = tid - row * 3;
                int node = n0 + row;
                if (node < NN) {
                    outp[node * 3 + k] = smf[W_SCR + row * 3 + k]
                                       + smf[W_SCR + 192 + row * 3 + k]
                                       + smf[W_SCR + 384 + row * 3 + k]
                                       + smf[W_SCR + 576 + row * 3 + k]
                                       + __ldg(&lbg[k]);
                }
            }
        }
    }
}

// ---------------- launch ----------------
extern "C" void kernel_launch(void* const* d_in, const int* in_sizes, int n_in,
                              void* d_out, int out_size) {
    const float* x    = (const float*)d_in[0];
    const int*   ei   = (const int*)  d_in[1];
    const float* encW = (const float*)d_in[2];
    const float* encb = (const float*)d_in[3];
    const float* t    = (const float*)d_in[4];
    const float* W1   = (const float*)d_in[5];
    const float* b1   = (const float*)d_in[6];
    const float* mg   = (const float*)d_in[7];
    const float* mb   = (const float*)d_in[8];
    const float* W2   = (const float*)d_in[9];
    const float* b2   = (const float*)d_in[10];
    const float* lng  = (const float*)d_in[11];
    const float* lnb  = (const float*)d_in[12];
    const float* lw   = (const float*)d_in[13];
    const float* lb   = (const float*)d_in[14];
    float* out = (float*)d_out;

    cudaFuncSetAttribute(k_mlp, cudaFuncAttributeMaxDynamicSharedMemorySize, SMEM_MLP_BYTES);

    const int WARP_BLOCKS = (NN * 32 + 255) / 256;
    const int MLP_BLOCKS  = (NN + 63) / 64;
    const int EH_BLOCKS   = (NN * 16 + 255) / 256;
    const int SS_BLOCKS   = 1172;

    k_enc_hist<<<EH_BLOCKS, 256>>>(x, encW, encb, ei, W1, W2, t);
    k_scan_scatter<<<SS_BLOCKS, 256>>>(ei);

    // layer 0 (launch 3 = mlp -> profiled slot)
    k_agg<<<WARP_BLOCKS, 256>>>(t + 0);
    k_mlp<<<MLP_BLOCKS, 256, SMEM_MLP_BYTES>>>(b1, mg, mb, b2,
                                               lng + HH, lnb + HH, t + 1,
                                               lw, lb, out, 0, 0, 1);

    k_agg<<<WARP_BLOCKS, 256>>>(t + 1);
    k_mlp<<<MLP_BLOCKS, 256, SMEM_MLP_BYTES>>>(b1 + H2, mg + H2, mb + H2, b2 + HH,
                                               lng + 2 * HH, lnb + 2 * HH, t + 2,
                                               lw, lb, out, 1, 1, 1);
    k_agg<<<WARP_BLOCKS, 256>>>(t + 2);
    k_mlp<<<MLP_BLOCKS, 256, SMEM_MLP_BYTES>>>(b1 + 2 * H2, mg + 2 * H2, mb + 2 * H2,
                                               b2 + 2 * HH, lng, lnb, t,
                                               lw, lb, out, 2, 1, 2);
}